// round 1
// baseline (speedup 1.0000x reference)
#include <cuda_runtime.h>
#include <math_constants.h>

#define BB 2
#define C 256
#define CI 128
#define NN 6400
#define NPROJ 384
#define SPLITK 4

// ---------------- scratch (static device allocations are allowed) ----------
__device__ float d_P[BB * NPROJ * NN];                 // theta(0),phi(128),g(256) each [CI][N]
__device__ float d_F[(size_t)BB * NN * NN];            // f logits [b][n][m]  (~328 MB)
__device__ float d_colM[BB * NN];                      // per-column (m) max over n
__device__ float d_colR[BB * NN];                      // 1 / per-column sum
__device__ float d_GS[BB * NN * CI];                   // g^T scaled: [m][c] = g[c][m]/D[m]
__device__ float d_YP[SPLITK * BB * CI * NN];          // split-K partials of y [c][n]
__device__ float d_Y[BB * CI * NN];                    // y [c][n]

// ---------------- shared SGEMM microkernel pieces (BM=BN=128, BK=8) --------
#define GEMM_PROLOG()                                   \
    __shared__ float As[8][128];                        \
    __shared__ float Bs[8][128];                        \
    float acc[8][8];                                    \
    _Pragma("unroll") for (int i = 0; i < 8; i++)       \
    _Pragma("unroll") for (int j = 0; j < 8; j++) acc[i][j] = 0.f; \
    const int t  = threadIdx.x;                         \
    const int tx = t & 15;                              \
    const int ty = t >> 4;                              \
    const int ar = t >> 1;                              \
    const int ac = (t & 1) * 4;                         \
    const int br = t >> 5;                              \
    const int bc = (t & 31) * 4;                        \
    (void)ar; (void)ac; (void)br; (void)bc;

#define GEMM_COMPUTE()                                  \
    __syncthreads();                                    \
    _Pragma("unroll")                                   \
    for (int k = 0; k < 8; ++k) {                       \
        float ra[8], rb[8];                             \
        *(float4*)(ra)     = *(const float4*)(&As[k][ty*4]);      \
        *(float4*)(ra + 4) = *(const float4*)(&As[k][ty*4 + 64]); \
        *(float4*)(rb)     = *(const float4*)(&Bs[k][tx*4]);      \
        *(float4*)(rb + 4) = *(const float4*)(&Bs[k][tx*4 + 64]); \
        _Pragma("unroll") for (int i = 0; i < 8; i++)   \
        _Pragma("unroll") for (int j = 0; j < 8; j++)   \
            acc[i][j] = fmaf(ra[i], rb[j], acc[i][j]);  \
    }                                                   \
    __syncthreads();

__device__ __forceinline__ int mrow(int i, int ty) {
    return (i < 4) ? (ty * 4 + i) : (64 + ty * 4 + i - 4);
}

// ---------------- 1: projections  P[o][n] = W[o][:]·X[:][n] + b ------------
__global__ void proj_kernel(const float* __restrict__ x,
                            const float* __restrict__ tw, const float* __restrict__ tb,
                            const float* __restrict__ pw, const float* __restrict__ pb,
                            const float* __restrict__ gw, const float* __restrict__ gb) {
    const int b = blockIdx.z;
    const int which = blockIdx.y;                        // 0=theta 1=phi 2=g
    const float* W    = (which == 0) ? tw : (which == 1) ? pw : gw;
    const float* bias = (which == 0) ? tb : (which == 1) ? pb : gb;
    const float* X = x + b * C * NN;
    float* P = d_P + (b * NPROJ + which * CI) * NN;
    const int n0 = blockIdx.x * 128;

    GEMM_PROLOG();
    for (int k0 = 0; k0 < C; k0 += 8) {
        float4 a = *(const float4*)(W + ar * C + k0 + ac);       // row-major A [128][256]
        As[ac + 0][ar] = a.x; As[ac + 1][ar] = a.y;
        As[ac + 2][ar] = a.z; As[ac + 3][ar] = a.w;
        *(float4*)&Bs[br][bc] = *(const float4*)(X + (k0 + br) * NN + n0 + bc);
        GEMM_COMPUTE();
    }
    #pragma unroll
    for (int i = 0; i < 8; i++) {
        const int m = mrow(i, ty);
        const float bv = bias[m];
        float4 v0 = make_float4(acc[i][0]+bv, acc[i][1]+bv, acc[i][2]+bv, acc[i][3]+bv);
        float4 v1 = make_float4(acc[i][4]+bv, acc[i][5]+bv, acc[i][6]+bv, acc[i][7]+bv);
        *(float4*)(P + m * NN + n0 + tx * 4)      = v0;
        *(float4*)(P + m * NN + n0 + 64 + tx * 4) = v1;
    }
}

// ---------------- 2: f[n][m] = sum_c theta[c][n] * phi[c][m] ---------------
__global__ void fgemm_kernel() {
    const int b  = blockIdx.z;
    const int n0 = blockIdx.y * 128;
    const int m0 = blockIdx.x * 128;
    const float* Th = d_P + b * NPROJ * NN;              // [CI][N]
    const float* Ph = Th + CI * NN;
    float* F = d_F + (size_t)b * NN * NN;

    GEMM_PROLOG();
    for (int k0 = 0; k0 < CI; k0 += 8) {                 // both operands K-major
        *(float4*)&As[br][bc] = *(const float4*)(Th + (k0 + br) * NN + n0 + bc);
        *(float4*)&Bs[br][bc] = *(const float4*)(Ph + (k0 + br) * NN + m0 + bc);
        GEMM_COMPUTE();
    }
    #pragma unroll
    for (int i = 0; i < 8; i++) {
        const int n = n0 + mrow(i, ty);
        *(float4*)(F + (size_t)n * NN + m0 + tx * 4)      = *(float4*)(&acc[i][0]);
        *(float4*)(F + (size_t)n * NN + m0 + 64 + tx * 4) = *(float4*)(&acc[i][4]);
    }
}

// ---------------- 3: column softmax stats (reduce over n, per m) -----------
__global__ void colsoftmax_kernel() {
    const int b = blockIdx.y;
    const int m = blockIdx.x * 128 + threadIdx.x;
    const float* Fm = d_F + (size_t)b * NN * NN + m;
    float mx = -CUDART_INF_F, d = 0.f;
    for (int n = 0; n < NN; n += 8) {
        float v[8];
        #pragma unroll
        for (int j = 0; j < 8; j++) v[j] = Fm[(size_t)(n + j) * NN];
        #pragma unroll
        for (int j = 0; j < 8; j++) {
            if (v[j] > mx) { d *= __expf(mx - v[j]); mx = v[j]; }
            d += __expf(v[j] - mx);
        }
    }
    d_colM[b * NN + m] = mx;
    d_colR[b * NN + m] = 1.f / d;
}

// ---------------- 4: gs[m][c] = g[c][m] / D[m]  (transpose + scale) --------
__global__ void gscale_kernel() {
    __shared__ float tsm[32][33];
    const int b  = blockIdx.z;
    const int m0 = blockIdx.x * 32;
    const int c0 = blockIdx.y * 32;
    const float* G = d_P + (b * NPROJ + 2 * CI) * NN;    // g proj [CI][N]
    const int tx = threadIdx.x, ty = threadIdx.y;        // 32 x 8
    #pragma unroll
    for (int j = 0; j < 32; j += 8)
        tsm[ty + j][tx] = G[(c0 + ty + j) * NN + m0 + tx];
    __syncthreads();
    #pragma unroll
    for (int j = 0; j < 32; j += 8) {
        const int m = m0 + ty + j;
        d_GS[(b * NN + m) * CI + c0 + tx] = tsm[tx][ty + j] * d_colR[b * NN + m];
    }
}

// ---------------- 5: y[n][c] = sum_m exp(f[n][m]-M[m]) * gs[m][c] ----------
__global__ void ygemm_kernel() {
    const int b     = blockIdx.z >> 2;
    const int split = blockIdx.z & 3;
    const int n0    = blockIdx.x * 128;
    const float* F  = d_F + (size_t)b * NN * NN;
    const float* GS = d_GS + b * NN * CI;
    const float* CM = d_colM + b * NN;
    float* YP = d_YP + (split * BB + b) * CI * NN;
    const int kbeg = split * (NN / SPLITK);
    const int kend = kbeg + (NN / SPLITK);

    GEMM_PROLOG();
    for (int k0 = kbeg; k0 < kend; k0 += 8) {
        float4 a = *(const float4*)(F + (size_t)(n0 + ar) * NN + k0 + ac);   // A row-major
        As[ac + 0][ar] = __expf(a.x - CM[k0 + ac + 0]);
        As[ac + 1][ar] = __expf(a.y - CM[k0 + ac + 1]);
        As[ac + 2][ar] = __expf(a.z - CM[k0 + ac + 2]);
        As[ac + 3][ar] = __expf(a.w - CM[k0 + ac + 3]);
        *(float4*)&Bs[br][bc] = *(const float4*)(GS + (k0 + br) * CI + bc);  // B [N][CI]
        GEMM_COMPUTE();
    }
    // transposed store: y partial [c][n]
    #pragma unroll
    for (int i = 0; i < 8; i++) {
        const int n = n0 + mrow(i, ty);
        #pragma unroll
        for (int j = 0; j < 8; j++) {
            const int c = (j < 4) ? (tx * 4 + j) : (64 + tx * 4 + j - 4);
            YP[c * NN + n] = acc[i][j];
        }
    }
}

// ---------------- 6: merge split-K partials --------------------------------
__global__ void reduceY_kernel() {
    const int i = blockIdx.x * 256 + threadIdx.x;
    const int S = BB * CI * NN;
    d_Y[i] = d_YP[i] + d_YP[S + i] + d_YP[2 * S + i] + d_YP[3 * S + i];
}

// ---------------- 7: out = Ww·y + Wb + x -----------------------------------
__global__ void out_kernel(const float* __restrict__ x,
                           const float* __restrict__ Ww, const float* __restrict__ Wb,
                           float* __restrict__ out) {
    const int b  = blockIdx.z;
    const int m0 = blockIdx.y * 128;
    const int n0 = blockIdx.x * 128;
    const float* Yb = d_Y + b * CI * NN;                 // [CI][N]

    GEMM_PROLOG();
    for (int k0 = 0; k0 < CI; k0 += 8) {
        float4 a = *(const float4*)(Ww + (m0 + ar) * CI + k0 + ac);  // [256][128] row-major
        As[ac + 0][ar] = a.x; As[ac + 1][ar] = a.y;
        As[ac + 2][ar] = a.z; As[ac + 3][ar] = a.w;
        *(float4*)&Bs[br][bc] = *(const float4*)(Yb + (k0 + br) * NN + n0 + bc);
        GEMM_COMPUTE();
    }
    #pragma unroll
    for (int i = 0; i < 8; i++) {
        const int m = m0 + mrow(i, ty);
        const float bv = Wb[m];
        const float* xr = x + (b * C + m) * NN;
        float* orow = out + (b * C + m) * NN;
        float4 x0 = *(const float4*)(xr + n0 + tx * 4);
        float4 x1 = *(const float4*)(xr + n0 + 64 + tx * 4);
        float4 v0 = make_float4(acc[i][0]+bv+x0.x, acc[i][1]+bv+x0.y,
                                acc[i][2]+bv+x0.z, acc[i][3]+bv+x0.w);
        float4 v1 = make_float4(acc[i][4]+bv+x1.x, acc[i][5]+bv+x1.y,
                                acc[i][6]+bv+x1.z, acc[i][7]+bv+x1.w);
        *(float4*)(orow + n0 + tx * 4)      = v0;
        *(float4*)(orow + n0 + 64 + tx * 4) = v1;
    }
}

// ---------------------------------------------------------------------------
extern "C" void kernel_launch(void* const* d_in, const int* in_sizes, int n_in,
                              void* d_out, int out_size) {
    const float* x  = (const float*)d_in[0];
    const float* gw = (const float*)d_in[1];
    const float* gb = (const float*)d_in[2];
    const float* tw = (const float*)d_in[3];
    const float* tb = (const float*)d_in[4];
    const float* pw = (const float*)d_in[5];
    const float* pb = (const float*)d_in[6];
    const float* Ww = (const float*)d_in[7];
    const float* Wb = (const float*)d_in[8];
    float* out = (float*)d_out;

    proj_kernel<<<dim3(NN / 128, 3, BB), 256>>>(x, tw, tb, pw, pb, gw, gb);
    fgemm_kernel<<<dim3(NN / 128, NN / 128, BB), 256>>>();
    colsoftmax_kernel<<<dim3(NN / 128, BB), 128>>>();
    gscale_kernel<<<dim3(NN / 32, CI / 32, BB), dim3(32, 8)>>>();
    ygemm_kernel<<<dim3(NN / 128, 1, BB * SPLITK), 256>>>();
    reduceY_kernel<<<(BB * CI * NN) / 256, 256>>>();
    out_kernel<<<dim3(NN / 128, C / 128, BB), 256>>>(x, Ww, Wb, out);
}

// round 3
// speedup vs baseline: 1.5334x; 1.5334x over previous
#include <cuda_runtime.h>
#include <math_constants.h>

#define BB 2
#define C 256
#define CI 128
#define NN 6400
#define NPROJ 384
#define SPLITK 4

// ---------------- scratch ---------------------------------------------------
__device__ float d_P[BB * NPROJ * NN];                 // theta(0),phi(128),g(256) each [CI][N]
__device__ float d_F[(size_t)BB * NN * NN];            // f logits [b][n][m]  (~328 MB)
__device__ float d_colM[BB * NN];                      // per-column (m) max over n
__device__ float d_colR[BB * NN];                      // 1 / per-column sum
__device__ float d_GS[BB * NN * CI];                   // g^T scaled: [m][c] = g[c][m]/D[m]
__device__ float d_YP[SPLITK * BB * NN * CI];          // split-K partials of y, [n][c]
__device__ float d_Y[BB * CI * NN];                    // y [c][n]

// ============================================================================
//                      tf32 mma.sync GEMM machinery
// ============================================================================
// smem tile [16][cols], stride 136 floats, XOR swizzle breaks all conflicts
__device__ __forceinline__ int swz(int kk, int col) {
    return kk * 136 + (col ^ ((kk & 12) << 1));
}

__device__ __forceinline__ unsigned f2tf32(float x) {
    unsigned r;
    asm("cvt.rna.tf32.f32 %0, %1;" : "=r"(r) : "f"(x));
    return r;
}

__device__ __forceinline__ void mma_tf32(float c[4], const unsigned a[4], const unsigned b[2]) {
    asm volatile(
        "mma.sync.aligned.m16n8k8.row.col.f32.tf32.tf32.f32 "
        "{%0,%1,%2,%3}, {%4,%5,%6,%7}, {%8,%9}, {%0,%1,%2,%3};"
        : "+f"(c[0]), "+f"(c[1]), "+f"(c[2]), "+f"(c[3])
        : "r"(a[0]), "r"(a[1]), "r"(a[2]), "r"(a[3]), "r"(b[0]), "r"(b[1]));
}

// warp-tile compute: 2 m-tiles x 8 n-tiles of m16n8k8, BK=16 (two k-steps)
#define MMA_COMPUTE(As, Bs, acc, wm, wn, g, tig)                         \
    _Pragma("unroll")                                                    \
    for (int ks = 0; ks < 16; ks += 8) {                                 \
        unsigned afr[2][4], bfr[8][2];                                   \
        _Pragma("unroll")                                                \
        for (int mt = 0; mt < 2; mt++) {                                 \
            const int mb = (wm) * 32 + mt * 16 + (g);                    \
            afr[mt][0] = __float_as_uint(As[swz(ks + (tig),     mb)]);   \
            afr[mt][1] = __float_as_uint(As[swz(ks + (tig),     mb + 8)]);\
            afr[mt][2] = __float_as_uint(As[swz(ks + (tig) + 4, mb)]);   \
            afr[mt][3] = __float_as_uint(As[swz(ks + (tig) + 4, mb + 8)]);\
        }                                                                \
        _Pragma("unroll")                                                \
        for (int nt = 0; nt < 8; nt++) {                                 \
            const int nb = (wn) * 64 + nt * 8 + (g);                     \
            bfr[nt][0] = __float_as_uint(Bs[swz(ks + (tig),     nb)]);   \
            bfr[nt][1] = __float_as_uint(Bs[swz(ks + (tig) + 4, nb)]);   \
        }                                                                \
        _Pragma("unroll")                                                \
        for (int mt = 0; mt < 2; mt++)                                   \
            _Pragma("unroll")                                            \
            for (int nt = 0; nt < 8; nt++)                               \
                mma_tf32(acc[mt][nt], afr[mt], bfr[nt]);                 \
    }

// ---------------- 2: f[n][m] = sum_c theta[c][n] * phi[c][m] (tf32 mma) ----
__global__ void __launch_bounds__(256, 2) fgemm_kernel() {
    __shared__ float As[16 * 136];
    __shared__ float Bs[16 * 136];
    const int b  = blockIdx.z;
    const int n0 = blockIdx.y * 128;
    const int m0 = blockIdx.x * 128;
    const float* Th = d_P + b * NPROJ * NN;              // [CI][N]
    const float* Ph = Th + CI * NN;
    float* F = d_F + (size_t)b * NN * NN;

    const int t = threadIdx.x, lane = t & 31, warp = t >> 5;
    const int wm = warp & 3, wn = warp >> 2;
    const int g = lane >> 2, tig = lane & 3;
    float acc[2][8][4];
    #pragma unroll
    for (int i = 0; i < 2; i++)
        #pragma unroll
        for (int j = 0; j < 8; j++)
            #pragma unroll
            for (int r = 0; r < 4; r++) acc[i][j][r] = 0.f;

    const int lr = t >> 5;          // 0..7 (row within half-tile)
    const int lc = (t & 31) * 4;    // float4 col

    #pragma unroll
    for (int k0 = 0; k0 < CI; k0 += 16) {
        #pragma unroll
        for (int j = 0; j < 2; j++) {
            const int kr = lr + 8 * j;
            float4 a = *(const float4*)(Th + (size_t)(k0 + kr) * NN + n0 + lc);
            float4 p = *(const float4*)(Ph + (size_t)(k0 + kr) * NN + m0 + lc);
            float* pa = As + swz(kr, lc);
            float* pb = Bs + swz(kr, lc);
            pa[0] = __uint_as_float(f2tf32(a.x)); pa[1] = __uint_as_float(f2tf32(a.y));
            pa[2] = __uint_as_float(f2tf32(a.z)); pa[3] = __uint_as_float(f2tf32(a.w));
            pb[0] = __uint_as_float(f2tf32(p.x)); pb[1] = __uint_as_float(f2tf32(p.y));
            pb[2] = __uint_as_float(f2tf32(p.z)); pb[3] = __uint_as_float(f2tf32(p.w));
        }
        __syncthreads();
        MMA_COMPUTE(As, Bs, acc, wm, wn, g, tig);
        __syncthreads();
    }

    #pragma unroll
    for (int mt = 0; mt < 2; mt++) {
        #pragma unroll
        for (int nt = 0; nt < 8; nt++) {
            const int n = n0 + wm * 32 + mt * 16 + g;
            const int m = m0 + wn * 64 + nt * 8 + tig * 2;
            float2 v01 = make_float2(acc[mt][nt][0], acc[mt][nt][1]);
            float2 v23 = make_float2(acc[mt][nt][2], acc[mt][nt][3]);
            *(float2*)(F + (size_t)n * NN + m)       = v01;
            *(float2*)(F + (size_t)(n + 8) * NN + m) = v23;
        }
    }
}

// ---------------- 5: y[n][c] = sum_m exp(f[n][m]-M[m]) * gs[m][c] (tf32) ---
__global__ void __launch_bounds__(256, 2) ygemm_kernel() {
    __shared__ float As[16 * 136];
    __shared__ float Bs[16 * 136];
    const int b     = blockIdx.z;
    const int split = blockIdx.y;
    const int n0    = blockIdx.x * 128;
    const float* F  = d_F + (size_t)b * NN * NN;
    const float* GS = d_GS + b * NN * CI;
    const float* CM = d_colM + b * NN;
    float* YP = d_YP + ((size_t)split * BB + b) * NN * CI;
    const int kbeg = split * (NN / SPLITK);
    const int kend = kbeg + (NN / SPLITK);

    const int t = threadIdx.x, lane = t & 31, warp = t >> 5;
    const int wm = warp & 3, wn = warp >> 2;
    const int g = lane >> 2, tig = lane & 3;
    float acc[2][8][4];
    #pragma unroll
    for (int i = 0; i < 2; i++)
        #pragma unroll
        for (int j = 0; j < 8; j++)
            #pragma unroll
            for (int r = 0; r < 4; r++) acc[i][j][r] = 0.f;

    const int q  = t & 3;           // k-quad for A loader
    const int nr = t >> 2;          // 0..63 (row)
    const int lr = t >> 5;          // B loader row
    const int lc = (t & 31) * 4;    // B loader col

    for (int k0 = kbeg; k0 < kend; k0 += 16) {
        // A: exp(F - colM) -> tf32, rows=n, cols=k
        #pragma unroll
        for (int p = 0; p < 2; p++) {
            const int nl = 64 * p + nr;
            float4 v = *(const float4*)(F + (size_t)(n0 + nl) * NN + k0 + q * 4);
            const float* cm = CM + k0 + q * 4;
            As[swz(q * 4 + 0, nl)] = __uint_as_float(f2tf32(__expf(v.x - cm[0])));
            As[swz(q * 4 + 1, nl)] = __uint_as_float(f2tf32(__expf(v.y - cm[1])));
            As[swz(q * 4 + 2, nl)] = __uint_as_float(f2tf32(__expf(v.z - cm[2])));
            As[swz(q * 4 + 3, nl)] = __uint_as_float(f2tf32(__expf(v.w - cm[3])));
        }
        // B: GS rows=m(k), cols=c
        #pragma unroll
        for (int j = 0; j < 2; j++) {
            const int kr = lr + 8 * j;
            float4 w = *(const float4*)(GS + (size_t)(k0 + kr) * CI + lc);
            float* pb = Bs + swz(kr, lc);
            pb[0] = __uint_as_float(f2tf32(w.x)); pb[1] = __uint_as_float(f2tf32(w.y));
            pb[2] = __uint_as_float(f2tf32(w.z)); pb[3] = __uint_as_float(f2tf32(w.w));
        }
        __syncthreads();
        MMA_COMPUTE(As, Bs, acc, wm, wn, g, tig);
        __syncthreads();
    }

    // store partial [n][c]
    #pragma unroll
    for (int mt = 0; mt < 2; mt++) {
        #pragma unroll
        for (int nt = 0; nt < 8; nt++) {
            const int n = n0 + wm * 32 + mt * 16 + g;
            const int c = wn * 64 + nt * 8 + tig * 2;
            float2 v01 = make_float2(acc[mt][nt][0], acc[mt][nt][1]);
            float2 v23 = make_float2(acc[mt][nt][2], acc[mt][nt][3]);
            *(float2*)(YP + (size_t)n * CI + c)       = v01;
            *(float2*)(YP + (size_t)(n + 8) * CI + c) = v23;
        }
    }
}

// ============================================================================
//                fp32 SIMT GEMM (small kernels: proj / out)
// ============================================================================
#define GEMM_PROLOG()                                   \
    __shared__ float Ass[8][128];                       \
    __shared__ float Bss[8][128];                       \
    float acc[8][8];                                    \
    _Pragma("unroll") for (int i = 0; i < 8; i++)       \
    _Pragma("unroll") for (int j = 0; j < 8; j++) acc[i][j] = 0.f; \
    const int t  = threadIdx.x;                         \
    const int tx = t & 15;                              \
    const int ty = t >> 4;                              \
    const int ar = t >> 1;                              \
    const int ac = (t & 1) * 4;                         \
    const int br = t >> 5;                              \
    const int bc = (t & 31) * 4;                        \
    (void)ar; (void)ac; (void)br; (void)bc;

#define GEMM_COMPUTE()                                  \
    __syncthreads();                                    \
    _Pragma("unroll")                                   \
    for (int k = 0; k < 8; ++k) {                       \
        float ra[8], rb[8];                             \
        *(float4*)(ra)     = *(const float4*)(&Ass[k][ty*4]);      \
        *(float4*)(ra + 4) = *(const float4*)(&Ass[k][ty*4 + 64]); \
        *(float4*)(rb)     = *(const float4*)(&Bss[k][tx*4]);      \
        *(float4*)(rb + 4) = *(const float4*)(&Bss[k][tx*4 + 64]); \
        _Pragma("unroll") for (int i = 0; i < 8; i++)   \
        _Pragma("unroll") for (int j = 0; j < 8; j++)   \
            acc[i][j] = fmaf(ra[i], rb[j], acc[i][j]);  \
    }                                                   \
    __syncthreads();

__device__ __forceinline__ int mrow(int i, int ty) {
    return (i < 4) ? (ty * 4 + i) : (64 + ty * 4 + i - 4);
}

// ---------------- 1: projections  P[o][n] = W[o][:]·X[:][n] + b ------------
__global__ void proj_kernel(const float* __restrict__ x,
                            const float* __restrict__ tw, const float* __restrict__ tb,
                            const float* __restrict__ pw, const float* __restrict__ pb,
                            const float* __restrict__ gw, const float* __restrict__ gb) {
    const int b = blockIdx.z;
    const int which = blockIdx.y;                        // 0=theta 1=phi 2=g
    const float* W    = (which == 0) ? tw : (which == 1) ? pw : gw;
    const float* bias = (which == 0) ? tb : (which == 1) ? pb : gb;
    const float* X = x + b * C * NN;
    float* P = d_P + (b * NPROJ + which * CI) * NN;
    const int n0 = blockIdx.x * 128;

    GEMM_PROLOG();
    for (int k0 = 0; k0 < C; k0 += 8) {
        float4 a = *(const float4*)(W + ar * C + k0 + ac);
        Ass[ac + 0][ar] = a.x; Ass[ac + 1][ar] = a.y;
        Ass[ac + 2][ar] = a.z; Ass[ac + 3][ar] = a.w;
        *(float4*)&Bss[br][bc] = *(const float4*)(X + (k0 + br) * NN + n0 + bc);
        GEMM_COMPUTE();
    }
    #pragma unroll
    for (int i = 0; i < 8; i++) {
        const int m = mrow(i, ty);
        const float bv = bias[m];
        float4 v0 = make_float4(acc[i][0]+bv, acc[i][1]+bv, acc[i][2]+bv, acc[i][3]+bv);
        float4 v1 = make_float4(acc[i][4]+bv, acc[i][5]+bv, acc[i][6]+bv, acc[i][7]+bv);
        *(float4*)(P + m * NN + n0 + tx * 4)      = v0;
        *(float4*)(P + m * NN + n0 + 64 + tx * 4) = v1;
    }
}

// ---------------- 3: column softmax stats (reduce over n, per m) -----------
__global__ void colsoftmax_kernel() {
    const int b = blockIdx.y;
    const int m = blockIdx.x * 128 + threadIdx.x;
    const float* Fm = d_F + (size_t)b * NN * NN + m;
    float mx = -CUDART_INF_F, d = 0.f;
    for (int n = 0; n < NN; n += 8) {
        float v[8];
        #pragma unroll
        for (int j = 0; j < 8; j++) v[j] = Fm[(size_t)(n + j) * NN];
        #pragma unroll
        for (int j = 0; j < 8; j++) {
            if (v[j] > mx) { d *= __expf(mx - v[j]); mx = v[j]; }
            d += __expf(v[j] - mx);
        }
    }
    d_colM[b * NN + m] = mx;
    d_colR[b * NN + m] = 1.f / d;
}

// ---------------- 4: gs[m][c] = g[c][m] / D[m]  (transpose + scale) --------
__global__ void gscale_kernel() {
    __shared__ float tsm[32][33];
    const int b  = blockIdx.z;
    const int m0 = blockIdx.x * 32;
    const int c0 = blockIdx.y * 32;
    const float* G = d_P + (b * NPROJ + 2 * CI) * NN;    // g proj [CI][N]
    const int tx = threadIdx.x, ty = threadIdx.y;        // 32 x 8
    #pragma unroll
    for (int j = 0; j < 32; j += 8)
        tsm[ty + j][tx] = G[(c0 + ty + j) * NN + m0 + tx];
    __syncthreads();
    #pragma unroll
    for (int j = 0; j < 32; j += 8) {
        const int m = m0 + ty + j;
        d_GS[(b * NN + m) * CI + c0 + tx] = tsm[tx][ty + j] * d_colR[b * NN + m];
    }
}

// ---------------- 6: merge split-K partials + transpose to [c][n] ----------
__global__ void reduceY_kernel() {
    __shared__ float tsm[32][33];
    const int b  = blockIdx.z;
    const int n0 = blockIdx.x * 32;
    const int c0 = blockIdx.y * 32;
    const int tx = threadIdx.x, ty = threadIdx.y;        // 32 x 8
    const size_t S = (size_t)BB * NN * CI;
    const size_t base = (size_t)b * NN * CI;
    #pragma unroll
    for (int j = 0; j < 32; j += 8) {
        const size_t idx = base + (size_t)(n0 + ty + j) * CI + c0 + tx;
        tsm[ty + j][tx] = d_YP[idx] + d_YP[S + idx] + d_YP[2 * S + idx] + d_YP[3 * S + idx];
    }
    __syncthreads();
    #pragma unroll
    for (int j = 0; j < 32; j += 8)
        d_Y[b * CI * NN + (c0 + ty + j) * NN + n0 + tx] = tsm[tx][ty + j];
}

// ---------------- 7: out = Ww·y + Wb + x -----------------------------------
__global__ void out_kernel(const float* __restrict__ x,
                           const float* __restrict__ Ww, const float* __restrict__ Wb,
                           float* __restrict__ out) {
    const int b  = blockIdx.z;
    const int m0 = blockIdx.y * 128;
    const int n0 = blockIdx.x * 128;
    const float* Yb = d_Y + b * CI * NN;                 // [CI][N]

    GEMM_PROLOG();
    for (int k0 = 0; k0 < CI; k0 += 8) {
        float4 a = *(const float4*)(Ww + (m0 + ar) * CI + k0 + ac);
        Ass[ac + 0][ar] = a.x; Ass[ac + 1][ar] = a.y;
        Ass[ac + 2][ar] = a.z; Ass[ac + 3][ar] = a.w;
        *(float4*)&Bss[br][bc] = *(const float4*)(Yb + (k0 + br) * NN + n0 + bc);
        GEMM_COMPUTE();
    }
    #pragma unroll
    for (int i = 0; i < 8; i++) {
        const int m = m0 + mrow(i, ty);
        const float bv = Wb[m];
        const float* xr = x + (b * C + m) * NN;
        float* orow = out + (b * C + m) * NN;
        float4 x0 = *(const float4*)(xr + n0 + tx * 4);
        float4 x1 = *(const float4*)(xr + n0 + 64 + tx * 4);
        float4 v0 = make_float4(acc[i][0]+bv+x0.x, acc[i][1]+bv+x0.y,
                                acc[i][2]+bv+x0.z, acc[i][3]+bv+x0.w);
        float4 v1 = make_float4(acc[i][4]+bv+x1.x, acc[i][5]+bv+x1.y,
                                acc[i][6]+bv+x1.z, acc[i][7]+bv+x1.w);
        *(float4*)(orow + n0 + tx * 4)      = v0;
        *(float4*)(orow + n0 + 64 + tx * 4) = v1;
    }
}

// ---------------------------------------------------------------------------
extern "C" void kernel_launch(void* const* d_in, const int* in_sizes, int n_in,
                              void* d_out, int out_size) {
    const float* x  = (const float*)d_in[0];
    const float* gw = (const float*)d_in[1];
    const float* gb = (const float*)d_in[2];
    const float* tw = (const float*)d_in[3];
    const float* tb = (const float*)d_in[4];
    const float* pw = (const float*)d_in[5];
    const float* pb = (const float*)d_in[6];
    const float* Ww = (const float*)d_in[7];
    const float* Wb = (const float*)d_in[8];
    float* out = (float*)d_out;

    proj_kernel<<<dim3(NN / 128, 3, BB), 256>>>(x, tw, tb, pw, pb, gw, gb);
    fgemm_kernel<<<dim3(NN / 128, NN / 128, BB), 256>>>();
    colsoftmax_kernel<<<dim3(NN / 128, BB), 128>>>();
    gscale_kernel<<<dim3(NN / 32, CI / 32, BB), dim3(32, 8)>>>();
    ygemm_kernel<<<dim3(NN / 128, SPLITK, BB), 256>>>();
    reduceY_kernel<<<dim3(NN / 32, CI / 32, BB), dim3(32, 8)>>>();
    out_kernel<<<dim3(NN / 128, C / 128, BB), 256>>>(x, Ww, Wb, out);
}

// round 4
// speedup vs baseline: 2.8126x; 1.8343x over previous
#include <cuda_runtime.h>
#include <math_constants.h>

#define BB 2
#define C 256
#define CI 128
#define NN 6400
#define NPROJ 384
#define SPLITK 4
#define NBLK (NN / 128)     // 50

// ---------------- scratch ---------------------------------------------------
__device__ float d_P[BB * NPROJ * NN];                 // theta(0),phi(128),g(256) each [CI][N]
__device__ float d_F[(size_t)BB * NN * NN];            // f logits [b][n][m]
__device__ float d_pM[BB * NBLK * NN];                 // per (n-block, m) tile col max
__device__ float d_pS[BB * NBLK * NN];                 // per (n-block, m) tile col sum-exp
__device__ float d_colM[BB * NN];                      // per-column (m) max over n
__device__ float d_colR[BB * NN];                      // 1 / per-column sum
__device__ float d_GS[BB * NN * CI];                   // g^T scaled: [m][c] = g[c][m]/D[m]
__device__ float d_YP[SPLITK * BB * NN * CI];          // split-K partials of y, [n][c]
__device__ float d_Y[BB * CI * NN];                    // y [c][n]

// ============================================================================
//                      tf32 mma.sync GEMM machinery
// ============================================================================
__device__ __forceinline__ int swz(int kk, int col) {
    return kk * 136 + (col ^ ((kk & 12) << 1));
}

__device__ __forceinline__ unsigned f2tf32(float x) {
    unsigned r;
    asm("cvt.rna.tf32.f32 %0, %1;" : "=r"(r) : "f"(x));
    return r;
}
__device__ __forceinline__ float rnd_tf32(float x) {
    return __uint_as_float(f2tf32(x));
}

__device__ __forceinline__ void mma_tf32(float c[4], const unsigned a[4], const unsigned b[2]) {
    asm volatile(
        "mma.sync.aligned.m16n8k8.row.col.f32.tf32.tf32.f32 "
        "{%0,%1,%2,%3}, {%4,%5,%6,%7}, {%8,%9}, {%0,%1,%2,%3};"
        : "+f"(c[0]), "+f"(c[1]), "+f"(c[2]), "+f"(c[3])
        : "r"(a[0]), "r"(a[1]), "r"(a[2]), "r"(a[3]), "r"(b[0]), "r"(b[1]));
}

#define MMA_COMPUTE(As, Bs, acc, wm, wn, g, tig)                         \
    _Pragma("unroll")                                                    \
    for (int ks = 0; ks < 16; ks += 8) {                                 \
        unsigned afr[2][4], bfr[8][2];                                   \
        _Pragma("unroll")                                                \
        for (int mt = 0; mt < 2; mt++) {                                 \
            const int mb = (wm) * 32 + mt * 16 + (g);                    \
            afr[mt][0] = __float_as_uint((As)[swz(ks + (tig),     mb)]);   \
            afr[mt][1] = __float_as_uint((As)[swz(ks + (tig),     mb + 8)]);\
            afr[mt][2] = __float_as_uint((As)[swz(ks + (tig) + 4, mb)]);   \
            afr[mt][3] = __float_as_uint((As)[swz(ks + (tig) + 4, mb + 8)]);\
        }                                                                \
        _Pragma("unroll")                                                \
        for (int nt = 0; nt < 8; nt++) {                                 \
            const int nb = (wn) * 64 + nt * 8 + (g);                     \
            bfr[nt][0] = __float_as_uint((Bs)[swz(ks + (tig),     nb)]);   \
            bfr[nt][1] = __float_as_uint((Bs)[swz(ks + (tig) + 4, nb)]);   \
        }                                                                \
        _Pragma("unroll")                                                \
        for (int mt = 0; mt < 2; mt++)                                   \
            _Pragma("unroll")                                            \
            for (int nt = 0; nt < 8; nt++)                               \
                mma_tf32(acc[mt][nt], afr[mt], bfr[nt]);                 \
    }

// cp.async helpers
__device__ __forceinline__ unsigned smem_u32(const void* p) {
    return (unsigned)__cvta_generic_to_shared(p);
}
#define CP16(dst, src) asm volatile("cp.async.cg.shared.global [%0], [%1], 16;" :: "r"(dst), "l"(src))
#define CPC()          asm volatile("cp.async.commit_group;")
#define CPW(n)         asm volatile("cp.async.wait_group %0;" :: "n"(n))

// ---------------- 2: f = theta^T phi (tf32, pipelined) + softmax partials --
__global__ void __launch_bounds__(256, 2) fgemm_kernel() {
    __shared__ float As[2][16 * 136];
    __shared__ float Bs[2][16 * 136];
    const int b  = blockIdx.z;
    const int n0 = blockIdx.y * 128;
    const int m0 = blockIdx.x * 128;
    const float* Th = d_P + b * NPROJ * NN;              // [CI][N] (tf32-rounded)
    const float* Ph = Th + CI * NN;
    float* F = d_F + (size_t)b * NN * NN;

    const int t = threadIdx.x, lane = t & 31, warp = t >> 5;
    const int wm = warp & 3, wn = warp >> 2;
    const int g = lane >> 2, tig = lane & 3;
    float acc[2][8][4];
    #pragma unroll
    for (int i = 0; i < 2; i++)
        #pragma unroll
        for (int j = 0; j < 8; j++)
            #pragma unroll
            for (int r = 0; r < 4; r++) acc[i][j][r] = 0.f;

    const int lr = t >> 5;          // 0..7
    const int lc = (t & 31) * 4;

    auto issue = [&](int ti, int s) {
        const int k0 = ti * 16;
        CP16(smem_u32(&As[s][swz(lr,     lc)]), Th + (size_t)(k0 + lr)     * NN + n0 + lc);
        CP16(smem_u32(&As[s][swz(lr + 8, lc)]), Th + (size_t)(k0 + lr + 8) * NN + n0 + lc);
        CP16(smem_u32(&Bs[s][swz(lr,     lc)]), Ph + (size_t)(k0 + lr)     * NN + m0 + lc);
        CP16(smem_u32(&Bs[s][swz(lr + 8, lc)]), Ph + (size_t)(k0 + lr + 8) * NN + m0 + lc);
        CPC();
    };

    issue(0, 0);
    #pragma unroll
    for (int tt = 0; tt < 8; ++tt) {
        if (tt + 1 < 8) { issue(tt + 1, (tt + 1) & 1); CPW(1); } else { CPW(0); }
        __syncthreads();
        MMA_COMPUTE(As[tt & 1], Bs[tt & 1], acc, wm, wn, g, tig);
        __syncthreads();
    }

    // store F tile
    #pragma unroll
    for (int mt = 0; mt < 2; mt++) {
        #pragma unroll
        for (int nt = 0; nt < 8; nt++) {
            const int n = n0 + wm * 32 + mt * 16 + g;
            const int m = m0 + wn * 64 + nt * 8 + tig * 2;
            *(float2*)(F + (size_t)n * NN + m)       = make_float2(acc[mt][nt][0], acc[mt][nt][1]);
            *(float2*)(F + (size_t)(n + 8) * NN + m) = make_float2(acc[mt][nt][2], acc[mt][nt][3]);
        }
    }

    // ---- fused column-softmax partials (max & sum-exp over this tile's rows)
    float* red = As[0];                                  // [4][128] + tilemax[128]
    float lv[8][2];
    #pragma unroll
    for (int nt = 0; nt < 8; nt++) {
        lv[nt][0] = fmaxf(fmaxf(acc[0][nt][0], acc[0][nt][2]), fmaxf(acc[1][nt][0], acc[1][nt][2]));
        lv[nt][1] = fmaxf(fmaxf(acc[0][nt][1], acc[0][nt][3]), fmaxf(acc[1][nt][1], acc[1][nt][3]));
        #pragma unroll
        for (int d = 4; d <= 16; d <<= 1) {
            lv[nt][0] = fmaxf(lv[nt][0], __shfl_xor_sync(0xffffffff, lv[nt][0], d));
            lv[nt][1] = fmaxf(lv[nt][1], __shfl_xor_sync(0xffffffff, lv[nt][1], d));
        }
    }
    if (g == 0) {
        #pragma unroll
        for (int nt = 0; nt < 8; nt++) {
            const int col = wn * 64 + nt * 8 + tig * 2;
            red[wm * 128 + col]     = lv[nt][0];
            red[wm * 128 + col + 1] = lv[nt][1];
        }
    }
    __syncthreads();
    if (t < 128) {
        float tm = fmaxf(fmaxf(red[t], red[128 + t]), fmaxf(red[256 + t], red[384 + t]));
        red[512 + t] = tm;
    }
    __syncthreads();
    #pragma unroll
    for (int nt = 0; nt < 8; nt++) {
        const int col = wn * 64 + nt * 8 + tig * 2;
        const float tm0 = red[512 + col], tm1 = red[512 + col + 1];
        lv[nt][0] = __expf(acc[0][nt][0] - tm0) + __expf(acc[0][nt][2] - tm0)
                  + __expf(acc[1][nt][0] - tm0) + __expf(acc[1][nt][2] - tm0);
        lv[nt][1] = __expf(acc[0][nt][1] - tm1) + __expf(acc[0][nt][3] - tm1)
                  + __expf(acc[1][nt][1] - tm1) + __expf(acc[1][nt][3] - tm1);
        #pragma unroll
        for (int d = 4; d <= 16; d <<= 1) {
            lv[nt][0] += __shfl_xor_sync(0xffffffff, lv[nt][0], d);
            lv[nt][1] += __shfl_xor_sync(0xffffffff, lv[nt][1], d);
        }
    }
    __syncthreads();
    if (g == 0) {
        #pragma unroll
        for (int nt = 0; nt < 8; nt++) {
            const int col = wn * 64 + nt * 8 + tig * 2;
            red[wm * 128 + col]     = lv[nt][0];
            red[wm * 128 + col + 1] = lv[nt][1];
        }
    }
    __syncthreads();
    if (t < 128) {
        const float s = red[t] + red[128 + t] + red[256 + t] + red[384 + t];
        const size_t idx = ((size_t)b * NBLK + blockIdx.y) * NN + m0 + t;
        d_pM[idx] = red[512 + t];
        d_pS[idx] = s;
    }
}

// ---------------- 3: merge softmax partials --------------------------------
__global__ void merge_stats_kernel() {
    const int b = blockIdx.y;
    const int m = blockIdx.x * 256 + threadIdx.x;
    const float* pM = d_pM + (size_t)b * NBLK * NN + m;
    const float* pS = d_pS + (size_t)b * NBLK * NN + m;
    float M = -CUDART_INF_F;
    #pragma unroll 10
    for (int i = 0; i < NBLK; i++) M = fmaxf(M, pM[(size_t)i * NN]);
    float s = 0.f;
    #pragma unroll 10
    for (int i = 0; i < NBLK; i++) s += pS[(size_t)i * NN] * __expf(pM[(size_t)i * NN] - M);
    d_colM[b * NN + m] = M;
    d_colR[b * NN + m] = 1.f / s;
}

// ---------------- 4: gs[m][c] = g[c][m] / D[m]  (transpose+scale, tf32) ----
__global__ void gscale_kernel() {
    __shared__ float tsm[32][33];
    const int b  = blockIdx.z;
    const int m0 = blockIdx.x * 32;
    const int c0 = blockIdx.y * 32;
    const float* G = d_P + (b * NPROJ + 2 * CI) * NN;
    const int tx = threadIdx.x, ty = threadIdx.y;        // 32 x 8
    #pragma unroll
    for (int j = 0; j < 32; j += 8)
        tsm[ty + j][tx] = G[(c0 + ty + j) * NN + m0 + tx];
    __syncthreads();
    #pragma unroll
    for (int j = 0; j < 32; j += 8) {
        const int m = m0 + ty + j;
        d_GS[(b * NN + m) * CI + c0 + tx] = rnd_tf32(tsm[tx][ty + j] * d_colR[b * NN + m]);
    }
}

// ---------------- 5: y = softmax(f) g  (tf32, pipelined) -------------------
__global__ void __launch_bounds__(256, 2) ygemm_kernel() {
    __shared__ float As[2][16 * 136];
    __shared__ float Bs[2][16 * 136];
    const int b     = blockIdx.z;
    const int split = blockIdx.y;
    const int n0    = blockIdx.x * 128;
    const float* F  = d_F + (size_t)b * NN * NN;
    const float* GS = d_GS + b * NN * CI;                // tf32-rounded
    const float* CM = d_colM + b * NN;
    float* YP = d_YP + ((size_t)split * BB + b) * NN * CI;
    const int kbeg = split * (NN / SPLITK);
    const int NT   = (NN / SPLITK) / 16;                 // 100

    const int t = threadIdx.x, lane = t & 31, warp = t >> 5;
    const int wm = warp & 3, wn = warp >> 2;
    const int g = lane >> 2, tig = lane & 3;
    float acc[2][8][4];
    #pragma unroll
    for (int i = 0; i < 2; i++)
        #pragma unroll
        for (int j = 0; j < 8; j++)
            #pragma unroll
            for (int r = 0; r < 4; r++) acc[i][j][r] = 0.f;

    const int q  = t & 3;
    const int nr = t >> 2;          // 0..63
    const int lr = t >> 5;
    const int lc = (t & 31) * 4;

    auto issueB = [&](int ti, int s) {
        const int k0 = kbeg + ti * 16;
        CP16(smem_u32(&Bs[s][swz(lr,     lc)]), GS + (size_t)(k0 + lr)     * CI + lc);
        CP16(smem_u32(&Bs[s][swz(lr + 8, lc)]), GS + (size_t)(k0 + lr + 8) * CI + lc);
        CPC();
    };
    auto ldA = [&](int ti, float4 fa[2], float4& cm) {
        const int k0 = kbeg + ti * 16;
        fa[0] = *(const float4*)(F + (size_t)(n0 + nr)      * NN + k0 + q * 4);
        fa[1] = *(const float4*)(F + (size_t)(n0 + nr + 64) * NN + k0 + q * 4);
        cm = *(const float4*)(CM + k0 + q * 4);
    };
    auto stsA = [&](int s, const float4 fa[2], const float4 cm) {
        #pragma unroll
        for (int p = 0; p < 2; p++) {
            const int nl = 64 * p + nr;
            As[s][swz(q * 4 + 0, nl)] = rnd_tf32(__expf(fa[p].x - cm.x));
            As[s][swz(q * 4 + 1, nl)] = rnd_tf32(__expf(fa[p].y - cm.y));
            As[s][swz(q * 4 + 2, nl)] = rnd_tf32(__expf(fa[p].z - cm.z));
            As[s][swz(q * 4 + 3, nl)] = rnd_tf32(__expf(fa[p].w - cm.w));
        }
    };

    float4 fa[2], fan[2], cm, cmn;
    ldA(0, fa, cm);
    issueB(0, 0);
    for (int tt = 0; tt < NT; ++tt) {
        if (tt + 1 < NT) issueB(tt + 1, (tt + 1) & 1);
        stsA(tt & 1, fa, cm);
        if (tt + 1 < NT) ldA(tt + 1, fan, cmn);
        if (tt + 1 < NT) { CPW(1); } else { CPW(0); }
        __syncthreads();
        MMA_COMPUTE(As[tt & 1], Bs[tt & 1], acc, wm, wn, g, tig);
        __syncthreads();
        fa[0] = fan[0]; fa[1] = fan[1]; cm = cmn;
    }

    #pragma unroll
    for (int mt = 0; mt < 2; mt++) {
        #pragma unroll
        for (int nt = 0; nt < 8; nt++) {
            const int n = n0 + wm * 32 + mt * 16 + g;
            const int c = wn * 64 + nt * 8 + tig * 2;
            *(float2*)(YP + (size_t)n * CI + c)       = make_float2(acc[mt][nt][0], acc[mt][nt][1]);
            *(float2*)(YP + (size_t)(n + 8) * CI + c) = make_float2(acc[mt][nt][2], acc[mt][nt][3]);
        }
    }
}

// ============================================================================
//                fp32 SIMT GEMM (small kernels: proj / out)
// ============================================================================
#define GEMM_PROLOG()                                   \
    __shared__ float Ass[8][128];                       \
    __shared__ float Bss[8][128];                       \
    float acc[8][8];                                    \
    _Pragma("unroll") for (int i = 0; i < 8; i++)       \
    _Pragma("unroll") for (int j = 0; j < 8; j++) acc[i][j] = 0.f; \
    const int t  = threadIdx.x;                         \
    const int tx = t & 15;                              \
    const int ty = t >> 4;                              \
    const int ar = t >> 1;                              \
    const int ac = (t & 1) * 4;                         \
    const int br = t >> 5;                              \
    const int bc = (t & 31) * 4;                        \
    (void)ar; (void)ac; (void)br; (void)bc;

#define GEMM_COMPUTE()                                  \
    __syncthreads();                                    \
    _Pragma("unroll")                                   \
    for (int k = 0; k < 8; ++k) {                       \
        float ra[8], rb[8];                             \
        *(float4*)(ra)     = *(const float4*)(&Ass[k][ty*4]);      \
        *(float4*)(ra + 4) = *(const float4*)(&Ass[k][ty*4 + 64]); \
        *(float4*)(rb)     = *(const float4*)(&Bss[k][tx*4]);      \
        *(float4*)(rb + 4) = *(const float4*)(&Bss[k][tx*4 + 64]); \
        _Pragma("unroll") for (int i = 0; i < 8; i++)   \
        _Pragma("unroll") for (int j = 0; j < 8; j++)   \
            acc[i][j] = fmaf(ra[i], rb[j], acc[i][j]);  \
    }                                                   \
    __syncthreads();

__device__ __forceinline__ int mrow(int i, int ty) {
    return (i < 4) ? (ty * 4 + i) : (64 + ty * 4 + i - 4);
}

// ---------------- 1: projections -------------------------------------------
__global__ void proj_kernel(const float* __restrict__ x,
                            const float* __restrict__ tw, const float* __restrict__ tb,
                            const float* __restrict__ pw, const float* __restrict__ pb,
                            const float* __restrict__ gw, const float* __restrict__ gb) {
    const int b = blockIdx.z;
    const int which = blockIdx.y;                        // 0=theta 1=phi 2=g
    const float* W    = (which == 0) ? tw : (which == 1) ? pw : gw;
    const float* bias = (which == 0) ? tb : (which == 1) ? pb : gb;
    const float* X = x + b * C * NN;
    float* P = d_P + (b * NPROJ + which * CI) * NN;
    const int n0 = blockIdx.x * 128;
    const bool doRound = (which < 2);                    // theta/phi feed tf32 mma

    GEMM_PROLOG();
    for (int k0 = 0; k0 < C; k0 += 8) {
        float4 a = *(const float4*)(W + ar * C + k0 + ac);
        Ass[ac + 0][ar] = a.x; Ass[ac + 1][ar] = a.y;
        Ass[ac + 2][ar] = a.z; Ass[ac + 3][ar] = a.w;
        *(float4*)&Bss[br][bc] = *(const float4*)(X + (k0 + br) * NN + n0 + bc);
        GEMM_COMPUTE();
    }
    #pragma unroll
    for (int i = 0; i < 8; i++) {
        const int m = mrow(i, ty);
        const float bv = bias[m];
        float v[8];
        #pragma unroll
        for (int j = 0; j < 8; j++) {
            v[j] = acc[i][j] + bv;
            if (doRound) v[j] = rnd_tf32(v[j]);
        }
        *(float4*)(P + m * NN + n0 + tx * 4)      = make_float4(v[0], v[1], v[2], v[3]);
        *(float4*)(P + m * NN + n0 + 64 + tx * 4) = make_float4(v[4], v[5], v[6], v[7]);
    }
}

// ---------------- 6: merge split-K partials + transpose to [c][n] ----------
__global__ void reduceY_kernel() {
    __shared__ float tsm[32][33];
    const int b  = blockIdx.z;
    const int n0 = blockIdx.x * 32;
    const int c0 = blockIdx.y * 32;
    const int tx = threadIdx.x, ty = threadIdx.y;        // 32 x 8
    const size_t S = (size_t)BB * NN * CI;
    const size_t base = (size_t)b * NN * CI;
    #pragma unroll
    for (int j = 0; j < 32; j += 8) {
        const size_t idx = base + (size_t)(n0 + ty + j) * CI + c0 + tx;
        tsm[ty + j][tx] = d_YP[idx] + d_YP[S + idx] + d_YP[2 * S + idx] + d_YP[3 * S + idx];
    }
    __syncthreads();
    #pragma unroll
    for (int j = 0; j < 32; j += 8)
        d_Y[b * CI * NN + (c0 + ty + j) * NN + n0 + tx] = tsm[tx][ty + j];
}

// ---------------- 7: out = Ww·y + Wb + x -----------------------------------
__global__ void out_kernel(const float* __restrict__ x,
                           const float* __restrict__ Ww, const float* __restrict__ Wb,
                           float* __restrict__ out) {
    const int b  = blockIdx.z;
    const int m0 = blockIdx.y * 128;
    const int n0 = blockIdx.x * 128;
    const float* Yb = d_Y + b * CI * NN;

    GEMM_PROLOG();
    for (int k0 = 0; k0 < CI; k0 += 8) {
        float4 a = *(const float4*)(Ww + (m0 + ar) * CI + k0 + ac);
        Ass[ac + 0][ar] = a.x; Ass[ac + 1][ar] = a.y;
        Ass[ac + 2][ar] = a.z; Ass[ac + 3][ar] = a.w;
        *(float4*)&Bss[br][bc] = *(const float4*)(Yb + (k0 + br) * NN + n0 + bc);
        GEMM_COMPUTE();
    }
    #pragma unroll
    for (int i = 0; i < 8; i++) {
        const int m = m0 + mrow(i, ty);
        const float bv = Wb[m];
        const float* xr = x + (b * C + m) * NN;
        float* orow = out + (b * C + m) * NN;
        float4 x0 = *(const float4*)(xr + n0 + tx * 4);
        float4 x1 = *(const float4*)(xr + n0 + 64 + tx * 4);
        *(float4*)(orow + n0 + tx * 4) =
            make_float4(acc[i][0]+bv+x0.x, acc[i][1]+bv+x0.y, acc[i][2]+bv+x0.z, acc[i][3]+bv+x0.w);
        *(float4*)(orow + n0 + 64 + tx * 4) =
            make_float4(acc[i][4]+bv+x1.x, acc[i][5]+bv+x1.y, acc[i][6]+bv+x1.z, acc[i][7]+bv+x1.w);
    }
}

// ---------------------------------------------------------------------------
extern "C" void kernel_launch(void* const* d_in, const int* in_sizes, int n_in,
                              void* d_out, int out_size) {
    const float* x  = (const float*)d_in[0];
    const float* gw = (const float*)d_in[1];
    const float* gb = (const float*)d_in[2];
    const float* tw = (const float*)d_in[3];
    const float* tb = (const float*)d_in[4];
    const float* pw = (const float*)d_in[5];
    const float* pb = (const float*)d_in[6];
    const float* Ww = (const float*)d_in[7];
    const float* Wb = (const float*)d_in[8];
    float* out = (float*)d_out;

    proj_kernel<<<dim3(NN / 128, 3, BB), 256>>>(x, tw, tb, pw, pb, gw, gb);
    fgemm_kernel<<<dim3(NN / 128, NN / 128, BB), 256>>>();
    merge_stats_kernel<<<dim3(NN / 256, BB), 256>>>();
    gscale_kernel<<<dim3(NN / 32, CI / 32, BB), dim3(32, 8)>>>();
    ygemm_kernel<<<dim3(NN / 128, SPLITK, BB), 256>>>();
    reduceY_kernel<<<dim3(NN / 32, CI / 32, BB), dim3(32, 8)>>>();
    out_kernel<<<dim3(NN / 128, C / 128, BB), 256>>>(x, Ww, Wb, out);
}

// round 6
// speedup vs baseline: 4.0045x; 1.4238x over previous
#include <cuda_runtime.h>
#include <cuda_fp16.h>
#include <math_constants.h>
#include <cstdint>

#define BB 2
#define C 256
#define CI 128
#define NN 6400
#define SPLITK 4
#define NBLK (NN / 128)     // 50

typedef unsigned u32;

// ---------------- scratch ---------------------------------------------------
__device__ u32   d_Th[BB * (CI / 2) * NN];             // theta pairs [c2][n] half2
__device__ u32   d_Ph[BB * (CI / 2) * NN];             // phi   pairs [c2][n] half2
__device__ float d_G[BB * CI * NN];                    // g proj fp32 [c][m]
__device__ float d_F[(size_t)BB * NN * NN];            // f logits [b][n][m]
__device__ float d_pM[BB * NBLK * NN];
__device__ float d_pS[BB * NBLK * NN];
__device__ float d_colM[BB * NN];
__device__ float d_colR[BB * NN];
__device__ u32   d_GSh[BB * (NN / 2) * CI];            // gs pairs [m2][c] half2
__device__ float d_YP[(size_t)SPLITK * BB * NN * CI];  // split-K partials, [n][c]
__device__ float d_Y[BB * CI * NN];                    // y [c][n]

// ============================================================================
//                      fp16 mma.sync GEMM machinery
// ============================================================================
// smem tile: 16 rows (k-pairs) x 128 cols (u32/half2 each), XOR swizzle bits 3-4
#define SWZ(row, col) ((row) * 128 + ((col) ^ (((row) & 3) << 3)))

__device__ __forceinline__ u32 packh2(float a, float b) {
    __half2 h = __halves2half2(__float2half_rn(a), __float2half_rn(b));
    return reinterpret_cast<u32&>(h);
}

__device__ __forceinline__ void mma_f16(float c[4], const u32 a[4], const u32 b[2]) {
    asm volatile(
        "mma.sync.aligned.m16n8k16.row.col.f32.f16.f16.f32 "
        "{%0,%1,%2,%3}, {%4,%5,%6,%7}, {%8,%9}, {%0,%1,%2,%3};"
        : "+f"(c[0]), "+f"(c[1]), "+f"(c[2]), "+f"(c[3])
        : "r"(a[0]), "r"(a[1]), "r"(a[2]), "r"(a[3]), "r"(b[0]), "r"(b[1]));
}

// one k32 chunk = two m16n8k16 steps; warp tile 32x64 (2 m-tiles x 8 n-tiles)
#define FCOMP(Asb, Bsb)                                                  \
    _Pragma("unroll")                                                    \
    for (int s16 = 0; s16 < 2; ++s16) {                                  \
        const int r0 = s16 * 8 + tig, r1 = s16 * 8 + tig + 4;            \
        u32 af[2][4], bf[8][2];                                          \
        _Pragma("unroll")                                                \
        for (int mt = 0; mt < 2; mt++) {                                 \
            const int mb = wm * 32 + mt * 16;                            \
            af[mt][0] = (Asb)[SWZ(r0, mb + g)];                          \
            af[mt][1] = (Asb)[SWZ(r0, mb + g + 8)];                      \
            af[mt][2] = (Asb)[SWZ(r1, mb + g)];                          \
            af[mt][3] = (Asb)[SWZ(r1, mb + g + 8)];                      \
        }                                                                \
        _Pragma("unroll")                                                \
        for (int nt = 0; nt < 8; nt++) {                                 \
            const int nb = wn * 64 + nt * 8 + g;                         \
            bf[nt][0] = (Bsb)[SWZ(r0, nb)];                              \
            bf[nt][1] = (Bsb)[SWZ(r1, nb)];                              \
        }                                                                \
        _Pragma("unroll")                                                \
        for (int mt = 0; mt < 2; mt++)                                   \
            _Pragma("unroll")                                            \
            for (int nt = 0; nt < 8; nt++)                               \
                mma_f16(acc[mt][nt], af[mt], bf[nt]);                    \
    }

__device__ __forceinline__ u32 smem_u32p(const void* p) {
    return (u32)__cvta_generic_to_shared(p);
}
#define CP16(dst, src) asm volatile("cp.async.cg.shared.global [%0], [%1], 16;" :: "r"(dst), "l"(src))
#define CPC()          asm volatile("cp.async.commit_group;")
#define CPW(n)         asm volatile("cp.async.wait_group %0;" :: "n"(n))

// ---------------- 2: f = theta^T phi  (fp16 mma) + softmax partials --------
__global__ void __launch_bounds__(256, 2) fgemm_kernel() {
    __shared__ u32 As[2][16 * 128];
    __shared__ u32 Bs[2][16 * 128];
    const int b  = blockIdx.z;
    const int n0 = blockIdx.y * 128;
    const int m0 = blockIdx.x * 128;
    const u32* Th = d_Th + (size_t)b * (CI / 2) * NN;
    const u32* Ph = d_Ph + (size_t)b * (CI / 2) * NN;
    float* F = d_F + (size_t)b * NN * NN;

    const int t = threadIdx.x, lane = t & 31, warp = t >> 5;
    const int wm = warp & 3, wn = warp >> 2;
    const int g = lane >> 2, tig = lane & 3;
    float acc[2][8][4];
    #pragma unroll
    for (int i = 0; i < 2; i++)
        #pragma unroll
        for (int j = 0; j < 8; j++)
            #pragma unroll
            for (int r = 0; r < 4; r++) acc[i][j][r] = 0.f;

    const int ldr = t >> 4;     // 0..15 (k-pair row)
    const int ldc = t & 15;     // 16B chunk

    auto issue = [&](int ch, int s) {
        const int kk0 = ch * 16;
        #pragma unroll
        for (int h = 0; h < 2; h++) {
            const int col4 = (ldc + 16 * h) * 4;
            CP16(smem_u32p(&As[s][SWZ(ldr, col4)]), Th + (size_t)(kk0 + ldr) * NN + n0 + col4);
            CP16(smem_u32p(&Bs[s][SWZ(ldr, col4)]), Ph + (size_t)(kk0 + ldr) * NN + m0 + col4);
        }
        CPC();
    };

    issue(0, 0);
    #pragma unroll
    for (int ch = 0; ch < 4; ++ch) {
        const int s = ch & 1;
        if (ch < 3) { issue(ch + 1, s ^ 1); CPW(1); } else { CPW(0); }
        __syncthreads();
        FCOMP(As[s], Bs[s]);
        __syncthreads();
    }

    // store F tile
    #pragma unroll
    for (int mt = 0; mt < 2; mt++) {
        #pragma unroll
        for (int nt = 0; nt < 8; nt++) {
            const int n = n0 + wm * 32 + mt * 16 + g;
            const int m = m0 + wn * 64 + nt * 8 + tig * 2;
            *(float2*)(F + (size_t)n * NN + m)       = make_float2(acc[mt][nt][0], acc[mt][nt][1]);
            *(float2*)(F + (size_t)(n + 8) * NN + m) = make_float2(acc[mt][nt][2], acc[mt][nt][3]);
        }
    }

    // ---- fused column-softmax partials over this tile's 128 rows ----
    float* red = (float*)As;                 // 640 floats scratch
    float lv[8][2];
    #pragma unroll
    for (int nt = 0; nt < 8; nt++) {
        lv[nt][0] = fmaxf(fmaxf(acc[0][nt][0], acc[0][nt][2]), fmaxf(acc[1][nt][0], acc[1][nt][2]));
        lv[nt][1] = fmaxf(fmaxf(acc[0][nt][1], acc[0][nt][3]), fmaxf(acc[1][nt][1], acc[1][nt][3]));
        #pragma unroll
        for (int d = 4; d <= 16; d <<= 1) {
            lv[nt][0] = fmaxf(lv[nt][0], __shfl_xor_sync(0xffffffff, lv[nt][0], d));
            lv[nt][1] = fmaxf(lv[nt][1], __shfl_xor_sync(0xffffffff, lv[nt][1], d));
        }
    }
    __syncthreads();
    if (g == 0) {
        #pragma unroll
        for (int nt = 0; nt < 8; nt++) {
            const int col = wn * 64 + nt * 8 + tig * 2;
            red[wm * 128 + col]     = lv[nt][0];
            red[wm * 128 + col + 1] = lv[nt][1];
        }
    }
    __syncthreads();
    if (t < 128) {
        red[512 + t] = fmaxf(fmaxf(red[t], red[128 + t]), fmaxf(red[256 + t], red[384 + t]));
    }
    __syncthreads();
    #pragma unroll
    for (int nt = 0; nt < 8; nt++) {
        const int col = wn * 64 + nt * 8 + tig * 2;
        const float tm0 = red[512 + col], tm1 = red[512 + col + 1];
        lv[nt][0] = __expf(acc[0][nt][0] - tm0) + __expf(acc[0][nt][2] - tm0)
                  + __expf(acc[1][nt][0] - tm0) + __expf(acc[1][nt][2] - tm0);
        lv[nt][1] = __expf(acc[0][nt][1] - tm1) + __expf(acc[0][nt][3] - tm1)
                  + __expf(acc[1][nt][1] - tm1) + __expf(acc[1][nt][3] - tm1);
        #pragma unroll
        for (int d = 4; d <= 16; d <<= 1) {
            lv[nt][0] += __shfl_xor_sync(0xffffffff, lv[nt][0], d);
            lv[nt][1] += __shfl_xor_sync(0xffffffff, lv[nt][1], d);
        }
    }
    __syncthreads();
    if (g == 0) {
        #pragma unroll
        for (int nt = 0; nt < 8; nt++) {
            const int col = wn * 64 + nt * 8 + tig * 2;
            red[wm * 128 + col]     = lv[nt][0];
            red[wm * 128 + col + 1] = lv[nt][1];
        }
    }
    __syncthreads();
    if (t < 128) {
        const float s = red[t] + red[128 + t] + red[256 + t] + red[384 + t];
        const size_t idx = ((size_t)b * NBLK + blockIdx.y) * NN + m0 + t;
        d_pM[idx] = red[512 + t];
        d_pS[idx] = s;
    }
}

// ---------------- 3: merge softmax partials --------------------------------
__global__ void merge_stats_kernel() {
    const int b = blockIdx.y;
    const int m = blockIdx.x * 256 + threadIdx.x;
    const float* pM = d_pM + (size_t)b * NBLK * NN + m;
    const float* pS = d_pS + (size_t)b * NBLK * NN + m;
    float M = -CUDART_INF_F;
    #pragma unroll 10
    for (int i = 0; i < NBLK; i++) M = fmaxf(M, pM[(size_t)i * NN]);
    float s = 0.f;
    #pragma unroll 10
    for (int i = 0; i < NBLK; i++) s += pS[(size_t)i * NN] * __expf(pM[(size_t)i * NN] - M);
    d_colM[b * NN + m] = M;
    d_colR[b * NN + m] = 1.f / s;
}

// ---------------- 4: gs pairs [m2][c] = half2(g[c][m]/D[m]) ----------------
__global__ void gscale_kernel() {
    __shared__ float tsm[32][33];
    const int b  = blockIdx.z;
    const int m0 = blockIdx.x * 32;
    const int c0 = blockIdx.y * 32;
    const int tx = threadIdx.x, ty = threadIdx.y;        // 32 x 8
    #pragma unroll
    for (int j = 0; j < 32; j += 8)
        tsm[ty + j][tx] = d_G[((size_t)b * CI + c0 + ty + j) * NN + m0 + tx];
    __syncthreads();
    #pragma unroll
    for (int j = 0; j < 2; j++) {
        const int kk2l = ty + 8 * j;                     // 0..15
        const int m = m0 + 2 * kk2l;
        const float r0 = d_colR[b * NN + m];
        const float r1 = d_colR[b * NN + m + 1];
        d_GSh[((size_t)b * (NN / 2) + (m >> 1)) * CI + c0 + tx] =
            packh2(tsm[tx][2 * kk2l] * r0, tsm[tx][2 * kk2l + 1] * r1);
    }
}

// ---------------- 5: y = softmax(f) g  (fp16 mma, split-K) -----------------
__global__ void __launch_bounds__(256, 2) ygemm_kernel() {
    __shared__ u32 As[2][16 * 128];
    __shared__ u32 Bs[2][16 * 128];
    const int b     = blockIdx.z;
    const int split = blockIdx.y;
    const int n0    = blockIdx.x * 128;
    const float* F  = d_F + (size_t)b * NN * NN;
    const u32* GSh  = d_GSh + (size_t)b * (NN / 2) * CI;
    const float* CM = d_colM + b * NN;
    float* YP = d_YP + ((size_t)split * BB + b) * NN * CI;
    const int kbase = split * (NN / SPLITK);
    const int NCH   = (NN / SPLITK) / 32;                // 50

    const int t = threadIdx.x, lane = t & 31, warp = t >> 5;
    const int wm = warp & 3, wn = warp >> 2;
    const int g = lane >> 2, tig = lane & 3;
    float acc[2][8][4];
    #pragma unroll
    for (int i = 0; i < 2; i++)
        #pragma unroll
        for (int j = 0; j < 8; j++)
            #pragma unroll
            for (int r = 0; r < 4; r++) acc[i][j][r] = 0.f;

    const int q8 = t & 7;       // k-oct (4 floats)
    const int nr = t >> 3;      // 0..31
    const int ldr = t >> 4, ldc = t & 15;

    float4 fa[4];
    auto ldA = [&](int ch) {
        const int k0 = kbase + ch * 32;
        #pragma unroll
        for (int rr = 0; rr < 4; rr++)
            fa[rr] = *(const float4*)(F + (size_t)(n0 + rr * 32 + nr) * NN + k0 + q8 * 4);
    };
    auto stsA = [&](int s, int ch) {
        const int k0 = kbase + ch * 32;
        const float4 cm = *(const float4*)(CM + k0 + q8 * 4);
        #pragma unroll
        for (int rr = 0; rr < 4; rr++) {
            const int n = rr * 32 + nr;
            As[s][SWZ(2 * q8,     n)] = packh2(__expf(fa[rr].x - cm.x), __expf(fa[rr].y - cm.y));
            As[s][SWZ(2 * q8 + 1, n)] = packh2(__expf(fa[rr].z - cm.z), __expf(fa[rr].w - cm.w));
        }
    };
    auto issueB = [&](int ch, int s) {
        const int kk0 = (kbase + ch * 32) >> 1;
        #pragma unroll
        for (int h = 0; h < 2; h++) {
            const int col4 = (ldc + 16 * h) * 4;
            CP16(smem_u32p(&Bs[s][SWZ(ldr, col4)]), GSh + (size_t)(kk0 + ldr) * CI + col4);
        }
        CPC();
    };

    ldA(0); issueB(0, 0);
    for (int ch = 0; ch < NCH; ++ch) {
        const int s = ch & 1;
        if (ch + 1 < NCH) issueB(ch + 1, s ^ 1);
        stsA(s, ch);
        if (ch + 1 < NCH) ldA(ch + 1);
        if (ch + 1 < NCH) { CPW(1); } else { CPW(0); }
        __syncthreads();
        FCOMP(As[s], Bs[s]);
        __syncthreads();
    }

    #pragma unroll
    for (int mt = 0; mt < 2; mt++) {
        #pragma unroll
        for (int nt = 0; nt < 8; nt++) {
            const int n = n0 + wm * 32 + mt * 16 + g;
            const int c = wn * 64 + nt * 8 + tig * 2;
            *(float2*)(YP + (size_t)n * CI + c)       = make_float2(acc[mt][nt][0], acc[mt][nt][1]);
            *(float2*)(YP + (size_t)(n + 8) * CI + c) = make_float2(acc[mt][nt][2], acc[mt][nt][3]);
        }
    }
}

// ============================================================================
//                fp32 SIMT GEMM (small kernels: proj / out)
// ============================================================================
#define GEMM_PROLOG()                                   \
    __shared__ float Ass[8][128];                       \
    __shared__ float Bss[8][128];                       \
    float acc[8][8];                                    \
    _Pragma("unroll") for (int i = 0; i < 8; i++)       \
    _Pragma("unroll") for (int j = 0; j < 8; j++) acc[i][j] = 0.f; \
    const int t  = threadIdx.x;                         \
    const int tx = t & 15;                              \
    const int ty = t >> 4;                              \
    const int ar = t >> 1;                              \
    const int ac = (t & 1) * 4;                         \
    const int br = t >> 5;                              \
    const int bc = (t & 31) * 4;                        \
    (void)ar; (void)ac; (void)br; (void)bc;

#define GEMM_COMPUTE()                                  \
    __syncthreads();                                    \
    _Pragma("unroll")                                   \
    for (int k = 0; k < 8; ++k) {                       \
        float ra[8], rb[8];                             \
        *(float4*)(ra)     = *(const float4*)(&Ass[k][ty*4]);      \
        *(float4*)(ra + 4) = *(const float4*)(&Ass[k][ty*4 + 64]); \
        *(float4*)(rb)     = *(const float4*)(&Bss[k][tx*4]);      \
        *(float4*)(rb + 4) = *(const float4*)(&Bss[k][tx*4 + 64]); \
        _Pragma("unroll") for (int i = 0; i < 8; i++)   \
        _Pragma("unroll") for (int j = 0; j < 8; j++)   \
            acc[i][j] = fmaf(ra[i], rb[j], acc[i][j]);  \
    }                                                   \
    __syncthreads();

__device__ __forceinline__ int mrow(int i, int ty) {
    return (i < 4) ? (ty * 4 + i) : (64 + ty * 4 + i - 4);
}

// ---------------- 1: projections -------------------------------------------
__global__ void proj_kernel(const float* __restrict__ x,
                            const float* __restrict__ tw, const float* __restrict__ tb,
                            const float* __restrict__ pw, const float* __restrict__ pb,
                            const float* __restrict__ gw, const float* __restrict__ gb) {
    const int b = blockIdx.z;
    const int which = blockIdx.y;
    const float* W    = (which == 0) ? tw : (which == 1) ? pw : gw;
    const float* bias = (which == 0) ? tb : (which == 1) ? pb : gb;
    const float* X = x + (size_t)b * C * NN;
    const int n0 = blockIdx.x * 128;

    GEMM_PROLOG();
    for (int k0 = 0; k0 < C; k0 += 8) {
        float4 a = *(const float4*)(W + ar * C + k0 + ac);
        Ass[ac + 0][ar] = a.x; Ass[ac + 1][ar] = a.y;
        Ass[ac + 2][ar] = a.z; Ass[ac + 3][ar] = a.w;
        *(float4*)&Bss[br][bc] = *(const float4*)(X + (size_t)(k0 + br) * NN + n0 + bc);
        GEMM_COMPUTE();
    }
    float v[8][8];
    #pragma unroll
    for (int i = 0; i < 8; i++) {
        const float bv = bias[mrow(i, ty)];
        #pragma unroll
        for (int j = 0; j < 8; j++) v[i][j] = acc[i][j] + bv;
    }
    if (which < 2) {
        u32* dst = (which == 0 ? d_Th : d_Ph) + (size_t)b * (CI / 2) * NN;
        #pragma unroll
        for (int p = 0; p < 4; p++) {
            const int i0 = 2 * p;
            const int c2 = (p < 2) ? (ty * 2 + p) : (32 + ty * 2 + (p - 2));
            uint4 w0 = make_uint4(packh2(v[i0][0], v[i0 + 1][0]), packh2(v[i0][1], v[i0 + 1][1]),
                                  packh2(v[i0][2], v[i0 + 1][2]), packh2(v[i0][3], v[i0 + 1][3]));
            uint4 w1 = make_uint4(packh2(v[i0][4], v[i0 + 1][4]), packh2(v[i0][5], v[i0 + 1][5]),
                                  packh2(v[i0][6], v[i0 + 1][6]), packh2(v[i0][7], v[i0 + 1][7]));
            *(uint4*)(dst + (size_t)c2 * NN + n0 + tx * 4)      = w0;
            *(uint4*)(dst + (size_t)c2 * NN + n0 + 64 + tx * 4) = w1;
        }
    } else {
        float* P = d_G + (size_t)b * CI * NN;
        #pragma unroll
        for (int i = 0; i < 8; i++) {
            const int m = mrow(i, ty);
            *(float4*)(P + (size_t)m * NN + n0 + tx * 4)      = make_float4(v[i][0], v[i][1], v[i][2], v[i][3]);
            *(float4*)(P + (size_t)m * NN + n0 + 64 + tx * 4) = make_float4(v[i][4], v[i][5], v[i][6], v[i][7]);
        }
    }
}

// ---------------- 6: merge split-K partials + transpose to [c][n] ----------
__global__ void reduceY_kernel() {
    __shared__ float tsm[32][33];
    const int b  = blockIdx.z;
    const int n0 = blockIdx.x * 32;
    const int c0 = blockIdx.y * 32;
    const int tx = threadIdx.x, ty = threadIdx.y;
    const size_t S = (size_t)BB * NN * CI;
    const size_t base = (size_t)b * NN * CI;
    #pragma unroll
    for (int j = 0; j < 32; j += 8) {
        const size_t idx = base + (size_t)(n0 + ty + j) * CI + c0 + tx;
        tsm[ty + j][tx] = d_YP[idx] + d_YP[S + idx] + d_YP[2 * S + idx] + d_YP[3 * S + idx];
    }
    __syncthreads();
    #pragma unroll
    for (int j = 0; j < 32; j += 8)
        d_Y[(size_t)b * CI * NN + (size_t)(c0 + ty + j) * NN + n0 + tx] = tsm[tx][ty + j];
}

// ---------------- 7: out = Ww·y + Wb + x -----------------------------------
__global__ void out_kernel(const float* __restrict__ x,
                           const float* __restrict__ Ww, const float* __restrict__ Wb,
                           float* __restrict__ out) {
    const int b  = blockIdx.z;
    const int m0 = blockIdx.y * 128;
    const int n0 = blockIdx.x * 128;
    const float* Yb = d_Y + (size_t)b * CI * NN;

    GEMM_PROLOG();
    for (int k0 = 0; k0 < CI; k0 += 8) {
        float4 a = *(const float4*)(Ww + (m0 + ar) * CI + k0 + ac);
        Ass[ac + 0][ar] = a.x; Ass[ac + 1][ar] = a.y;
        Ass[ac + 2][ar] = a.z; Ass[ac + 3][ar] = a.w;
        *(float4*)&Bss[br][bc] = *(const float4*)(Yb + (size_t)(k0 + br) * NN + n0 + bc);
        GEMM_COMPUTE();
    }
    #pragma unroll
    for (int i = 0; i < 8; i++) {
        const int m = m0 + mrow(i, ty);
        const float bv = Wb[m];
        const float* xr = x + ((size_t)b * C + m) * NN;
        float* orow = out + ((size_t)b * C + m) * NN;
        float4 x0 = *(const float4*)(xr + n0 + tx * 4);
        float4 x1 = *(const float4*)(xr + n0 + 64 + tx * 4);
        *(float4*)(orow + n0 + tx * 4) =
            make_float4(acc[i][0]+bv+x0.x, acc[i][1]+bv+x0.y, acc[i][2]+bv+x0.z, acc[i][3]+bv+x0.w);
        *(float4*)(orow + n0 + 64 + tx * 4) =
            make_float4(acc[i][4]+bv+x1.x, acc[i][5]+bv+x1.y, acc[i][6]+bv+x1.z, acc[i][7]+bv+x1.w);
    }
}

// ---------------------------------------------------------------------------
extern "C" void kernel_launch(void* const* d_in, const int* in_sizes, int n_in,
                              void* d_out, int out_size) {
    const float* x  = (const float*)d_in[0];
    const float* gw = (const float*)d_in[1];
    const float* gb = (const float*)d_in[2];
    const float* tw = (const float*)d_in[3];
    const float* tb = (const float*)d_in[4];
    const float* pw = (const float*)d_in[5];
    const float* pb = (const float*)d_in[6];
    const float* Ww = (const float*)d_in[7];
    const float* Wb = (const float*)d_in[8];
    float* out = (float*)d_out;

    proj_kernel<<<dim3(NN / 128, 3, BB), 256>>>(x, tw, tb, pw, pb, gw, gb);
    fgemm_kernel<<<dim3(NN / 128, NN / 128, BB), 256>>>();
    merge_stats_kernel<<<dim3(NN / 256, BB), 256>>>();
    gscale_kernel<<<dim3(NN / 32, CI / 32, BB), dim3(32, 8)>>>();
    ygemm_kernel<<<dim3(NN / 128, SPLITK, BB), 256>>>();
    reduceY_kernel<<<dim3(NN / 32, CI / 32, BB), dim3(32, 8)>>>();
    out_kernel<<<dim3(NN / 128, C / 128, BB), 256>>>(x, Ww, Wb, out);
}

// round 7
// speedup vs baseline: 4.9016x; 1.2240x over previous
#include <cuda_runtime.h>
#include <cuda_fp16.h>
#include <math_constants.h>
#include <cstdint>

#define BB 2
#define C 256
#define CI 128
#define NN 6400
#define NH (NN / 2)
#define SPLITK 4
#define NBLK (NN / 128)     // 50

typedef unsigned u32;

// ---------------- scratch ---------------------------------------------------
__device__ u32   d_Th[BB * (CI / 2) * NN];             // theta pairs [c2][n] half2
__device__ u32   d_Ph[BB * (CI / 2) * NN];             // phi   pairs [c2][n] half2
__device__ float d_G[BB * CI * NN];                    // g proj fp32 [c][m]
__device__ u32   d_Sh[(size_t)BB * NN * NH];           // S = exp(f - tileMax), half2 [n][m2]
__device__ float d_pM[BB * NBLK * NN];                 // per (n-block, m) tile col max
__device__ float d_pS[BB * NBLK * NN];                 // per (n-block, m) tile col sum-exp
__device__ u32   d_corr[BB * NBLK * NH];               // half2 corr[nblk][m2]
__device__ u32   d_GSh[BB * NH * CI];                  // g pairs [m2][c] half2 (raw g)
__device__ float d_YP[(size_t)SPLITK * BB * NN * CI];  // split-K partials, [n][c]
__device__ u32   d_Yh[BB * (CI / 2) * NN];             // y pairs [c2][n] half2
__device__ u32   d_Wt[(CI / 2) * C];                   // Ww^T pairs [c2][m] half2

// ============================================================================
//                      fp16 mma.sync GEMM machinery
// ============================================================================
#define SWZ(row, col) ((row) * 128 + ((col) ^ (((row) & 3) << 3)))

__device__ __forceinline__ u32 packh2(float a, float b) {
    __half2 h = __halves2half2(__float2half_rn(a), __float2half_rn(b));
    return reinterpret_cast<u32&>(h);
}
__device__ __forceinline__ u32 hmul_u32(u32 a, u32 b) {
    __half2 r = __hmul2(reinterpret_cast<__half2&>(a), reinterpret_cast<__half2&>(b));
    return reinterpret_cast<u32&>(r);
}

__device__ __forceinline__ void mma_f16(float c[4], const u32 a[4], const u32 b[2]) {
    asm volatile(
        "mma.sync.aligned.m16n8k16.row.col.f32.f16.f16.f32 "
        "{%0,%1,%2,%3}, {%4,%5,%6,%7}, {%8,%9}, {%0,%1,%2,%3};"
        : "+f"(c[0]), "+f"(c[1]), "+f"(c[2]), "+f"(c[3])
        : "r"(a[0]), "r"(a[1]), "r"(a[2]), "r"(a[3]), "r"(b[0]), "r"(b[1]));
}

#define FCOMP(Asb, Bsb)                                                  \
    _Pragma("unroll")                                                    \
    for (int s16 = 0; s16 < 2; ++s16) {                                  \
        const int r0 = s16 * 8 + tig, r1 = s16 * 8 + tig + 4;            \
        u32 af[2][4], bf[8][2];                                          \
        _Pragma("unroll")                                                \
        for (int mt = 0; mt < 2; mt++) {                                 \
            const int mb = wm * 32 + mt * 16;                            \
            af[mt][0] = (Asb)[SWZ(r0, mb + g)];                          \
            af[mt][1] = (Asb)[SWZ(r0, mb + g + 8)];                      \
            af[mt][2] = (Asb)[SWZ(r1, mb + g)];                          \
            af[mt][3] = (Asb)[SWZ(r1, mb + g + 8)];                      \
        }                                                                \
        _Pragma("unroll")                                                \
        for (int nt = 0; nt < 8; nt++) {                                 \
            const int nb = wn * 64 + nt * 8 + g;                         \
            bf[nt][0] = (Bsb)[SWZ(r0, nb)];                              \
            bf[nt][1] = (Bsb)[SWZ(r1, nb)];                              \
        }                                                                \
        _Pragma("unroll")                                                \
        for (int mt = 0; mt < 2; mt++)                                   \
            _Pragma("unroll")                                            \
            for (int nt = 0; nt < 8; nt++)                               \
                mma_f16(acc[mt][nt], af[mt], bf[nt]);                    \
    }

__device__ __forceinline__ u32 smem_u32p(const void* p) {
    return (u32)__cvta_generic_to_shared(p);
}
#define CP16(dst, src) asm volatile("cp.async.cg.shared.global [%0], [%1], 16;" :: "r"(dst), "l"(src))
#define CPC()          asm volatile("cp.async.commit_group;")
#define CPW(n)         asm volatile("cp.async.wait_group %0;" :: "n"(n))

// ---------------- 2: f = theta^T phi ; store S=exp(f-tileMax) fp16 + stats -
__global__ void __launch_bounds__(256, 2) fgemm_kernel() {
    __shared__ u32 As[2][16 * 128];
    __shared__ u32 Bs[2][16 * 128];
    const int b  = blockIdx.z;
    const int n0 = blockIdx.y * 128;
    const int m0 = blockIdx.x * 128;
    const u32* Th = d_Th + (size_t)b * (CI / 2) * NN;
    const u32* Ph = d_Ph + (size_t)b * (CI / 2) * NN;
    u32* S = d_Sh + (size_t)b * NN * NH;

    const int t = threadIdx.x, lane = t & 31, warp = t >> 5;
    const int wm = warp & 3, wn = warp >> 2;
    const int g = lane >> 2, tig = lane & 3;
    float acc[2][8][4];
    #pragma unroll
    for (int i = 0; i < 2; i++)
        #pragma unroll
        for (int j = 0; j < 8; j++)
            #pragma unroll
            for (int r = 0; r < 4; r++) acc[i][j][r] = 0.f;

    const int ldr = t >> 4;     // 0..15 (k-pair row)
    const int ldc = t & 15;     // 16B chunk

    auto issue = [&](int ch, int s) {
        const int kk0 = ch * 16;
        #pragma unroll
        for (int h = 0; h < 2; h++) {
            const int col4 = (ldc + 16 * h) * 4;
            CP16(smem_u32p(&As[s][SWZ(ldr, col4)]), Th + (size_t)(kk0 + ldr) * NN + n0 + col4);
            CP16(smem_u32p(&Bs[s][SWZ(ldr, col4)]), Ph + (size_t)(kk0 + ldr) * NN + m0 + col4);
        }
        CPC();
    };

    issue(0, 0);
    #pragma unroll
    for (int ch = 0; ch < 4; ++ch) {
        const int s = ch & 1;
        if (ch < 3) { issue(ch + 1, s ^ 1); CPW(1); } else { CPW(0); }
        __syncthreads();
        FCOMP(As[s], Bs[s]);
        __syncthreads();
    }

    // ---- column-softmax: tile max, then exp (stored as S fp16) + sums ----
    float* red = (float*)As;                 // 640 floats scratch
    float lv[8][2];
    #pragma unroll
    for (int nt = 0; nt < 8; nt++) {
        lv[nt][0] = fmaxf(fmaxf(acc[0][nt][0], acc[0][nt][2]), fmaxf(acc[1][nt][0], acc[1][nt][2]));
        lv[nt][1] = fmaxf(fmaxf(acc[0][nt][1], acc[0][nt][3]), fmaxf(acc[1][nt][1], acc[1][nt][3]));
        #pragma unroll
        for (int d = 4; d <= 16; d <<= 1) {
            lv[nt][0] = fmaxf(lv[nt][0], __shfl_xor_sync(0xffffffff, lv[nt][0], d));
            lv[nt][1] = fmaxf(lv[nt][1], __shfl_xor_sync(0xffffffff, lv[nt][1], d));
        }
    }
    __syncthreads();
    if (g == 0) {
        #pragma unroll
        for (int nt = 0; nt < 8; nt++) {
            const int col = wn * 64 + nt * 8 + tig * 2;
            red[wm * 128 + col]     = lv[nt][0];
            red[wm * 128 + col + 1] = lv[nt][1];
        }
    }
    __syncthreads();
    if (t < 128) {
        red[512 + t] = fmaxf(fmaxf(red[t], red[128 + t]), fmaxf(red[256 + t], red[384 + t]));
    }
    __syncthreads();
    #pragma unroll
    for (int nt = 0; nt < 8; nt++) {
        const int col = wn * 64 + nt * 8 + tig * 2;
        const float tm0 = red[512 + col], tm1 = red[512 + col + 1];
        float s0 = 0.f, s1 = 0.f;
        #pragma unroll
        for (int mt = 0; mt < 2; mt++) {
            const int n = n0 + wm * 32 + mt * 16 + g;
            const float e0 = __expf(acc[mt][nt][0] - tm0);
            const float e1 = __expf(acc[mt][nt][1] - tm1);
            const float e2 = __expf(acc[mt][nt][2] - tm0);
            const float e3 = __expf(acc[mt][nt][3] - tm1);
            const size_t m2 = (size_t)((m0 + col) >> 1);
            S[(size_t)n * NH + m2]       = packh2(e0, e1);
            S[(size_t)(n + 8) * NH + m2] = packh2(e2, e3);
            s0 += e0 + e2; s1 += e1 + e3;
        }
        #pragma unroll
        for (int d = 4; d <= 16; d <<= 1) {
            s0 += __shfl_xor_sync(0xffffffff, s0, d);
            s1 += __shfl_xor_sync(0xffffffff, s1, d);
        }
        lv[nt][0] = s0; lv[nt][1] = s1;
    }
    __syncthreads();
    if (g == 0) {
        #pragma unroll
        for (int nt = 0; nt < 8; nt++) {
            const int col = wn * 64 + nt * 8 + tig * 2;
            red[wm * 128 + col]     = lv[nt][0];
            red[wm * 128 + col + 1] = lv[nt][1];
        }
    }
    __syncthreads();
    if (t < 128) {
        const float s = red[t] + red[128 + t] + red[256 + t] + red[384 + t];
        const size_t idx = ((size_t)b * NBLK + blockIdx.y) * NN + m0 + t;
        d_pM[idx] = red[512 + t];
        d_pS[idx] = s;
    }
}

// ---------------- 3: merge stats -> corr[nblk][m2] half2 -------------------
__global__ void merge_stats_kernel() {
    const int b  = blockIdx.y;
    const int m2 = blockIdx.x * 128 + threadIdx.x;       // 0..NH-1
    const float* pM = d_pM + (size_t)b * NBLK * NN + 2 * m2;
    const float* pS = d_pS + (size_t)b * NBLK * NN + 2 * m2;
    float M0 = -CUDART_INF_F, M1 = -CUDART_INF_F;
    #pragma unroll 10
    for (int i = 0; i < NBLK; i++) {
        M0 = fmaxf(M0, pM[(size_t)i * NN]);
        M1 = fmaxf(M1, pM[(size_t)i * NN + 1]);
    }
    float s0 = 0.f, s1 = 0.f;
    #pragma unroll 10
    for (int i = 0; i < NBLK; i++) {
        s0 += pS[(size_t)i * NN]     * __expf(pM[(size_t)i * NN]     - M0);
        s1 += pS[(size_t)i * NN + 1] * __expf(pM[(size_t)i * NN + 1] - M1);
    }
    const float R0 = 1.f / s0, R1 = 1.f / s1;
    u32* cw = d_corr + (size_t)b * NBLK * NH + m2;
    #pragma unroll 10
    for (int i = 0; i < NBLK; i++) {
        cw[(size_t)i * NH] = packh2(__expf(pM[(size_t)i * NN]     - M0) * R0,
                                    __expf(pM[(size_t)i * NN + 1] - M1) * R1);
    }
}

// ---------------- 4: gs pairs [m2][c] = half2(g[c][m]) ---------------------
__global__ void gscale_kernel() {
    __shared__ float tsm[32][33];
    const int b  = blockIdx.z;
    const int m0 = blockIdx.x * 32;
    const int c0 = blockIdx.y * 32;
    const int tx = threadIdx.x, ty = threadIdx.y;        // 32 x 8
    #pragma unroll
    for (int j = 0; j < 32; j += 8)
        tsm[ty + j][tx] = d_G[((size_t)b * CI + c0 + ty + j) * NN + m0 + tx];
    __syncthreads();
    #pragma unroll
    for (int j = 0; j < 2; j++) {
        const int kk2l = ty + 8 * j;                     // 0..15
        d_GSh[((size_t)b * NH + ((m0 >> 1) + kk2l)) * CI + c0 + tx] =
            packh2(tsm[tx][2 * kk2l], tsm[tx][2 * kk2l + 1]);
    }
}

// ---------------- 5: y = (S*corr) g  (fp16 mma, split-K) -------------------
__global__ void __launch_bounds__(256, 2) ygemm_kernel() {
    __shared__ u32 As[2][16 * 128];
    __shared__ u32 Bs[2][16 * 128];
    const int b     = blockIdx.z;
    const int split = blockIdx.y;
    const int n0    = blockIdx.x * 128;
    const u32* S    = d_Sh + (size_t)b * NN * NH;
    const u32* GSh  = d_GSh + (size_t)b * NH * CI;
    const u32* corr = d_corr + ((size_t)b * NBLK + blockIdx.x) * NH;
    float* YP = d_YP + ((size_t)split * BB + b) * NN * CI;
    const int kbase = split * (NN / SPLITK);
    const int NCH   = (NN / SPLITK) / 32;                // 50

    const int t = threadIdx.x, lane = t & 31, warp = t >> 5;
    const int wm = warp & 3, wn = warp >> 2;
    const int g = lane >> 2, tig = lane & 3;
    float acc[2][8][4];
    #pragma unroll
    for (int i = 0; i < 2; i++)
        #pragma unroll
        for (int j = 0; j < 8; j++)
            #pragma unroll
            for (int r = 0; r < 4; r++) acc[i][j][r] = 0.f;

    const int q8 = t & 7;       // k u32-pair index
    const int nr = t >> 3;      // 0..31
    const int ldr = t >> 4, ldc = t & 15;

    uint2 fa2[4], cr2;
    auto ldA = [&](int ch) {
        const int m2b = (kbase >> 1) + ch * 16 + q8 * 2;
        #pragma unroll
        for (int rr = 0; rr < 4; rr++)
            fa2[rr] = *(const uint2*)(S + (size_t)(n0 + rr * 32 + nr) * NH + m2b);
        cr2 = *(const uint2*)(corr + m2b);
    };
    auto stsA = [&](int s) {
        #pragma unroll
        for (int rr = 0; rr < 4; rr++) {
            const int n = rr * 32 + nr;
            As[s][SWZ(2 * q8,     n)] = hmul_u32(fa2[rr].x, cr2.x);
            As[s][SWZ(2 * q8 + 1, n)] = hmul_u32(fa2[rr].y, cr2.y);
        }
    };
    auto issueB = [&](int ch, int s) {
        const int kk0 = (kbase + ch * 32) >> 1;
        #pragma unroll
        for (int h = 0; h < 2; h++) {
            const int col4 = (ldc + 16 * h) * 4;
            CP16(smem_u32p(&Bs[s][SWZ(ldr, col4)]), GSh + (size_t)(kk0 + ldr) * CI + col4);
        }
        CPC();
    };

    ldA(0); issueB(0, 0);
    for (int ch = 0; ch < NCH; ++ch) {
        const int s = ch & 1;
        if (ch + 1 < NCH) issueB(ch + 1, s ^ 1);
        stsA(s);
        if (ch + 1 < NCH) ldA(ch + 1);
        if (ch + 1 < NCH) { CPW(1); } else { CPW(0); }
        __syncthreads();
        FCOMP(As[s], Bs[s]);
        __syncthreads();
    }

    #pragma unroll
    for (int mt = 0; mt < 2; mt++) {
        #pragma unroll
        for (int nt = 0; nt < 8; nt++) {
            const int n = n0 + wm * 32 + mt * 16 + g;
            const int c = wn * 64 + nt * 8 + tig * 2;
            *(float2*)(YP + (size_t)n * CI + c)       = make_float2(acc[mt][nt][0], acc[mt][nt][1]);
            *(float2*)(YP + (size_t)(n + 8) * CI + c) = make_float2(acc[mt][nt][2], acc[mt][nt][3]);
        }
    }
}

// ---------------- 6: merge split-K + transpose + pack half2 [c2][n] --------
__global__ void reduceY_kernel() {
    __shared__ float tsm[32][33];
    const int b  = blockIdx.z;
    const int n0 = blockIdx.x * 32;
    const int c0 = blockIdx.y * 32;
    const int tx = threadIdx.x, ty = threadIdx.y;        // 32 x 8
    const size_t SS = (size_t)BB * NN * CI;
    const size_t base = (size_t)b * NN * CI;
    #pragma unroll
    for (int j = 0; j < 32; j += 8) {
        const size_t idx = base + (size_t)(n0 + ty + j) * CI + c0 + tx;
        tsm[ty + j][tx] = d_YP[idx] + d_YP[SS + idx] + d_YP[2 * SS + idx] + d_YP[3 * SS + idx];
    }
    __syncthreads();
    #pragma unroll
    for (int j = 0; j < 2; j++) {
        const int cl2 = ty + 8 * j;                      // 0..15
        d_Yh[((size_t)b * (CI / 2) + ((c0 >> 1) + cl2)) * NN + n0 + tx] =
            packh2(tsm[tx][2 * cl2], tsm[tx][2 * cl2 + 1]);
    }
}

// ---------------- 8: pack Ww^T pairs [c2][m] -------------------------------
__global__ void wconv_kernel(const float* __restrict__ Ww) {
    const int id = blockIdx.x * 256 + threadIdx.x;       // 0..16383
    const int c2 = id >> 8, m = id & 255;
    d_Wt[c2 * C + m] = packh2(Ww[m * CI + 2 * c2], Ww[m * CI + 2 * c2 + 1]);
}

// ---------------- 9: out = Ww·y + Wb + x  (fp16 mma) -----------------------
__global__ void __launch_bounds__(256, 2) out_kernel(const float* __restrict__ x,
                                                     const float* __restrict__ Wb,
                                                     float* __restrict__ out) {
    __shared__ u32 As[2][16 * 128];
    __shared__ u32 Bs[2][16 * 128];
    const int b  = blockIdx.z;
    const int m0 = blockIdx.y * 128;
    const int n0 = blockIdx.x * 128;
    const u32* Yh = d_Yh + (size_t)b * (CI / 2) * NN;

    const int t = threadIdx.x, lane = t & 31, warp = t >> 5;
    const int wm = warp & 3, wn = warp >> 2;
    const int g = lane >> 2, tig = lane & 3;
    float acc[2][8][4];
    #pragma unroll
    for (int i = 0; i < 2; i++)
        #pragma unroll
        for (int j = 0; j < 8; j++)
            #pragma unroll
            for (int r = 0; r < 4; r++) acc[i][j][r] = 0.f;

    const int ldr = t >> 4, ldc = t & 15;

    auto issue = [&](int ch, int s) {
        const int kk0 = ch * 16;
        #pragma unroll
        for (int h = 0; h < 2; h++) {
            const int col4 = (ldc + 16 * h) * 4;
            CP16(smem_u32p(&As[s][SWZ(ldr, col4)]), d_Wt + (size_t)(kk0 + ldr) * C + m0 + col4);
            CP16(smem_u32p(&Bs[s][SWZ(ldr, col4)]), Yh + (size_t)(kk0 + ldr) * NN + n0 + col4);
        }
        CPC();
    };

    issue(0, 0);
    #pragma unroll
    for (int ch = 0; ch < 4; ++ch) {
        const int s = ch & 1;
        if (ch < 3) { issue(ch + 1, s ^ 1); CPW(1); } else { CPW(0); }
        __syncthreads();
        FCOMP(As[s], Bs[s]);
        __syncthreads();
    }

    #pragma unroll
    for (int mt = 0; mt < 2; mt++) {
        #pragma unroll
        for (int nt = 0; nt < 8; nt++) {
            const int m = m0 + wm * 32 + mt * 16 + g;
            const int n = n0 + wn * 64 + nt * 8 + tig * 2;
            {
                const float bv = Wb[m];
                const float2 xv = *(const float2*)(x + ((size_t)b * C + m) * NN + n);
                *(float2*)(out + ((size_t)b * C + m) * NN + n) =
                    make_float2(acc[mt][nt][0] + bv + xv.x, acc[mt][nt][1] + bv + xv.y);
            }
            {
                const float bv = Wb[m + 8];
                const float2 xv = *(const float2*)(x + ((size_t)b * C + m + 8) * NN + n);
                *(float2*)(out + ((size_t)b * C + m + 8) * NN + n) =
                    make_float2(acc[mt][nt][2] + bv + xv.x, acc[mt][nt][3] + bv + xv.y);
            }
        }
    }
}

// ============================================================================
//                fp32 SIMT GEMM (proj only)
// ============================================================================
#define GEMM_PROLOG()                                   \
    __shared__ float Ass[8][128];                       \
    __shared__ float Bss[8][128];                       \
    float acc[8][8];                                    \
    _Pragma("unroll") for (int i = 0; i < 8; i++)       \
    _Pragma("unroll") for (int j = 0; j < 8; j++) acc[i][j] = 0.f; \
    const int t  = threadIdx.x;                         \
    const int tx = t & 15;                              \
    const int ty = t >> 4;                              \
    const int ar = t >> 1;                              \
    const int ac = (t & 1) * 4;                         \
    const int br = t >> 5;                              \
    const int bc = (t & 31) * 4;                        \
    (void)ar; (void)ac; (void)br; (void)bc;

#define GEMM_COMPUTE()                                  \
    __syncthreads();                                    \
    _Pragma("unroll")                                   \
    for (int k = 0; k < 8; ++k) {                       \
        float ra[8], rb[8];                             \
        *(float4*)(ra)     = *(const float4*)(&Ass[k][ty*4]);      \
        *(float4*)(ra + 4) = *(const float4*)(&Ass[k][ty*4 + 64]); \
        *(float4*)(rb)     = *(const float4*)(&Bss[k][tx*4]);      \
        *(float4*)(rb + 4) = *(const float4*)(&Bss[k][tx*4 + 64]); \
        _Pragma("unroll") for (int i = 0; i < 8; i++)   \
        _Pragma("unroll") for (int j = 0; j < 8; j++)   \
            acc[i][j] = fmaf(ra[i], rb[j], acc[i][j]);  \
    }                                                   \
    __syncthreads();

__device__ __forceinline__ int mrow(int i, int ty) {
    return (i < 4) ? (ty * 4 + i) : (64 + ty * 4 + i - 4);
}

// ---------------- 1: projections -------------------------------------------
__global__ void proj_kernel(const float* __restrict__ x,
                            const float* __restrict__ tw, const float* __restrict__ tb,
                            const float* __restrict__ pw, const float* __restrict__ pb,
                            const float* __restrict__ gw, const float* __restrict__ gb) {
    const int b = blockIdx.z;
    const int which = blockIdx.y;
    const float* W    = (which == 0) ? tw : (which == 1) ? pw : gw;
    const float* bias = (which == 0) ? tb : (which == 1) ? pb : gb;
    const float* X = x + (size_t)b * C * NN;
    const int n0 = blockIdx.x * 128;

    GEMM_PROLOG();
    for (int k0 = 0; k0 < C; k0 += 8) {
        float4 a = *(const float4*)(W + ar * C + k0 + ac);
        Ass[ac + 0][ar] = a.x; Ass[ac + 1][ar] = a.y;
        Ass[ac + 2][ar] = a.z; Ass[ac + 3][ar] = a.w;
        *(float4*)&Bss[br][bc] = *(const float4*)(X + (size_t)(k0 + br) * NN + n0 + bc);
        GEMM_COMPUTE();
    }
    float v[8][8];
    #pragma unroll
    for (int i = 0; i < 8; i++) {
        const float bv = bias[mrow(i, ty)];
        #pragma unroll
        for (int j = 0; j < 8; j++) v[i][j] = acc[i][j] + bv;
    }
    if (which < 2) {
        u32* dst = (which == 0 ? d_Th : d_Ph) + (size_t)b * (CI / 2) * NN;
        #pragma unroll
        for (int p = 0; p < 4; p++) {
            const int i0 = 2 * p;
            const int c2 = (p < 2) ? (ty * 2 + p) : (32 + ty * 2 + (p - 2));
            uint4 w0 = make_uint4(packh2(v[i0][0], v[i0 + 1][0]), packh2(v[i0][1], v[i0 + 1][1]),
                                  packh2(v[i0][2], v[i0 + 1][2]), packh2(v[i0][3], v[i0 + 1][3]));
            uint4 w1 = make_uint4(packh2(v[i0][4], v[i0 + 1][4]), packh2(v[i0][5], v[i0 + 1][5]),
                                  packh2(v[i0][6], v[i0 + 1][6]), packh2(v[i0][7], v[i0 + 1][7]));
            *(uint4*)(dst + (size_t)c2 * NN + n0 + tx * 4)      = w0;
            *(uint4*)(dst + (size_t)c2 * NN + n0 + 64 + tx * 4) = w1;
        }
    } else {
        float* P = d_G + (size_t)b * CI * NN;
        #pragma unroll
        for (int i = 0; i < 8; i++) {
            const int m = mrow(i, ty);
            *(float4*)(P + (size_t)m * NN + n0 + tx * 4)      = make_float4(v[i][0], v[i][1], v[i][2], v[i][3]);
            *(float4*)(P + (size_t)m * NN + n0 + 64 + tx * 4) = make_float4(v[i][4], v[i][5], v[i][6], v[i][7]);
        }
    }
}

// ---------------------------------------------------------------------------
extern "C" void kernel_launch(void* const* d_in, const int* in_sizes, int n_in,
                              void* d_out, int out_size) {
    const float* x  = (const float*)d_in[0];
    const float* gw = (const float*)d_in[1];
    const float* gb = (const float*)d_in[2];
    const float* tw = (const float*)d_in[3];
    const float* tb = (const float*)d_in[4];
    const float* pw = (const float*)d_in[5];
    const float* pb = (const float*)d_in[6];
    const float* Ww = (const float*)d_in[7];
    const float* Wb = (const float*)d_in[8];
    float* out = (float*)d_out;

    wconv_kernel<<<(CI / 2) * C / 256, 256>>>(Ww);
    proj_kernel<<<dim3(NN / 128, 3, BB), 256>>>(x, tw, tb, pw, pb, gw, gb);
    fgemm_kernel<<<dim3(NN / 128, NN / 128, BB), 256>>>();
    merge_stats_kernel<<<dim3(NH / 128, BB), 128>>>();
    gscale_kernel<<<dim3(NN / 32, CI / 32, BB), dim3(32, 8)>>>();
    ygemm_kernel<<<dim3(NN / 128, SPLITK, BB), 256>>>();
    reduceY_kernel<<<dim3(NN / 32, CI / 32, BB), dim3(32, 8)>>>();
    out_kernel<<<dim3(NN / 128, C / 128, BB), 256>>>(x, Wb, out);
}

// round 8
// speedup vs baseline: 6.4503x; 1.3160x over previous
#include <cuda_runtime.h>
#include <cuda_fp16.h>
#include <math_constants.h>
#include <cstdint>

#define BB 2
#define C 256
#define CI 128
#define NN 6400
#define NH (NN / 2)
#define SPLITK 4
#define NBLK (NN / 128)     // 50

typedef unsigned u32;

// ---------------- scratch ---------------------------------------------------
__device__ u32   d_Xh[BB * (C / 2) * NN];              // x pairs [c2][n] half2
__device__ u32   d_Wh[(C / 2) * 384];                  // stacked proj weights [k2][which*128+o]
__device__ u32   d_Th[BB * (CI / 2) * NN];             // theta pairs [c2][n] half2
__device__ u32   d_Ph[BB * (CI / 2) * NN];             // phi   pairs [c2][n] half2
__device__ float d_G[BB * CI * NN];                    // g proj fp32 [c][m]
__device__ u32   d_Sh[(size_t)BB * NN * NH];           // S = exp(f - tileMax), half2 [n][m2]
__device__ float d_pM[BB * NBLK * NN];                 // per (n-block, m) tile col max
__device__ float d_pS[BB * NBLK * NN];                 // per (n-block, m) tile col sum-exp
__device__ u32   d_corr[BB * NBLK * NH];               // half2 corr[nblk][m2]
__device__ u32   d_GSh[BB * NH * CI];                  // g pairs [m2][c] half2 (raw g)
__device__ float d_YP[(size_t)SPLITK * BB * NN * CI];  // split-K partials, [n][c]
__device__ u32   d_Yh[BB * (CI / 2) * NN];             // y pairs [c2][n] half2
__device__ u32   d_Wt[(CI / 2) * C];                   // Ww^T pairs [c2][m] half2

// ============================================================================
//                      fp16 mma.sync GEMM machinery
// ============================================================================
#define SWZ(row, col) ((row) * 128 + ((col) ^ (((row) & 3) << 3)))

__device__ __forceinline__ u32 packh2(float a, float b) {
    __half2 h = __halves2half2(__float2half_rn(a), __float2half_rn(b));
    return reinterpret_cast<u32&>(h);
}
__device__ __forceinline__ u32 hmul_u32(u32 a, u32 b) {
    __half2 r = __hmul2(reinterpret_cast<__half2&>(a), reinterpret_cast<__half2&>(b));
    return reinterpret_cast<u32&>(r);
}

__device__ __forceinline__ void mma_f16(float c[4], const u32 a[4], const u32 b[2]) {
    asm volatile(
        "mma.sync.aligned.m16n8k16.row.col.f32.f16.f16.f32 "
        "{%0,%1,%2,%3}, {%4,%5,%6,%7}, {%8,%9}, {%0,%1,%2,%3};"
        : "+f"(c[0]), "+f"(c[1]), "+f"(c[2]), "+f"(c[3])
        : "r"(a[0]), "r"(a[1]), "r"(a[2]), "r"(a[3]), "r"(b[0]), "r"(b[1]));
}

#define FCOMP(Asb, Bsb)                                                  \
    _Pragma("unroll")                                                    \
    for (int s16 = 0; s16 < 2; ++s16) {                                  \
        const int r0 = s16 * 8 + tig, r1 = s16 * 8 + tig + 4;            \
        u32 af[2][4], bf[8][2];                                          \
        _Pragma("unroll")                                                \
        for (int mt = 0; mt < 2; mt++) {                                 \
            const int mb = wm * 32 + mt * 16;                            \
            af[mt][0] = (Asb)[SWZ(r0, mb + g)];                          \
            af[mt][1] = (Asb)[SWZ(r0, mb + g + 8)];                      \
            af[mt][2] = (Asb)[SWZ(r1, mb + g)];                          \
            af[mt][3] = (Asb)[SWZ(r1, mb + g + 8)];                      \
        }                                                                \
        _Pragma("unroll")                                                \
        for (int nt = 0; nt < 8; nt++) {                                 \
            const int nb = wn * 64 + nt * 8 + g;                         \
            bf[nt][0] = (Bsb)[SWZ(r0, nb)];                              \
            bf[nt][1] = (Bsb)[SWZ(r1, nb)];                              \
        }                                                                \
        _Pragma("unroll")                                                \
        for (int mt = 0; mt < 2; mt++)                                   \
            _Pragma("unroll")                                            \
            for (int nt = 0; nt < 8; nt++)                               \
                mma_f16(acc[mt][nt], af[mt], bf[nt]);                    \
    }

__device__ __forceinline__ u32 smem_u32p(const void* p) {
    return (u32)__cvta_generic_to_shared(p);
}
#define CP16(dst, src) asm volatile("cp.async.cg.shared.global [%0], [%1], 16;" :: "r"(dst), "l"(src))
#define CPC()          asm volatile("cp.async.commit_group;")
#define CPW(n)         asm volatile("cp.async.wait_group %0;" :: "n"(n))

#define ACC_INIT()                                      \
    float acc[2][8][4];                                 \
    _Pragma("unroll") for (int i = 0; i < 2; i++)       \
    _Pragma("unroll") for (int j = 0; j < 8; j++)       \
    _Pragma("unroll") for (int r = 0; r < 4; r++) acc[i][j][r] = 0.f;

// ---------------- 0a: pack x into half2 pairs [c2][n] ----------------------
__global__ void packX_kernel(const float* __restrict__ x) {
    const int n  = blockIdx.x * 256 + threadIdx.x;
    const int c2 = blockIdx.y;
    const int b  = blockIdx.z;
    const float* xb = x + ((size_t)b * C + 2 * c2) * NN;
    d_Xh[((size_t)b * (C / 2) + c2) * NN + n] = packh2(xb[n], xb[NN + n]);
}

// ---------------- 0b: pack stacked proj weights [k2][which*128+o] ----------
__global__ void packWall_kernel(const float* __restrict__ tw,
                                const float* __restrict__ pw,
                                const float* __restrict__ gw) {
    const int id = blockIdx.x * 256 + threadIdx.x;       // 0 .. 128*384-1
    const int k2 = id / 384, col = id % 384;
    const int which = col >> 7, o = col & 127;
    const float* W = (which == 0) ? tw : (which == 1) ? pw : gw;
    d_Wh[id] = packh2(W[o * C + 2 * k2], W[o * C + 2 * k2 + 1]);
}

// ---------------- 1: projections (fp16 mma) --------------------------------
__global__ void __launch_bounds__(256, 2) proj_kernel(const float* __restrict__ tb,
                                                      const float* __restrict__ pb,
                                                      const float* __restrict__ gb) {
    __shared__ u32 As[2][16 * 128];
    __shared__ u32 Bs[2][16 * 128];
    const int b     = blockIdx.z;
    const int which = blockIdx.y;
    const int n0    = blockIdx.x * 128;
    const u32* Xh = d_Xh + (size_t)b * (C / 2) * NN;
    const float* bias = (which == 0) ? tb : (which == 1) ? pb : gb;

    const int t = threadIdx.x, lane = t & 31, warp = t >> 5;
    const int wm = warp & 3, wn = warp >> 2;
    const int g = lane >> 2, tig = lane & 3;
    ACC_INIT();

    const int ldr = t >> 4, ldc = t & 15;

    auto issue = [&](int ch, int s) {
        const int kk0 = ch * 16;
        #pragma unroll
        for (int h = 0; h < 2; h++) {
            const int col4 = (ldc + 16 * h) * 4;
            CP16(smem_u32p(&As[s][SWZ(ldr, col4)]), d_Wh + (size_t)(kk0 + ldr) * 384 + which * 128 + col4);
            CP16(smem_u32p(&Bs[s][SWZ(ldr, col4)]), Xh + (size_t)(kk0 + ldr) * NN + n0 + col4);
        }
        CPC();
    };

    issue(0, 0);
    #pragma unroll
    for (int ch = 0; ch < 8; ++ch) {
        const int s = ch & 1;
        if (ch < 7) { issue(ch + 1, s ^ 1); CPW(1); } else { CPW(0); }
        __syncthreads();
        FCOMP(As[s], Bs[s]);
        __syncthreads();
    }

    if (which < 2) {
        u32* dst = (which == 0 ? d_Th : d_Ph) + (size_t)b * (CI / 2) * NN;
        #pragma unroll
        for (int mt = 0; mt < 2; mt++) {
            const int r = wm * 32 + mt * 16 + g;          // even lanes: even r
            const float bv0 = bias[r], bv8 = bias[r + 8];
            #pragma unroll
            for (int nt = 0; nt < 8; nt++) {
                const int n = n0 + wn * 64 + nt * 8 + tig * 2;
                float v0 = acc[mt][nt][0] + bv0, v1 = acc[mt][nt][1] + bv0;
                float v2 = acc[mt][nt][2] + bv8, v3 = acc[mt][nt][3] + bv8;
                const float p0 = __shfl_xor_sync(0xffffffff, v0, 4);
                const float p1 = __shfl_xor_sync(0xffffffff, v1, 4);
                const float p2 = __shfl_xor_sync(0xffffffff, v2, 4);
                const float p3 = __shfl_xor_sync(0xffffffff, v3, 4);
                if ((g & 1) == 0) {
                    *(uint2*)(dst + (size_t)(r >> 1) * NN + n) =
                        make_uint2(packh2(v0, p0), packh2(v1, p1));
                    *(uint2*)(dst + (size_t)((r + 8) >> 1) * NN + n) =
                        make_uint2(packh2(v2, p2), packh2(v3, p3));
                }
            }
        }
    } else {
        float* P = d_G + (size_t)b * CI * NN;
        #pragma unroll
        for (int mt = 0; mt < 2; mt++) {
            const int r = wm * 32 + mt * 16 + g;
            const float bv0 = bias[r], bv8 = bias[r + 8];
            #pragma unroll
            for (int nt = 0; nt < 8; nt++) {
                const int n = n0 + wn * 64 + nt * 8 + tig * 2;
                *(float2*)(P + (size_t)r * NN + n) =
                    make_float2(acc[mt][nt][0] + bv0, acc[mt][nt][1] + bv0);
                *(float2*)(P + (size_t)(r + 8) * NN + n) =
                    make_float2(acc[mt][nt][2] + bv8, acc[mt][nt][3] + bv8);
            }
        }
    }
}

// ---------------- 2: f = theta^T phi ; store S=exp(f-tileMax) fp16 + stats -
__global__ void __launch_bounds__(256, 2) fgemm_kernel() {
    __shared__ u32 As[2][16 * 128];
    __shared__ u32 Bs[2][16 * 128];
    const int b  = blockIdx.z;
    const int n0 = blockIdx.y * 128;
    const int m0 = blockIdx.x * 128;
    const u32* Th = d_Th + (size_t)b * (CI / 2) * NN;
    const u32* Ph = d_Ph + (size_t)b * (CI / 2) * NN;
    u32* S = d_Sh + (size_t)b * NN * NH;

    const int t = threadIdx.x, lane = t & 31, warp = t >> 5;
    const int wm = warp & 3, wn = warp >> 2;
    const int g = lane >> 2, tig = lane & 3;
    ACC_INIT();

    const int ldr = t >> 4, ldc = t & 15;

    auto issue = [&](int ch, int s) {
        const int kk0 = ch * 16;
        #pragma unroll
        for (int h = 0; h < 2; h++) {
            const int col4 = (ldc + 16 * h) * 4;
            CP16(smem_u32p(&As[s][SWZ(ldr, col4)]), Th + (size_t)(kk0 + ldr) * NN + n0 + col4);
            CP16(smem_u32p(&Bs[s][SWZ(ldr, col4)]), Ph + (size_t)(kk0 + ldr) * NN + m0 + col4);
        }
        CPC();
    };

    issue(0, 0);
    #pragma unroll
    for (int ch = 0; ch < 4; ++ch) {
        const int s = ch & 1;
        if (ch < 3) { issue(ch + 1, s ^ 1); CPW(1); } else { CPW(0); }
        __syncthreads();
        FCOMP(As[s], Bs[s]);
        __syncthreads();
    }

    // ---- column-softmax: tile max, then exp (stored as S fp16) + sums ----
    float* red = (float*)As;
    float lv[8][2];
    #pragma unroll
    for (int nt = 0; nt < 8; nt++) {
        lv[nt][0] = fmaxf(fmaxf(acc[0][nt][0], acc[0][nt][2]), fmaxf(acc[1][nt][0], acc[1][nt][2]));
        lv[nt][1] = fmaxf(fmaxf(acc[0][nt][1], acc[0][nt][3]), fmaxf(acc[1][nt][1], acc[1][nt][3]));
        #pragma unroll
        for (int d = 4; d <= 16; d <<= 1) {
            lv[nt][0] = fmaxf(lv[nt][0], __shfl_xor_sync(0xffffffff, lv[nt][0], d));
            lv[nt][1] = fmaxf(lv[nt][1], __shfl_xor_sync(0xffffffff, lv[nt][1], d));
        }
    }
    __syncthreads();
    if (g == 0) {
        #pragma unroll
        for (int nt = 0; nt < 8; nt++) {
            const int col = wn * 64 + nt * 8 + tig * 2;
            red[wm * 128 + col]     = lv[nt][0];
            red[wm * 128 + col + 1] = lv[nt][1];
        }
    }
    __syncthreads();
    if (t < 128) {
        red[512 + t] = fmaxf(fmaxf(red[t], red[128 + t]), fmaxf(red[256 + t], red[384 + t]));
    }
    __syncthreads();
    #pragma unroll
    for (int nt = 0; nt < 8; nt++) {
        const int col = wn * 64 + nt * 8 + tig * 2;
        const float tm0 = red[512 + col], tm1 = red[512 + col + 1];
        float s0 = 0.f, s1 = 0.f;
        #pragma unroll
        for (int mt = 0; mt < 2; mt++) {
            const int n = n0 + wm * 32 + mt * 16 + g;
            const float e0 = __expf(acc[mt][nt][0] - tm0);
            const float e1 = __expf(acc[mt][nt][1] - tm1);
            const float e2 = __expf(acc[mt][nt][2] - tm0);
            const float e3 = __expf(acc[mt][nt][3] - tm1);
            const size_t m2 = (size_t)((m0 + col) >> 1);
            S[(size_t)n * NH + m2]       = packh2(e0, e1);
            S[(size_t)(n + 8) * NH + m2] = packh2(e2, e3);
            s0 += e0 + e2; s1 += e1 + e3;
        }
        #pragma unroll
        for (int d = 4; d <= 16; d <<= 1) {
            s0 += __shfl_xor_sync(0xffffffff, s0, d);
            s1 += __shfl_xor_sync(0xffffffff, s1, d);
        }
        lv[nt][0] = s0; lv[nt][1] = s1;
    }
    __syncthreads();
    if (g == 0) {
        #pragma unroll
        for (int nt = 0; nt < 8; nt++) {
            const int col = wn * 64 + nt * 8 + tig * 2;
            red[wm * 128 + col]     = lv[nt][0];
            red[wm * 128 + col + 1] = lv[nt][1];
        }
    }
    __syncthreads();
    if (t < 128) {
        const float s = red[t] + red[128 + t] + red[256 + t] + red[384 + t];
        const size_t idx = ((size_t)b * NBLK + blockIdx.y) * NN + m0 + t;
        d_pM[idx] = red[512 + t];
        d_pS[idx] = s;
    }
}

// ---------------- 3: merge stats -> corr[nblk][m2] half2 (parallel) --------
__global__ void __launch_bounds__(256) merge_stats_kernel() {
    __shared__ float2 red[8][32];
    __shared__ float2 resM[32], resR[32];
    const int b    = blockIdx.y;
    const int lane = threadIdx.x & 31, seg = threadIdx.x >> 5;
    const int m2   = blockIdx.x * 32 + lane;
    const float* pM = d_pM + (size_t)b * NBLK * NN + 2 * m2;
    const float* pS = d_pS + (size_t)b * NBLK * NN + 2 * m2;

    float2 vm[7];
    int cnt = 0;
    float M0 = -CUDART_INF_F, M1 = -CUDART_INF_F;
    for (int i = seg; i < NBLK; i += 8) {
        vm[cnt] = *(const float2*)(pM + (size_t)i * NN);
        M0 = fmaxf(M0, vm[cnt].x); M1 = fmaxf(M1, vm[cnt].y);
        cnt++;
    }
    red[seg][lane] = make_float2(M0, M1);
    __syncthreads();
    if (seg == 0) {
        #pragma unroll
        for (int j = 1; j < 8; j++) {
            M0 = fmaxf(M0, red[j][lane].x);
            M1 = fmaxf(M1, red[j][lane].y);
        }
        resM[lane] = make_float2(M0, M1);
    }
    __syncthreads();
    M0 = resM[lane].x; M1 = resM[lane].y;

    float s0 = 0.f, s1 = 0.f;
    {
        int k = 0;
        for (int i = seg; i < NBLK; i += 8, k++) {
            const float2 vs = *(const float2*)(pS + (size_t)i * NN);
            s0 += vs.x * __expf(vm[k].x - M0);
            s1 += vs.y * __expf(vm[k].y - M1);
        }
    }
    red[seg][lane] = make_float2(s0, s1);
    __syncthreads();
    if (seg == 0) {
        #pragma unroll
        for (int j = 1; j < 8; j++) {
            s0 += red[j][lane].x;
            s1 += red[j][lane].y;
        }
        resR[lane] = make_float2(1.f / s0, 1.f / s1);
    }
    __syncthreads();
    const float R0 = resR[lane].x, R1 = resR[lane].y;
    {
        u32* cw = d_corr + (size_t)b * NBLK * NH + m2;
        int k = 0;
        for (int i = seg; i < NBLK; i += 8, k++)
            cw[(size_t)i * NH] = packh2(__expf(vm[k].x - M0) * R0, __expf(vm[k].y - M1) * R1);
    }
}

// ---------------- 4: gs pairs [m2][c] = half2(g[c][m]) ---------------------
__global__ void gscale_kernel() {
    __shared__ float tsm[32][33];
    const int b  = blockIdx.z;
    const int m0 = blockIdx.x * 32;
    const int c0 = blockIdx.y * 32;
    const int tx = threadIdx.x, ty = threadIdx.y;        // 32 x 8
    #pragma unroll
    for (int j = 0; j < 32; j += 8)
        tsm[ty + j][tx] = d_G[((size_t)b * CI + c0 + ty + j) * NN + m0 + tx];
    __syncthreads();
    #pragma unroll
    for (int j = 0; j < 2; j++) {
        const int kk2l = ty + 8 * j;
        d_GSh[((size_t)b * NH + ((m0 >> 1) + kk2l)) * CI + c0 + tx] =
            packh2(tsm[tx][2 * kk2l], tsm[tx][2 * kk2l + 1]);
    }
}

// ---------------- 5: y = (S*corr) g  (fp16 mma, split-K) -------------------
__global__ void __launch_bounds__(256, 2) ygemm_kernel() {
    __shared__ u32 As[2][16 * 128];
    __shared__ u32 Bs[2][16 * 128];
    const int b     = blockIdx.z;
    const int split = blockIdx.y;
    const int n0    = blockIdx.x * 128;
    const u32* S    = d_Sh + (size_t)b * NN * NH;
    const u32* GSh  = d_GSh + (size_t)b * NH * CI;
    const u32* corr = d_corr + ((size_t)b * NBLK + blockIdx.x) * NH;
    float* YP = d_YP + ((size_t)split * BB + b) * NN * CI;
    const int kbase = split * (NN / SPLITK);
    const int NCH   = (NN / SPLITK) / 32;                // 50

    const int t = threadIdx.x, lane = t & 31, warp = t >> 5;
    const int wm = warp & 3, wn = warp >> 2;
    const int g = lane >> 2, tig = lane & 3;
    ACC_INIT();

    const int q8 = t & 7;
    const int nr = t >> 3;
    const int ldr = t >> 4, ldc = t & 15;

    uint2 fa2[4], cr2;
    auto ldA = [&](int ch) {
        const int m2b = (kbase >> 1) + ch * 16 + q8 * 2;
        #pragma unroll
        for (int rr = 0; rr < 4; rr++)
            fa2[rr] = *(const uint2*)(S + (size_t)(n0 + rr * 32 + nr) * NH + m2b);
        cr2 = *(const uint2*)(corr + m2b);
    };
    auto stsA = [&](int s) {
        #pragma unroll
        for (int rr = 0; rr < 4; rr++) {
            const int n = rr * 32 + nr;
            As[s][SWZ(2 * q8,     n)] = hmul_u32(fa2[rr].x, cr2.x);
            As[s][SWZ(2 * q8 + 1, n)] = hmul_u32(fa2[rr].y, cr2.y);
        }
    };
    auto issueB = [&](int ch, int s) {
        const int kk0 = (kbase + ch * 32) >> 1;
        #pragma unroll
        for (int h = 0; h < 2; h++) {
            const int col4 = (ldc + 16 * h) * 4;
            CP16(smem_u32p(&Bs[s][SWZ(ldr, col4)]), GSh + (size_t)(kk0 + ldr) * CI + col4);
        }
        CPC();
    };

    ldA(0); issueB(0, 0);
    for (int ch = 0; ch < NCH; ++ch) {
        const int s = ch & 1;
        if (ch + 1 < NCH) issueB(ch + 1, s ^ 1);
        stsA(s);
        if (ch + 1 < NCH) ldA(ch + 1);
        if (ch + 1 < NCH) { CPW(1); } else { CPW(0); }
        __syncthreads();
        FCOMP(As[s], Bs[s]);
        __syncthreads();
    }

    #pragma unroll
    for (int mt = 0; mt < 2; mt++) {
        #pragma unroll
        for (int nt = 0; nt < 8; nt++) {
            const int n = n0 + wm * 32 + mt * 16 + g;
            const int c = wn * 64 + nt * 8 + tig * 2;
            *(float2*)(YP + (size_t)n * CI + c)       = make_float2(acc[mt][nt][0], acc[mt][nt][1]);
            *(float2*)(YP + (size_t)(n + 8) * CI + c) = make_float2(acc[mt][nt][2], acc[mt][nt][3]);
        }
    }
}

// ---------------- 6: merge split-K + transpose + pack half2 [c2][n] --------
__global__ void reduceY_kernel() {
    __shared__ float tsm[32][33];
    const int b  = blockIdx.z;
    const int n0 = blockIdx.x * 32;
    const int c0 = blockIdx.y * 32;
    const int tx = threadIdx.x, ty = threadIdx.y;
    const size_t SS = (size_t)BB * NN * CI;
    const size_t base = (size_t)b * NN * CI;
    #pragma unroll
    for (int j = 0; j < 32; j += 8) {
        const size_t idx = base + (size_t)(n0 + ty + j) * CI + c0 + tx;
        tsm[ty + j][tx] = d_YP[idx] + d_YP[SS + idx] + d_YP[2 * SS + idx] + d_YP[3 * SS + idx];
    }
    __syncthreads();
    #pragma unroll
    for (int j = 0; j < 2; j++) {
        const int cl2 = ty + 8 * j;
        d_Yh[((size_t)b * (CI / 2) + ((c0 >> 1) + cl2)) * NN + n0 + tx] =
            packh2(tsm[tx][2 * cl2], tsm[tx][2 * cl2 + 1]);
    }
}

// ---------------- 8: pack Ww^T pairs [c2][m] -------------------------------
__global__ void wconv_kernel(const float* __restrict__ Ww) {
    const int id = blockIdx.x * 256 + threadIdx.x;
    const int c2 = id >> 8, m = id & 255;
    d_Wt[c2 * C + m] = packh2(Ww[m * CI + 2 * c2], Ww[m * CI + 2 * c2 + 1]);
}

// ---------------- 9: out = Ww·y + Wb + x  (fp16 mma) -----------------------
__global__ void __launch_bounds__(256, 2) out_kernel(const float* __restrict__ x,
                                                     const float* __restrict__ Wb,
                                                     float* __restrict__ out) {
    __shared__ u32 As[2][16 * 128];
    __shared__ u32 Bs[2][16 * 128];
    const int b  = blockIdx.z;
    const int m0 = blockIdx.y * 128;
    const int n0 = blockIdx.x * 128;
    const u32* Yh = d_Yh + (size_t)b * (CI / 2) * NN;

    const int t = threadIdx.x, lane = t & 31, warp = t >> 5;
    const int wm = warp & 3, wn = warp >> 2;
    const int g = lane >> 2, tig = lane & 3;
    ACC_INIT();

    const int ldr = t >> 4, ldc = t & 15;

    auto issue = [&](int ch, int s) {
        const int kk0 = ch * 16;
        #pragma unroll
        for (int h = 0; h < 2; h++) {
            const int col4 = (ldc + 16 * h) * 4;
            CP16(smem_u32p(&As[s][SWZ(ldr, col4)]), d_Wt + (size_t)(kk0 + ldr) * C + m0 + col4);
            CP16(smem_u32p(&Bs[s][SWZ(ldr, col4)]), Yh + (size_t)(kk0 + ldr) * NN + n0 + col4);
        }
        CPC();
    };

    issue(0, 0);
    #pragma unroll
    for (int ch = 0; ch < 4; ++ch) {
        const int s = ch & 1;
        if (ch < 3) { issue(ch + 1, s ^ 1); CPW(1); } else { CPW(0); }
        __syncthreads();
        FCOMP(As[s], Bs[s]);
        __syncthreads();
    }

    #pragma unroll
    for (int mt = 0; mt < 2; mt++) {
        #pragma unroll
        for (int nt = 0; nt < 8; nt++) {
            const int m = m0 + wm * 32 + mt * 16 + g;
            const int n = n0 + wn * 64 + nt * 8 + tig * 2;
            {
                const float bv = Wb[m];
                const float2 xv = *(const float2*)(x + ((size_t)b * C + m) * NN + n);
                *(float2*)(out + ((size_t)b * C + m) * NN + n) =
                    make_float2(acc[mt][nt][0] + bv + xv.x, acc[mt][nt][1] + bv + xv.y);
            }
            {
                const float bv = Wb[m + 8];
                const float2 xv = *(const float2*)(x + ((size_t)b * C + m + 8) * NN + n);
                *(float2*)(out + ((size_t)b * C + m + 8) * NN + n) =
                    make_float2(acc[mt][nt][2] + bv + xv.x, acc[mt][nt][3] + bv + xv.y);
            }
        }
    }
}

// ---------------------------------------------------------------------------
extern "C" void kernel_launch(void* const* d_in, const int* in_sizes, int n_in,
                              void* d_out, int out_size) {
    const float* x  = (const float*)d_in[0];
    const float* gw = (const float*)d_in[1];
    const float* gb = (const float*)d_in[2];
    const float* tw = (const float*)d_in[3];
    const float* tb = (const float*)d_in[4];
    const float* pw = (const float*)d_in[5];
    const float* pb = (const float*)d_in[6];
    const float* Ww = (const float*)d_in[7];
    const float* Wb = (const float*)d_in[8];
    float* out = (float*)d_out;

    packX_kernel<<<dim3(NN / 256, C / 2, BB), 256>>>(x);
    packWall_kernel<<<(C / 2) * 384 / 256, 256>>>(tw, pw, gw);
    wconv_kernel<<<(CI / 2) * C / 256, 256>>>(Ww);
    proj_kernel<<<dim3(NN / 128, 3, BB), 256>>>(tb, pb, gb);
    fgemm_kernel<<<dim3(NN / 128, NN / 128, BB), 256>>>();
    merge_stats_kernel<<<dim3(NH / 32, BB), 256>>>();
    gscale_kernel<<<dim3(NN / 32, CI / 32, BB), dim3(32, 8)>>>();
    ygemm_kernel<<<dim3(NN / 128, SPLITK, BB), 256>>>();
    reduceY_kernel<<<dim3(NN / 32, CI / 32, BB), dim3(32, 8)>>>();
    out_kernel<<<dim3(NN / 128, C / 128, BB), 256>>>(x, Wb, out);
}

// round 9
// speedup vs baseline: 6.4985x; 1.0075x over previous
#include <cuda_runtime.h>
#include <cuda_fp16.h>
#include <math_constants.h>
#include <cstdint>

#define BB 2
#define C 256
#define CI 128
#define NN 6400
#define NH (NN / 2)
#define SPLITK 8
#define NBLK (NN / 128)     // 50

typedef unsigned u32;

// ---------------- scratch ---------------------------------------------------
__device__ u32   d_Xh[BB * (C / 2) * NN];              // x pairs [c2][n] half2
__device__ u32   d_Wh[(C / 2) * 384];                  // stacked proj weights [k2][which*128+o]
__device__ u32   d_Th[BB * (CI / 2) * NN];             // theta pairs [c2][n] half2
__device__ u32   d_Ph[BB * (CI / 2) * NN];             // phi   pairs [c2][n] half2
__device__ float d_G[BB * CI * NN];                    // g proj fp32 [c][m]
__device__ u32   d_Sh[(size_t)BB * NN * NH];           // S = exp(f - tileMax), half2 [n][m2]
__device__ float d_pM[BB * NBLK * NN];                 // per (n-block, m) tile col max
__device__ float d_pS[BB * NBLK * NN];                 // per (n-block, m) tile col sum-exp
__device__ u32   d_corr[BB * NBLK * NH];               // half2 corr[nblk][m2]
__device__ u32   d_GSh[BB * NH * CI];                  // g pairs [m2][c] half2 (raw g)
__device__ float d_YP[(size_t)SPLITK * BB * NN * CI];  // split-K partials, [n][c]
__device__ u32   d_Yh[BB * (CI / 2) * NN];             // y pairs [c2][n] half2
__device__ u32   d_Wt[(CI / 2) * C];                   // Ww^T pairs [c2][m] half2

// ============================================================================
//                      fp16 mma.sync GEMM machinery
// ============================================================================
#define SWZ(row, col) ((row) * 128 + ((col) ^ (((row) & 3) << 3)))

__device__ __forceinline__ u32 packh2(float a, float b) {
    __half2 h = __halves2half2(__float2half_rn(a), __float2half_rn(b));
    return reinterpret_cast<u32&>(h);
}
__device__ __forceinline__ u32 hmul_u32(u32 a, u32 b) {
    __half2 r = __hmul2(reinterpret_cast<__half2&>(a), reinterpret_cast<__half2&>(b));
    return reinterpret_cast<u32&>(r);
}

__device__ __forceinline__ void mma_f16(float c[4], const u32 a[4], const u32 b[2]) {
    asm volatile(
        "mma.sync.aligned.m16n8k16.row.col.f32.f16.f16.f32 "
        "{%0,%1,%2,%3}, {%4,%5,%6,%7}, {%8,%9}, {%0,%1,%2,%3};"
        : "+f"(c[0]), "+f"(c[1]), "+f"(c[2]), "+f"(c[3])
        : "r"(a[0]), "r"(a[1]), "r"(a[2]), "r"(a[3]), "r"(b[0]), "r"(b[1]));
}

#define FCOMP(Asb, Bsb)                                                  \
    _Pragma("unroll")                                                    \
    for (int s16 = 0; s16 < 2; ++s16) {                                  \
        const int r0 = s16 * 8 + tig, r1 = s16 * 8 + tig + 4;            \
        u32 af[2][4], bf[8][2];                                          \
        _Pragma("unroll")                                                \
        for (int mt = 0; mt < 2; mt++) {                                 \
            const int mb = wm * 32 + mt * 16;                            \
            af[mt][0] = (Asb)[SWZ(r0, mb + g)];                          \
            af[mt][1] = (Asb)[SWZ(r0, mb + g + 8)];                      \
            af[mt][2] = (Asb)[SWZ(r1, mb + g)];                          \
            af[mt][3] = (Asb)[SWZ(r1, mb + g + 8)];                      \
        }                                                                \
        _Pragma("unroll")                                                \
        for (int nt = 0; nt < 8; nt++) {                                 \
            const int nb = wn * 64 + nt * 8 + g;                         \
            bf[nt][0] = (Bsb)[SWZ(r0, nb)];                              \
            bf[nt][1] = (Bsb)[SWZ(r1, nb)];                              \
        }                                                                \
        _Pragma("unroll")                                                \
        for (int mt = 0; mt < 2; mt++)                                   \
            _Pragma("unroll")                                            \
            for (int nt = 0; nt < 8; nt++)                               \
                mma_f16(acc[mt][nt], af[mt], bf[nt]);                    \
    }

__device__ __forceinline__ u32 smem_u32p(const void* p) {
    return (u32)__cvta_generic_to_shared(p);
}
#define CP16(dst, src) asm volatile("cp.async.cg.shared.global [%0], [%1], 16;" :: "r"(dst), "l"(src))
#define CPC()          asm volatile("cp.async.commit_group;")
#define CPW(n)         asm volatile("cp.async.wait_group %0;" :: "n"(n))

#define ACC_INIT()                                      \
    float acc[2][8][4];                                 \
    _Pragma("unroll") for (int i = 0; i < 2; i++)       \
    _Pragma("unroll") for (int j = 0; j < 8; j++)       \
    _Pragma("unroll") for (int r = 0; r < 4; r++) acc[i][j][r] = 0.f;

// ---------------- 0a: pack x into half2 pairs [c2][n] ----------------------
__global__ void packX_kernel(const float* __restrict__ x) {
    const int n  = blockIdx.x * 256 + threadIdx.x;
    const int c2 = blockIdx.y;
    const int b  = blockIdx.z;
    const float* xb = x + ((size_t)b * C + 2 * c2) * NN;
    d_Xh[((size_t)b * (C / 2) + c2) * NN + n] = packh2(xb[n], xb[NN + n]);
}

// ---------------- 0b: pack stacked proj weights [k2][which*128+o] ----------
__global__ void packWall_kernel(const float* __restrict__ tw,
                                const float* __restrict__ pw,
                                const float* __restrict__ gw) {
    const int id = blockIdx.x * 256 + threadIdx.x;       // 0 .. 128*384-1
    const int k2 = id / 384, col = id % 384;
    const int which = col >> 7, o = col & 127;
    const float* W = (which == 0) ? tw : (which == 1) ? pw : gw;
    d_Wh[id] = packh2(W[o * C + 2 * k2], W[o * C + 2 * k2 + 1]);
}

// ---------------- 1: projections (fp16 mma, 3-stage) -----------------------
__global__ void __launch_bounds__(256, 2) proj_kernel(const float* __restrict__ tb,
                                                      const float* __restrict__ pb,
                                                      const float* __restrict__ gb) {
    __shared__ u32 As[3][16 * 128];
    __shared__ u32 Bs[3][16 * 128];
    const int b     = blockIdx.z;
    const int which = blockIdx.y;
    const int n0    = blockIdx.x * 128;
    const u32* Xh = d_Xh + (size_t)b * (C / 2) * NN;
    const float* bias = (which == 0) ? tb : (which == 1) ? pb : gb;

    const int t = threadIdx.x, lane = t & 31, warp = t >> 5;
    const int wm = warp & 3, wn = warp >> 2;
    const int g = lane >> 2, tig = lane & 3;
    ACC_INIT();

    const int ldr = t >> 4, ldc = t & 15;

    auto issue = [&](int ch, int s) {
        const int kk0 = ch * 16;
        #pragma unroll
        for (int h = 0; h < 2; h++) {
            const int col4 = (ldc + 16 * h) * 4;
            CP16(smem_u32p(&As[s][SWZ(ldr, col4)]), d_Wh + (size_t)(kk0 + ldr) * 384 + which * 128 + col4);
            CP16(smem_u32p(&Bs[s][SWZ(ldr, col4)]), Xh + (size_t)(kk0 + ldr) * NN + n0 + col4);
        }
        CPC();
    };

    issue(0, 0); issue(1, 1);
    #pragma unroll
    for (int ch = 0; ch < 8; ++ch) {
        if (ch + 1 < 8) { CPW(1); } else { CPW(0); }
        __syncthreads();
        if (ch + 2 < 8) issue(ch + 2, (ch + 2) % 3);
        FCOMP(As[ch % 3], Bs[ch % 3]);
    }

    if (which < 2) {
        u32* dst = (which == 0 ? d_Th : d_Ph) + (size_t)b * (CI / 2) * NN;
        #pragma unroll
        for (int mt = 0; mt < 2; mt++) {
            const int r = wm * 32 + mt * 16 + g;
            const float bv0 = bias[r], bv8 = bias[r + 8];
            #pragma unroll
            for (int nt = 0; nt < 8; nt++) {
                const int n = n0 + wn * 64 + nt * 8 + tig * 2;
                float v0 = acc[mt][nt][0] + bv0, v1 = acc[mt][nt][1] + bv0;
                float v2 = acc[mt][nt][2] + bv8, v3 = acc[mt][nt][3] + bv8;
                const float p0 = __shfl_xor_sync(0xffffffff, v0, 4);
                const float p1 = __shfl_xor_sync(0xffffffff, v1, 4);
                const float p2 = __shfl_xor_sync(0xffffffff, v2, 4);
                const float p3 = __shfl_xor_sync(0xffffffff, v3, 4);
                if ((g & 1) == 0) {
                    *(uint2*)(dst + (size_t)(r >> 1) * NN + n) =
                        make_uint2(packh2(v0, p0), packh2(v1, p1));
                    *(uint2*)(dst + (size_t)((r + 8) >> 1) * NN + n) =
                        make_uint2(packh2(v2, p2), packh2(v3, p3));
                }
            }
        }
    } else {
        float* P = d_G + (size_t)b * CI * NN;
        #pragma unroll
        for (int mt = 0; mt < 2; mt++) {
            const int r = wm * 32 + mt * 16 + g;
            const float bv0 = bias[r], bv8 = bias[r + 8];
            #pragma unroll
            for (int nt = 0; nt < 8; nt++) {
                const int n = n0 + wn * 64 + nt * 8 + tig * 2;
                *(float2*)(P + (size_t)r * NN + n) =
                    make_float2(acc[mt][nt][0] + bv0, acc[mt][nt][1] + bv0);
                *(float2*)(P + (size_t)(r + 8) * NN + n) =
                    make_float2(acc[mt][nt][2] + bv8, acc[mt][nt][3] + bv8);
            }
        }
    }
}

// ---------------- 2: f = theta^T phi ; store S=exp(f-tileMax) fp16 + stats -
__global__ void __launch_bounds__(256, 2) fgemm_kernel() {
    __shared__ u32 As[3][16 * 128];
    __shared__ u32 Bs[3][16 * 128];
    const int b  = blockIdx.z;
    const int n0 = blockIdx.y * 128;
    const int m0 = blockIdx.x * 128;
    const u32* Th = d_Th + (size_t)b * (CI / 2) * NN;
    const u32* Ph = d_Ph + (size_t)b * (CI / 2) * NN;
    u32* S = d_Sh + (size_t)b * NN * NH;

    const int t = threadIdx.x, lane = t & 31, warp = t >> 5;
    const int wm = warp & 3, wn = warp >> 2;
    const int g = lane >> 2, tig = lane & 3;
    ACC_INIT();

    const int ldr = t >> 4, ldc = t & 15;

    auto issue = [&](int ch, int s) {
        const int kk0 = ch * 16;
        #pragma unroll
        for (int h = 0; h < 2; h++) {
            const int col4 = (ldc + 16 * h) * 4;
            CP16(smem_u32p(&As[s][SWZ(ldr, col4)]), Th + (size_t)(kk0 + ldr) * NN + n0 + col4);
            CP16(smem_u32p(&Bs[s][SWZ(ldr, col4)]), Ph + (size_t)(kk0 + ldr) * NN + m0 + col4);
        }
        CPC();
    };

    issue(0, 0); issue(1, 1);
    #pragma unroll
    for (int ch = 0; ch < 4; ++ch) {
        if (ch + 1 < 4) { CPW(1); } else { CPW(0); }
        __syncthreads();
        if (ch + 2 < 4) issue(ch + 2, (ch + 2) % 3);
        FCOMP(As[ch % 3], Bs[ch % 3]);
    }

    // ---- column-softmax: tile max, then exp (stored as S fp16) + sums ----
    float* red = (float*)As;
    float lv[8][2];
    #pragma unroll
    for (int nt = 0; nt < 8; nt++) {
        lv[nt][0] = fmaxf(fmaxf(acc[0][nt][0], acc[0][nt][2]), fmaxf(acc[1][nt][0], acc[1][nt][2]));
        lv[nt][1] = fmaxf(fmaxf(acc[0][nt][1], acc[0][nt][3]), fmaxf(acc[1][nt][1], acc[1][nt][3]));
        #pragma unroll
        for (int d = 4; d <= 16; d <<= 1) {
            lv[nt][0] = fmaxf(lv[nt][0], __shfl_xor_sync(0xffffffff, lv[nt][0], d));
            lv[nt][1] = fmaxf(lv[nt][1], __shfl_xor_sync(0xffffffff, lv[nt][1], d));
        }
    }
    __syncthreads();
    if (g == 0) {
        #pragma unroll
        for (int nt = 0; nt < 8; nt++) {
            const int col = wn * 64 + nt * 8 + tig * 2;
            red[wm * 128 + col]     = lv[nt][0];
            red[wm * 128 + col + 1] = lv[nt][1];
        }
    }
    __syncthreads();
    if (t < 128) {
        red[512 + t] = fmaxf(fmaxf(red[t], red[128 + t]), fmaxf(red[256 + t], red[384 + t]));
    }
    __syncthreads();
    #pragma unroll
    for (int nt = 0; nt < 8; nt++) {
        const int col = wn * 64 + nt * 8 + tig * 2;
        const float tm0 = red[512 + col], tm1 = red[512 + col + 1];
        float s0 = 0.f, s1 = 0.f;
        #pragma unroll
        for (int mt = 0; mt < 2; mt++) {
            const int n = n0 + wm * 32 + mt * 16 + g;
            const float e0 = __expf(acc[mt][nt][0] - tm0);
            const float e1 = __expf(acc[mt][nt][1] - tm1);
            const float e2 = __expf(acc[mt][nt][2] - tm0);
            const float e3 = __expf(acc[mt][nt][3] - tm1);
            const size_t m2 = (size_t)((m0 + col) >> 1);
            S[(size_t)n * NH + m2]       = packh2(e0, e1);
            S[(size_t)(n + 8) * NH + m2] = packh2(e2, e3);
            s0 += e0 + e2; s1 += e1 + e3;
        }
        #pragma unroll
        for (int d = 4; d <= 16; d <<= 1) {
            s0 += __shfl_xor_sync(0xffffffff, s0, d);
            s1 += __shfl_xor_sync(0xffffffff, s1, d);
        }
        lv[nt][0] = s0; lv[nt][1] = s1;
    }
    __syncthreads();
    if (g == 0) {
        #pragma unroll
        for (int nt = 0; nt < 8; nt++) {
            const int col = wn * 64 + nt * 8 + tig * 2;
            red[wm * 128 + col]     = lv[nt][0];
            red[wm * 128 + col + 1] = lv[nt][1];
        }
    }
    __syncthreads();
    if (t < 128) {
        const float s = red[t] + red[128 + t] + red[256 + t] + red[384 + t];
        const size_t idx = ((size_t)b * NBLK + blockIdx.y) * NN + m0 + t;
        d_pM[idx] = red[512 + t];
        d_pS[idx] = s;
    }
}

// ---------------- 3: merge stats -> corr[nblk][m2] half2 (parallel) --------
__global__ void __launch_bounds__(256) merge_stats_kernel() {
    __shared__ float2 red[8][32];
    __shared__ float2 resM[32], resR[32];
    const int b    = blockIdx.y;
    const int lane = threadIdx.x & 31, seg = threadIdx.x >> 5;
    const int m2   = blockIdx.x * 32 + lane;
    const float* pM = d_pM + (size_t)b * NBLK * NN + 2 * m2;
    const float* pS = d_pS + (size_t)b * NBLK * NN + 2 * m2;

    float2 vm[7];
    int cnt = 0;
    float M0 = -CUDART_INF_F, M1 = -CUDART_INF_F;
    for (int i = seg; i < NBLK; i += 8) {
        vm[cnt] = *(const float2*)(pM + (size_t)i * NN);
        M0 = fmaxf(M0, vm[cnt].x); M1 = fmaxf(M1, vm[cnt].y);
        cnt++;
    }
    red[seg][lane] = make_float2(M0, M1);
    __syncthreads();
    if (seg == 0) {
        #pragma unroll
        for (int j = 1; j < 8; j++) {
            M0 = fmaxf(M0, red[j][lane].x);
            M1 = fmaxf(M1, red[j][lane].y);
        }
        resM[lane] = make_float2(M0, M1);
    }
    __syncthreads();
    M0 = resM[lane].x; M1 = resM[lane].y;

    float s0 = 0.f, s1 = 0.f;
    {
        int k = 0;
        for (int i = seg; i < NBLK; i += 8, k++) {
            const float2 vs = *(const float2*)(pS + (size_t)i * NN);
            s0 += vs.x * __expf(vm[k].x - M0);
            s1 += vs.y * __expf(vm[k].y - M1);
        }
    }
    red[seg][lane] = make_float2(s0, s1);
    __syncthreads();
    if (seg == 0) {
        #pragma unroll
        for (int j = 1; j < 8; j++) {
            s0 += red[j][lane].x;
            s1 += red[j][lane].y;
        }
        resR[lane] = make_float2(1.f / s0, 1.f / s1);
    }
    __syncthreads();
    const float R0 = resR[lane].x, R1 = resR[lane].y;
    {
        u32* cw = d_corr + (size_t)b * NBLK * NH + m2;
        int k = 0;
        for (int i = seg; i < NBLK; i += 8, k++)
            cw[(size_t)i * NH] = packh2(__expf(vm[k].x - M0) * R0, __expf(vm[k].y - M1) * R1);
    }
}

// ---------------- 4: gs pairs [m2][c] = half2(g[c][m]) ---------------------
__global__ void gscale_kernel() {
    __shared__ float tsm[32][33];
    const int b  = blockIdx.z;
    const int m0 = blockIdx.x * 32;
    const int c0 = blockIdx.y * 32;
    const int tx = threadIdx.x, ty = threadIdx.y;        // 32 x 8
    #pragma unroll
    for (int j = 0; j < 32; j += 8)
        tsm[ty + j][tx] = d_G[((size_t)b * CI + c0 + ty + j) * NN + m0 + tx];
    __syncthreads();
    #pragma unroll
    for (int j = 0; j < 2; j++) {
        const int kk2l = ty + 8 * j;
        d_GSh[((size_t)b * NH + ((m0 >> 1) + kk2l)) * CI + c0 + tx] =
            packh2(tsm[tx][2 * kk2l], tsm[tx][2 * kk2l + 1]);
    }
}

// ---------------- 5: y = (S*corr) g  (fp16 mma, split-K=8, 3-stage) --------
__global__ void __launch_bounds__(256, 2) ygemm_kernel() {
    __shared__ u32 As[3][16 * 128];
    __shared__ u32 Bs[3][16 * 128];
    const int b     = blockIdx.z;
    const int split = blockIdx.y;
    const int n0    = blockIdx.x * 128;
    const u32* S    = d_Sh + (size_t)b * NN * NH;
    const u32* GSh  = d_GSh + (size_t)b * NH * CI;
    const u32* corr = d_corr + ((size_t)b * NBLK + blockIdx.x) * NH;
    float* YP = d_YP + ((size_t)split * BB + b) * NN * CI;
    const int kbase = split * (NN / SPLITK);             // 800 per split
    const int NCH   = (NN / SPLITK) / 32;                // 25

    const int t = threadIdx.x, lane = t & 31, warp = t >> 5;
    const int wm = warp & 3, wn = warp >> 2;
    const int g = lane >> 2, tig = lane & 3;
    ACC_INIT();

    const int q8 = t & 7;
    const int nr = t >> 3;
    const int ldr = t >> 4, ldc = t & 15;

    uint2 fa2[4], cr2;
    auto ldA = [&](int ch) {
        const int m2b = (kbase >> 1) + ch * 16 + q8 * 2;
        #pragma unroll
        for (int rr = 0; rr < 4; rr++)
            fa2[rr] = *(const uint2*)(S + (size_t)(n0 + rr * 32 + nr) * NH + m2b);
        cr2 = *(const uint2*)(corr + m2b);
    };
    auto stsA = [&](int s) {
        #pragma unroll
        for (int rr = 0; rr < 4; rr++) {
            const int n = rr * 32 + nr;
            As[s][SWZ(2 * q8,     n)] = hmul_u32(fa2[rr].x, cr2.x);
            As[s][SWZ(2 * q8 + 1, n)] = hmul_u32(fa2[rr].y, cr2.y);
        }
    };
    auto issueB = [&](int ch, int s) {
        const int kk0 = (kbase + ch * 32) >> 1;
        #pragma unroll
        for (int h = 0; h < 2; h++) {
            const int col4 = (ldc + 16 * h) * 4;
            CP16(smem_u32p(&Bs[s][SWZ(ldr, col4)]), GSh + (size_t)(kk0 + ldr) * CI + col4);
        }
        CPC();
    };

    ldA(0); issueB(0, 0); issueB(1, 1);
    for (int ch = 0; ch < NCH; ++ch) {
        if (ch + 1 < NCH) { CPW(1); } else { CPW(0); }
        stsA(ch % 3);                       // writes As slot computed >=2 barriers ago
        __syncthreads();                    // makes STS + cp.async data visible
        if (ch + 1 < NCH) ldA(ch + 1);
        if (ch + 2 < NCH) issueB(ch + 2, (ch + 2) % 3);
        FCOMP(As[ch % 3], Bs[ch % 3]);
    }

    #pragma unroll
    for (int mt = 0; mt < 2; mt++) {
        #pragma unroll
        for (int nt = 0; nt < 8; nt++) {
            const int n = n0 + wm * 32 + mt * 16 + g;
            const int c = wn * 64 + nt * 8 + tig * 2;
            *(float2*)(YP + (size_t)n * CI + c)       = make_float2(acc[mt][nt][0], acc[mt][nt][1]);
            *(float2*)(YP + (size_t)(n + 8) * CI + c) = make_float2(acc[mt][nt][2], acc[mt][nt][3]);
        }
    }
}

// ---------------- 6: merge split-K + transpose + pack half2 [c2][n] --------
__global__ void reduceY_kernel() {
    __shared__ float tsm[32][33];
    const int b  = blockIdx.z;
    const int n0 = blockIdx.x * 32;
    const int c0 = blockIdx.y * 32;
    const int tx = threadIdx.x, ty = threadIdx.y;
    const size_t SS = (size_t)BB * NN * CI;
    const size_t base = (size_t)b * NN * CI;
    #pragma unroll
    for (int j = 0; j < 32; j += 8) {
        const size_t idx = base + (size_t)(n0 + ty + j) * CI + c0 + tx;
        float v = 0.f;
        #pragma unroll
        for (int sp = 0; sp < SPLITK; sp++) v += d_YP[sp * SS + idx];
        tsm[ty + j][tx] = v;
    }
    __syncthreads();
    #pragma unroll
    for (int j = 0; j < 2; j++) {
        const int cl2 = ty + 8 * j;
        d_Yh[((size_t)b * (CI / 2) + ((c0 >> 1) + cl2)) * NN + n0 + tx] =
            packh2(tsm[tx][2 * cl2], tsm[tx][2 * cl2 + 1]);
    }
}

// ---------------- 8: pack Ww^T pairs [c2][m] -------------------------------
__global__ void wconv_kernel(const float* __restrict__ Ww) {
    const int id = blockIdx.x * 256 + threadIdx.x;
    const int c2 = id >> 8, m = id & 255;
    d_Wt[c2 * C + m] = packh2(Ww[m * CI + 2 * c2], Ww[m * CI + 2 * c2 + 1]);
}

// ---------------- 9: out = Ww·y + Wb + x  (fp16 mma, 3-stage) --------------
__global__ void __launch_bounds__(256, 2) out_kernel(const float* __restrict__ x,
                                                     const float* __restrict__ Wb,
                                                     float* __restrict__ out) {
    __shared__ u32 As[3][16 * 128];
    __shared__ u32 Bs[3][16 * 128];
    const int b  = blockIdx.z;
    const int m0 = blockIdx.y * 128;
    const int n0 = blockIdx.x * 128;
    const u32* Yh = d_Yh + (size_t)b * (CI / 2) * NN;

    const int t = threadIdx.x, lane = t & 31, warp = t >> 5;
    const int wm = warp & 3, wn = warp >> 2;
    const int g = lane >> 2, tig = lane & 3;
    ACC_INIT();

    const int ldr = t >> 4, ldc = t & 15;

    auto issue = [&](int ch, int s) {
        const int kk0 = ch * 16;
        #pragma unroll
        for (int h = 0; h < 2; h++) {
            const int col4 = (ldc + 16 * h) * 4;
            CP16(smem_u32p(&As[s][SWZ(ldr, col4)]), d_Wt + (size_t)(kk0 + ldr) * C + m0 + col4);
            CP16(smem_u32p(&Bs[s][SWZ(ldr, col4)]), Yh + (size_t)(kk0 + ldr) * NN + n0 + col4);
        }
        CPC();
    };

    issue(0, 0); issue(1, 1);
    #pragma unroll
    for (int ch = 0; ch < 4; ++ch) {
        if (ch + 1 < 4) { CPW(1); } else { CPW(0); }
        __syncthreads();
        if (ch + 2 < 4) issue(ch + 2, (ch + 2) % 3);
        FCOMP(As[ch % 3], Bs[ch % 3]);
    }

    #pragma unroll
    for (int mt = 0; mt < 2; mt++) {
        #pragma unroll
        for (int nt = 0; nt < 8; nt++) {
            const int m = m0 + wm * 32 + mt * 16 + g;
            const int n = n0 + wn * 64 + nt * 8 + tig * 2;
            {
                const float bv = Wb[m];
                const float2 xv = *(const float2*)(x + ((size_t)b * C + m) * NN + n);
                *(float2*)(out + ((size_t)b * C + m) * NN + n) =
                    make_float2(acc[mt][nt][0] + bv + xv.x, acc[mt][nt][1] + bv + xv.y);
            }
            {
                const float bv = Wb[m + 8];
                const float2 xv = *(const float2*)(x + ((size_t)b * C + m + 8) * NN + n);
                *(float2*)(out + ((size_t)b * C + m + 8) * NN + n) =
                    make_float2(acc[mt][nt][2] + bv + xv.x, acc[mt][nt][3] + bv + xv.y);
            }
        }
    }
}

// ---------------------------------------------------------------------------
extern "C" void kernel_launch(void* const* d_in, const int* in_sizes, int n_in,
                              void* d_out, int out_size) {
    const float* x  = (const float*)d_in[0];
    const float* gw = (const float*)d_in[1];
    const float* gb = (const float*)d_in[2];
    const float* tw = (const float*)d_in[3];
    const float* tb = (const float*)d_in[4];
    const float* pw = (const float*)d_in[5];
    const float* pb = (const float*)d_in[6];
    const float* Ww = (const float*)d_in[7];
    const float* Wb = (const float*)d_in[8];
    float* out = (float*)d_out;

    packX_kernel<<<dim3(NN / 256, C / 2, BB), 256>>>(x);
    packWall_kernel<<<(C / 2) * 384 / 256, 256>>>(tw, pw, gw);
    wconv_kernel<<<(CI / 2) * C / 256, 256>>>(Ww);
    proj_kernel<<<dim3(NN / 128, 3, BB), 256>>>(tb, pb, gb);
    fgemm_kernel<<<dim3(NN / 128, NN / 128, BB), 256>>>();
    merge_stats_kernel<<<dim3(NH / 32, BB), 256>>>();
    gscale_kernel<<<dim3(NN / 32, CI / 32, BB), dim3(32, 8)>>>();
    ygemm_kernel<<<dim3(NN / 128, SPLITK, BB), 256>>>();
    reduceY_kernel<<<dim3(NN / 32, CI / 32, BB), dim3(32, 8)>>>();
    out_kernel<<<dim3(NN / 128, C / 128, BB), 256>>>(x, Wb, out);
}

// round 10
// speedup vs baseline: 6.9712x; 1.0727x over previous
#include <cuda_runtime.h>
#include <cuda_fp16.h>
#include <math_constants.h>
#include <cstdint>

#define BB 2
#define C 256
#define CI 128
#define NN 6400
#define NH (NN / 2)
#define SPLITK 8
#define NBLK (NN / 128)     // 50

typedef unsigned u32;

// ---------------- scratch (all fp16 arrays are plain-half, col-contiguous) --
__device__ __half d_Xh[BB * C * NN];                   // x [c][n]
__device__ __half d_Wh[C * 384];                       // proj weights [c][which*128+o]
__device__ __half d_Th[BB * CI * NN];                  // theta [c][n]
__device__ __half d_Ph[BB * CI * NN];                  // phi   [c][n]
__device__ float  d_G[BB * CI * NN];                   // g proj fp32 [c][m]
__device__ u32    d_Sh[(size_t)BB * NN * NH];          // S = exp(f-tileMax): half [n][m]
__device__ float  d_pM[BB * NBLK * NN];
__device__ float  d_pS[BB * NBLK * NN];
__device__ __half d_corr[BB * NBLK * NN];              // corr [nblk][m]
__device__ __half d_GSh[BB * NN * CI];                 // g [m][c]
__device__ float  d_YP[(size_t)SPLITK * BB * NN * CI]; // split-K partials, [n][c]
__device__ __half d_Yh[BB * CI * NN];                  // y [c][n]
__device__ __half d_Wt[CI * C];                        // Ww^T [ci][m]

// ============================================================================
//                    fp16 mma + ldmatrix machinery
// ============================================================================
__device__ __forceinline__ u32 packh2(float a, float b) {
    __half2 h = __halves2half2(__float2half_rn(a), __float2half_rn(b));
    return reinterpret_cast<u32&>(h);
}
__device__ __forceinline__ u32 hmul_u32(u32 a, u32 b) {
    __half2 r = __hmul2(reinterpret_cast<__half2&>(a), reinterpret_cast<__half2&>(b));
    return reinterpret_cast<u32&>(r);
}
__device__ __forceinline__ void mma_f16(float c[4], const u32 a[4], const u32 b[2]) {
    asm volatile(
        "mma.sync.aligned.m16n8k16.row.col.f32.f16.f16.f32 "
        "{%0,%1,%2,%3}, {%4,%5,%6,%7}, {%8,%9}, {%0,%1,%2,%3};"
        : "+f"(c[0]), "+f"(c[1]), "+f"(c[2]), "+f"(c[3])
        : "r"(a[0]), "r"(a[1]), "r"(a[2]), "r"(a[3]), "r"(b[0]), "r"(b[1]));
}
#define LDSM4(d, a) \
    asm volatile("ldmatrix.sync.aligned.m8n8.x4.shared.b16 {%0,%1,%2,%3}, [%4];" \
        : "=r"((d)[0]), "=r"((d)[1]), "=r"((d)[2]), "=r"((d)[3]) : "r"(a))
#define LDSM4T(d, a) \
    asm volatile("ldmatrix.sync.aligned.m8n8.x4.trans.shared.b16 {%0,%1,%2,%3}, [%4];" \
        : "=r"((d)[0]), "=r"((d)[1]), "=r"((d)[2]), "=r"((d)[3]) : "r"(a))

__device__ __forceinline__ u32 smem_u32p(const void* p) {
    return (u32)__cvta_generic_to_shared(p);
}
#define CP16(dst, src) asm volatile("cp.async.cg.shared.global [%0], [%1], 16;" :: "r"(dst), "l"(src))
#define CPC()          asm volatile("cp.async.commit_group;")
#define CPW(n)         asm volatile("cp.async.wait_group %0;" :: "n"(n))
#define STS128A(addr, a, b, c, d) \
    asm volatile("st.shared.v4.b32 [%0], {%1,%2,%3,%4};" :: "r"(addr), "r"(a), "r"(b), "r"(c), "r"(d) : "memory")

#define ACC_INIT()                                      \
    float acc[2][8][4];                                 \
    _Pragma("unroll") for (int i = 0; i < 2; i++)       \
    _Pragma("unroll") for (int j = 0; j < 8; j++)       \
    _Pragma("unroll") for (int r = 0; r < 4; r++) acc[i][j][r] = 0.f;

// ldmatrix addr precompute (KTILE = [32 k rows][128 cols] half, 256B rows,
// chunk swizzle c' = c ^ (k&7)):
//   A (warp m-range, trans): lanes: k=(l&7)+((l>>4)&1)*8, oct=(l>>3)&1
//   B (warp n-range, trans): lanes: k=(l&7)+((l>>3)&1)*8, oct=(l>>4)&1
#define KT_ADDRS(adA, adB, base_a, base_b)                               \
    u32 adA[2], adB[4];                                                  \
    {                                                                    \
        const int kA = (lane & 7) + ((lane >> 4) & 1) * 8;               \
        const int oA = (lane >> 3) & 1;                                  \
        _Pragma("unroll")                                                \
        for (int mt = 0; mt < 2; mt++) {                                 \
            const int chk = wm * 4 + mt * 2 + oA;                        \
            adA[mt] = (base_a) + kA * 256 + ((chk ^ (lane & 7)) << 4);   \
        }                                                                \
        const int kB = (lane & 7) + ((lane >> 3) & 1) * 8;               \
        const int oB = (lane >> 4) & 1;                                  \
        _Pragma("unroll")                                                \
        for (int p = 0; p < 4; p++) {                                    \
            const int chk = wn * 8 + p * 2 + oB;                         \
            adB[p] = (base_b) + kB * 256 + ((chk ^ (lane & 7)) << 4);    \
        }                                                                \
    }

// trans-trans compute: stage byte offset so
#define FCOMP_TT(so)                                                     \
    _Pragma("unroll")                                                    \
    for (int s16 = 0; s16 < 2; ++s16) {                                  \
        const u32 o16 = (so) + s16 * 4096;                               \
        u32 af[2][4], bq[4][4];                                          \
        LDSM4T(af[0], adA[0] + o16);                                     \
        LDSM4T(af[1], adA[1] + o16);                                     \
        _Pragma("unroll")                                                \
        for (int p = 0; p < 4; p++) LDSM4T(bq[p], adB[p] + o16);         \
        _Pragma("unroll")                                                \
        for (int mt = 0; mt < 2; mt++)                                   \
            _Pragma("unroll")                                            \
            for (int p = 0; p < 4; p++) {                                \
                u32 b0[2] = {bq[p][0], bq[p][1]};                        \
                u32 b1[2] = {bq[p][2], bq[p][3]};                        \
                mma_f16(acc[mt][2 * p],     af[mt], b0);                 \
                mma_f16(acc[mt][2 * p + 1], af[mt], b1);                 \
            }                                                            \
    }

// cp.async writer for a KTILE: thread t -> row=t>>3, chunks (t&7), (t&7)+8
#define KT_CP(dstBase, srcPtr, pitch)                                            \
    {                                                                            \
        const int kr = t >> 3, c0k = t & 7;                                      \
        const __half* sp_ = (srcPtr) + (size_t)kr * (pitch);                     \
        CP16((dstBase) + kr * 256 + (((c0k)     ^ (kr & 7)) << 4), sp_ + c0k * 8);       \
        CP16((dstBase) + kr * 256 + (((c0k + 8) ^ (kr & 7)) << 4), sp_ + (c0k + 8) * 8); \
    }

// ---------------- 0a: pack x -> half [c][n] --------------------------------
__global__ void packX_kernel(const float* __restrict__ x) {
    const int n = (blockIdx.x * 128 + threadIdx.x) * 2;
    const int c = blockIdx.y, b = blockIdx.z;
    const float2 v = *(const float2*)(x + ((size_t)b * C + c) * NN + n);
    *(u32*)(d_Xh + ((size_t)b * C + c) * NN + n) = packh2(v.x, v.y);
}

// ---------------- 0b: pack stacked proj weights [c][which*128+o] -----------
__global__ void packWall_kernel(const float* __restrict__ tw,
                                const float* __restrict__ pw,
                                const float* __restrict__ gw) {
    const int id = blockIdx.x * 256 + threadIdx.x;       // 0 .. 256*384-1
    const int c = id / 384, col = id % 384;
    const int which = col >> 7, o = col & 127;
    const float* W = (which == 0) ? tw : (which == 1) ? pw : gw;
    d_Wh[id] = __float2half_rn(W[o * C + c]);
}

// ---------------- 0c: Ww^T [ci][m] -----------------------------------------
__global__ void wconv_kernel(const float* __restrict__ Ww) {
    const int id = blockIdx.x * 256 + threadIdx.x;       // 0..16383
    const int ci = id >> 7, m2 = id & 127;
    *(u32*)(d_Wt + ci * C + 2 * m2) =
        packh2(Ww[(2 * m2) * CI + ci], Ww[(2 * m2 + 1) * CI + ci]);
}

// ---------------- 1: projections (fp16 mma + ldmatrix, persistent x2) ------
__global__ void __launch_bounds__(256, 2) proj_kernel(const float* __restrict__ tb,
                                                      const float* __restrict__ pb,
                                                      const float* __restrict__ gb) {
    __shared__ u32 As[3][2048];
    __shared__ u32 Bs[3][2048];
    const int t = threadIdx.x, lane = t & 31, warp = t >> 5;
    const int wm = warp & 3, wn = warp >> 2;
    const int g = lane >> 2, tig = lane & 3;
    const u32 aB = smem_u32p(As), bB = smem_u32p(Bs);
    KT_ADDRS(adA, adB, aB, bB);

    for (int rep = 0; rep < 2; rep++) {
        const int tile = blockIdx.x * 2 + rep;           // 0..299
        const int b = tile / 150;
        const int rem = tile % 150;
        const int which = rem / 50;
        const int n0 = (rem % 50) * 128;
        const __half* Xh = d_Xh + (size_t)b * C * NN;
        const float* bias = (which == 0) ? tb : (which == 1) ? pb : gb;
        __syncthreads();                                 // protect smem across reps
        ACC_INIT();

        auto issue = [&](int ch, int s) {
            KT_CP(aB + s * 8192, d_Wh + (size_t)(ch * 32) * 384 + which * 128, 384);
            KT_CP(bB + s * 8192, Xh + (size_t)(ch * 32) * NN + n0, NN);
            CPC();
        };
        issue(0, 0); issue(1, 1);
        #pragma unroll
        for (int ch = 0; ch < 8; ++ch) {
            if (ch + 1 < 8) { CPW(1); } else { CPW(0); }
            __syncthreads();
            if (ch + 2 < 8) issue(ch + 2, (ch + 2) % 3);
            FCOMP_TT((ch % 3) * 8192);
        }

        if (which < 2) {
            __half* dst = (which == 0 ? d_Th : d_Ph) + (size_t)b * CI * NN;
            #pragma unroll
            for (int mt = 0; mt < 2; mt++) {
                const int r = wm * 32 + mt * 16 + g;
                const float bv0 = bias[r], bv8 = bias[r + 8];
                #pragma unroll
                for (int nt = 0; nt < 8; nt++) {
                    const int n = n0 + wn * 64 + nt * 8 + tig * 2;
                    *(u32*)(dst + (size_t)r * NN + n) =
                        packh2(acc[mt][nt][0] + bv0, acc[mt][nt][1] + bv0);
                    *(u32*)(dst + (size_t)(r + 8) * NN + n) =
                        packh2(acc[mt][nt][2] + bv8, acc[mt][nt][3] + bv8);
                }
            }
        } else {
            float* P = d_G + (size_t)b * CI * NN;
            #pragma unroll
            for (int mt = 0; mt < 2; mt++) {
                const int r = wm * 32 + mt * 16 + g;
                const float bv0 = bias[r], bv8 = bias[r + 8];
                #pragma unroll
                for (int nt = 0; nt < 8; nt++) {
                    const int n = n0 + wn * 64 + nt * 8 + tig * 2;
                    *(float2*)(P + (size_t)r * NN + n) =
                        make_float2(acc[mt][nt][0] + bv0, acc[mt][nt][1] + bv0);
                    *(float2*)(P + (size_t)(r + 8) * NN + n) =
                        make_float2(acc[mt][nt][2] + bv8, acc[mt][nt][3] + bv8);
                }
            }
        }
    }
}

// ---------------- 2: f = theta^T phi ; store S fp16 + stats ----------------
__global__ void __launch_bounds__(256, 2) fgemm_kernel() {
    __shared__ u32 As[3][2048];
    __shared__ u32 Bs[3][2048];
    const int b  = blockIdx.z;
    const int n0 = blockIdx.y * 128;
    const int m0 = blockIdx.x * 128;
    const __half* Th = d_Th + (size_t)b * CI * NN;
    const __half* Ph = d_Ph + (size_t)b * CI * NN;
    u32* S = d_Sh + (size_t)b * NN * NH;

    const int t = threadIdx.x, lane = t & 31, warp = t >> 5;
    const int wm = warp & 3, wn = warp >> 2;
    const int g = lane >> 2, tig = lane & 3;
    const u32 aB = smem_u32p(As), bB = smem_u32p(Bs);
    KT_ADDRS(adA, adB, aB, bB);
    ACC_INIT();

    auto issue = [&](int ch, int s) {
        KT_CP(aB + s * 8192, Th + (size_t)(ch * 32) * NN + n0, NN);
        KT_CP(bB + s * 8192, Ph + (size_t)(ch * 32) * NN + m0, NN);
        CPC();
    };
    issue(0, 0); issue(1, 1);
    #pragma unroll
    for (int ch = 0; ch < 4; ++ch) {
        if (ch + 1 < 4) { CPW(1); } else { CPW(0); }
        __syncthreads();
        if (ch + 2 < 4) issue(ch + 2, (ch + 2) % 3);
        FCOMP_TT((ch % 3) * 8192);
    }

    // ---- column-softmax: tile max, then exp (stored as S fp16) + sums ----
    float* red = (float*)As;
    float lv[8][2];
    #pragma unroll
    for (int nt = 0; nt < 8; nt++) {
        lv[nt][0] = fmaxf(fmaxf(acc[0][nt][0], acc[0][nt][2]), fmaxf(acc[1][nt][0], acc[1][nt][2]));
        lv[nt][1] = fmaxf(fmaxf(acc[0][nt][1], acc[0][nt][3]), fmaxf(acc[1][nt][1], acc[1][nt][3]));
        #pragma unroll
        for (int d = 4; d <= 16; d <<= 1) {
            lv[nt][0] = fmaxf(lv[nt][0], __shfl_xor_sync(0xffffffff, lv[nt][0], d));
            lv[nt][1] = fmaxf(lv[nt][1], __shfl_xor_sync(0xffffffff, lv[nt][1], d));
        }
    }
    __syncthreads();
    if (g == 0) {
        #pragma unroll
        for (int nt = 0; nt < 8; nt++) {
            const int col = wn * 64 + nt * 8 + tig * 2;
            red[wm * 128 + col]     = lv[nt][0];
            red[wm * 128 + col + 1] = lv[nt][1];
        }
    }
    __syncthreads();
    if (t < 128) {
        red[512 + t] = fmaxf(fmaxf(red[t], red[128 + t]), fmaxf(red[256 + t], red[384 + t]));
    }
    __syncthreads();
    #pragma unroll
    for (int nt = 0; nt < 8; nt++) {
        const int col = wn * 64 + nt * 8 + tig * 2;
        const float tm0 = red[512 + col], tm1 = red[512 + col + 1];
        float s0 = 0.f, s1 = 0.f;
        #pragma unroll
        for (int mt = 0; mt < 2; mt++) {
            const int n = n0 + wm * 32 + mt * 16 + g;
            const float e0 = __expf(acc[mt][nt][0] - tm0);
            const float e1 = __expf(acc[mt][nt][1] - tm1);
            const float e2 = __expf(acc[mt][nt][2] - tm0);
            const float e3 = __expf(acc[mt][nt][3] - tm1);
            const size_t m2 = (size_t)((m0 + col) >> 1);
            S[(size_t)n * NH + m2]       = packh2(e0, e1);
            S[(size_t)(n + 8) * NH + m2] = packh2(e2, e3);
            s0 += e0 + e2; s1 += e1 + e3;
        }
        #pragma unroll
        for (int d = 4; d <= 16; d <<= 1) {
            s0 += __shfl_xor_sync(0xffffffff, s0, d);
            s1 += __shfl_xor_sync(0xffffffff, s1, d);
        }
        lv[nt][0] = s0; lv[nt][1] = s1;
    }
    __syncthreads();
    if (g == 0) {
        #pragma unroll
        for (int nt = 0; nt < 8; nt++) {
            const int col = wn * 64 + nt * 8 + tig * 2;
            red[wm * 128 + col]     = lv[nt][0];
            red[wm * 128 + col + 1] = lv[nt][1];
        }
    }
    __syncthreads();
    if (t < 128) {
        const float s = red[t] + red[128 + t] + red[256 + t] + red[384 + t];
        const size_t idx = ((size_t)b * NBLK + blockIdx.y) * NN + m0 + t;
        d_pM[idx] = red[512 + t];
        d_pS[idx] = s;
    }
}

// ---------------- 3: merge stats -> corr[nblk][m] half ---------------------
__global__ void __launch_bounds__(256) merge_stats_kernel() {
    __shared__ float2 red[8][32];
    __shared__ float2 resM[32], resR[32];
    const int b    = blockIdx.y;
    const int lane = threadIdx.x & 31, seg = threadIdx.x >> 5;
    const int m2   = blockIdx.x * 32 + lane;
    const float* pM = d_pM + (size_t)b * NBLK * NN + 2 * m2;
    const float* pS = d_pS + (size_t)b * NBLK * NN + 2 * m2;

    float2 vm[7];
    int cnt = 0;
    float M0 = -CUDART_INF_F, M1 = -CUDART_INF_F;
    for (int i = seg; i < NBLK; i += 8) {
        vm[cnt] = *(const float2*)(pM + (size_t)i * NN);
        M0 = fmaxf(M0, vm[cnt].x); M1 = fmaxf(M1, vm[cnt].y);
        cnt++;
    }
    red[seg][lane] = make_float2(M0, M1);
    __syncthreads();
    if (seg == 0) {
        #pragma unroll
        for (int j = 1; j < 8; j++) {
            M0 = fmaxf(M0, red[j][lane].x);
            M1 = fmaxf(M1, red[j][lane].y);
        }
        resM[lane] = make_float2(M0, M1);
    }
    __syncthreads();
    M0 = resM[lane].x; M1 = resM[lane].y;

    float s0 = 0.f, s1 = 0.f;
    {
        int k = 0;
        for (int i = seg; i < NBLK; i += 8, k++) {
            const float2 vs = *(const float2*)(pS + (size_t)i * NN);
            s0 += vs.x * __expf(vm[k].x - M0);
            s1 += vs.y * __expf(vm[k].y - M1);
        }
    }
    red[seg][lane] = make_float2(s0, s1);
    __syncthreads();
    if (seg == 0) {
        #pragma unroll
        for (int j = 1; j < 8; j++) {
            s0 += red[j][lane].x;
            s1 += red[j][lane].y;
        }
        resR[lane] = make_float2(1.f / s0, 1.f / s1);
    }
    __syncthreads();
    const float R0 = resR[lane].x, R1 = resR[lane].y;
    {
        __half* cw = d_corr + (size_t)b * NBLK * NN + 2 * m2;
        int k = 0;
        for (int i = seg; i < NBLK; i += 8, k++)
            *(u32*)(cw + (size_t)i * NN) =
                packh2(__expf(vm[k].x - M0) * R0, __expf(vm[k].y - M1) * R1);
    }
}

// ---------------- 4: g -> half [m][c] --------------------------------------
__global__ void gscale_kernel() {
    __shared__ float tsm[32][33];
    const int b  = blockIdx.z;
    const int m0 = blockIdx.x * 32;
    const int c0 = blockIdx.y * 32;
    const int tx = threadIdx.x, ty = threadIdx.y;        // 32 x 8
    #pragma unroll
    for (int j = 0; j < 32; j += 8)
        tsm[ty + j][tx] = d_G[((size_t)b * CI + c0 + ty + j) * NN + m0 + tx];
    __syncthreads();
    #pragma unroll
    for (int jj = 0; jj < 2; jj++) {
        const int ml = ty + 8 * jj + 16 * (tx >> 4);
        const int c2 = tx & 15;
        *(u32*)(d_GSh + ((size_t)b * NN + m0 + ml) * CI + c0 + 2 * c2) =
            packh2(tsm[2 * c2][ml], tsm[2 * c2 + 1][ml]);
    }
}

// ---------------- 5: y = (S*corr) g  (ldmatrix fp16 mma, split-K) ----------
__global__ void __launch_bounds__(256, 2) ygemm_kernel() {
    __shared__ u32 As[3][2048];                          // S tile [128 n][32 k] half
    __shared__ u32 Bs[3][2048];                          // B' tile [32 k][128 c] half
    const int b     = blockIdx.z;
    const int split = blockIdx.y;
    const int n0    = blockIdx.x * 128;
    const __half* S   = (const __half*)(const void*)(d_Sh + (size_t)b * NN * NH);
    const __half* GSh = d_GSh + (size_t)b * NN * CI;
    const __half* corrh = d_corr + ((size_t)b * NBLK + blockIdx.x) * NN;
    float* YP = d_YP + ((size_t)split * BB + b) * NN * CI;
    const int kbase = split * (NN / SPLITK);             // 800 per split
    const int NCH   = (NN / SPLITK) / 32;                // 25

    const int t = threadIdx.x, lane = t & 31, warp = t >> 5;
    const int wm = warp & 3, wn = warp >> 2;
    const int g = lane >> 2, tig = lane & 3;
    const u32 aB = smem_u32p(As), bB = smem_u32p(Bs);
    ACC_INIT();

    // A (non-trans, [n][k] 64B rows, swz c^= (n>>1)&3): addrs per (mt, s16)
    u32 adAy[2][2];
    {
        const int nl = lane & 15, kh = (lane >> 4) & 1;
        #pragma unroll
        for (int mt = 0; mt < 2; mt++) {
            const int n = wm * 32 + mt * 16 + nl;
            #pragma unroll
            for (int s16 = 0; s16 < 2; s16++) {
                const int chk = s16 * 2 + kh;
                adAy[mt][s16] = aB + n * 64 + ((chk ^ ((n >> 1) & 3)) << 4);
            }
        }
    }
    // B (trans KTILE)
    u32 adB[4];
    {
        const int kB = (lane & 7) + ((lane >> 3) & 1) * 8;
        const int oB = (lane >> 4) & 1;
        #pragma unroll
        for (int p = 0; p < 4; p++) {
            const int chk = wn * 8 + p * 2 + oB;
            adB[p] = bB + kB * 256 + ((chk ^ (lane & 7)) << 4);
        }
    }

    // A loader: cp.async, thread -> row n=t>>1, chunks (t&1)*2, +1
    auto issueA = [&](int ch, int s) {
        const int nr = t >> 1, cc = (t & 1) * 2;
        const __half* sp = S + (size_t)(n0 + nr) * NN + kbase + ch * 32;
        const u32 dst = aB + s * 8192 + nr * 64;
        CP16(dst + (((cc)     ^ ((nr >> 1) & 3)) << 4), sp + cc * 8);
        CP16(dst + (((cc + 1) ^ ((nr >> 1) & 3)) << 4), sp + (cc + 1) * 8);
        CPC();
    };
    // B' loader: registers (g * corr)
    const int rowB = t >> 3, cB = t & 7;
    uint4 gv[2]; __half crh;
    auto ldB = [&](int ch) {
        const int m = kbase + ch * 32 + rowB;
        const __half* gp = GSh + (size_t)m * CI;
        gv[0] = *(const uint4*)(gp + cB * 8);
        gv[1] = *(const uint4*)(gp + (cB + 8) * 8);
        crh = corrh[m];
    };
    auto stsB = [&](int s) {
        const __half2 crs2 = __half2half2(crh);
        const u32 crs = reinterpret_cast<const u32&>(crs2);
        const u32 dst = bB + s * 8192 + rowB * 256;
        #pragma unroll
        for (int i = 0; i < 2; i++) {
            uint4 w = gv[i];
            STS128A(dst + (((cB + 8 * i) ^ (rowB & 7)) << 4),
                    hmul_u32(w.x, crs), hmul_u32(w.y, crs),
                    hmul_u32(w.z, crs), hmul_u32(w.w, crs));
        }
    };

    ldB(0); issueA(0, 0); issueA(1, 1);
    for (int ch = 0; ch < NCH; ++ch) {
        if (ch + 1 < NCH) { CPW(1); } else { CPW(0); }
        stsB(ch % 3);
        __syncthreads();
        if (ch + 1 < NCH) ldB(ch + 1);
        if (ch + 2 < NCH) issueA(ch + 2, (ch + 2) % 3);
        const u32 so = (ch % 3) * 8192;
        #pragma unroll
        for (int s16 = 0; s16 < 2; ++s16) {
            u32 af[2][4], bq[4][4];
            LDSM4(af[0], adAy[0][s16] + so);
            LDSM4(af[1], adAy[1][s16] + so);
            #pragma unroll
            for (int p = 0; p < 4; p++) LDSM4T(bq[p], adB[p] + so + s16 * 4096);
            #pragma unroll
            for (int mt = 0; mt < 2; mt++)
                #pragma unroll
                for (int p = 0; p < 4; p++) {
                    u32 b0[2] = {bq[p][0], bq[p][1]};
                    u32 b1[2] = {bq[p][2], bq[p][3]};
                    mma_f16(acc[mt][2 * p],     af[mt], b0);
                    mma_f16(acc[mt][2 * p + 1], af[mt], b1);
                }
        }
    }

    #pragma unroll
    for (int mt = 0; mt < 2; mt++) {
        #pragma unroll
        for (int nt = 0; nt < 8; nt++) {
            const int n = n0 + wm * 32 + mt * 16 + g;
            const int c = wn * 64 + nt * 8 + tig * 2;
            *(float2*)(YP + (size_t)n * CI + c)       = make_float2(acc[mt][nt][0], acc[mt][nt][1]);
            *(float2*)(YP + (size_t)(n + 8) * CI + c) = make_float2(acc[mt][nt][2], acc[mt][nt][3]);
        }
    }
}

// ---------------- 6: merge split-K + transpose -> half [c][n] --------------
__global__ void reduceY_kernel() {
    __shared__ float tsm[32][33];
    const int b  = blockIdx.z;
    const int n0 = blockIdx.x * 32;
    const int c0 = blockIdx.y * 32;
    const int tx = threadIdx.x, ty = threadIdx.y;
    const size_t SS = (size_t)BB * NN * CI;
    const size_t base = (size_t)b * NN * CI;
    #pragma unroll
    for (int j = 0; j < 32; j += 8) {
        const size_t idx = base + (size_t)(n0 + ty + j) * CI + c0 + tx;
        float v = 0.f;
        #pragma unroll
        for (int sp = 0; sp < SPLITK; sp++) v += d_YP[sp * SS + idx];
        tsm[tx][ty + j] = v;                             // tsm[c-local][n-local]
    }
    __syncthreads();
    #pragma unroll
    for (int jj = 0; jj < 2; jj++) {
        const int cl = ty + 8 * jj + 16 * (tx >> 4);
        const int n2 = tx & 15;
        *(u32*)(d_Yh + ((size_t)b * CI + c0 + cl) * NN + n0 + 2 * n2) =
            packh2(tsm[cl][2 * n2], tsm[cl][2 * n2 + 1]);
    }
}

// ---------------- 9: out = Ww·y + Wb + x  (ldmatrix fp16 mma) --------------
__global__ void __launch_bounds__(256, 2) out_kernel(const float* __restrict__ x,
                                                     const float* __restrict__ Wb,
                                                     float* __restrict__ out) {
    __shared__ u32 As[3][2048];
    __shared__ u32 Bs[3][2048];
    const int b  = blockIdx.z;
    const int m0 = blockIdx.y * 128;
    const int n0 = blockIdx.x * 128;
    const __half* Yh = d_Yh + (size_t)b * CI * NN;

    const int t = threadIdx.x, lane = t & 31, warp = t >> 5;
    const int wm = warp & 3, wn = warp >> 2;
    const int g = lane >> 2, tig = lane & 3;
    const u32 aB = smem_u32p(As), bB = smem_u32p(Bs);
    KT_ADDRS(adA, adB, aB, bB);
    ACC_INIT();

    auto issue = [&](int ch, int s) {
        KT_CP(aB + s * 8192, d_Wt + (size_t)(ch * 32) * C + m0, C);
        KT_CP(bB + s * 8192, Yh + (size_t)(ch * 32) * NN + n0, NN);
        CPC();
    };
    issue(0, 0); issue(1, 1);
    #pragma unroll
    for (int ch = 0; ch < 4; ++ch) {
        if (ch + 1 < 4) { CPW(1); } else { CPW(0); }
        __syncthreads();
        if (ch + 2 < 4) issue(ch + 2, (ch + 2) % 3);
        FCOMP_TT((ch % 3) * 8192);
    }

    #pragma unroll
    for (int mt = 0; mt < 2; mt++) {
        #pragma unroll
        for (int nt = 0; nt < 8; nt++) {
            const int m = m0 + wm * 32 + mt * 16 + g;
            const int n = n0 + wn * 64 + nt * 8 + tig * 2;
            {
                const float bv = Wb[m];
                const float2 xv = *(const float2*)(x + ((size_t)b * C + m) * NN + n);
                *(float2*)(out + ((size_t)b * C + m) * NN + n) =
                    make_float2(acc[mt][nt][0] + bv + xv.x, acc[mt][nt][1] + bv + xv.y);
            }
            {
                const float bv = Wb[m + 8];
                const float2 xv = *(const float2*)(x + ((size_t)b * C + m + 8) * NN + n);
                *(float2*)(out + ((size_t)b * C + m + 8) * NN + n) =
                    make_float2(acc[mt][nt][2] + bv + xv.x, acc[mt][nt][3] + bv + xv.y);
            }
        }
    }
}

// ---------------------------------------------------------------------------
extern "C" void kernel_launch(void* const* d_in, const int* in_sizes, int n_in,
                              void* d_out, int out_size) {
    const float* x  = (const float*)d_in[0];
    const float* gw = (const float*)d_in[1];
    const float* gb = (const float*)d_in[2];
    const float* tw = (const float*)d_in[3];
    const float* tb = (const float*)d_in[4];
    const float* pw = (const float*)d_in[5];
    const float* pb = (const float*)d_in[6];
    const float* Ww = (const float*)d_in[7];
    const float* Wb = (const float*)d_in[8];
    float* out = (float*)d_out;

    packX_kernel<<<dim3(25, C, BB), 128>>>(x);
    packWall_kernel<<<(C * 384) / 256, 256>>>(tw, pw, gw);
    wconv_kernel<<<(CI * C / 2) / 256, 256>>>(Ww);
    proj_kernel<<<150, 256>>>(tb, pb, gb);
    fgemm_kernel<<<dim3(NN / 128, NN / 128, BB), 256>>>();
    merge_stats_kernel<<<dim3(NH / 32, BB), 256>>>();
    gscale_kernel<<<dim3(NN / 32, CI / 32, BB), dim3(32, 8)>>>();
    ygemm_kernel<<<dim3(NN / 128, SPLITK, BB), 256>>>();
    reduceY_kernel<<<dim3(NN / 32, CI / 32, BB), dim3(32, 8)>>>();
    out_kernel<<<dim3(NN / 128, C / 128, BB), 256>>>(x, Wb, out);
}

// round 11
// speedup vs baseline: 7.2918x; 1.0460x over previous
#include <cuda_runtime.h>
#include <cuda_fp16.h>
#include <math_constants.h>
#include <cstdint>

#define BB 2
#define C 256
#define CI 128
#define NN 6400
#define NH (NN / 2)
#define SPLITK 8
#define NBLK (NN / 128)     // 50

typedef unsigned u32;

// ---------------- scratch (all fp16 arrays are plain-half, col-contiguous) --
__device__ __half d_Xh[BB * C * NN];                   // x [c][n]
__device__ __half d_Wh[C * 384];                       // proj weights [c][which*128+o]
__device__ __half d_Th[BB * CI * NN];                  // theta [c][n]
__device__ __half d_Ph[BB * CI * NN];                  // phi   [c][n]
__device__ __half d_Gh[BB * CI * NN];                  // g proj half [c][m]
__device__ u32    d_Sh[(size_t)BB * NN * NH];          // S = exp(f-tileMax): half [n][m]
__device__ float  d_pM[BB * NBLK * NN];
__device__ float  d_pS[BB * NBLK * NN];
__device__ __half d_corr[BB * NBLK * NN];              // corr [nblk][m]
__device__ __half d_GSh[BB * NN * CI];                 // g [m][c]
__device__ float  d_YP[(size_t)SPLITK * BB * NN * CI]; // split-K partials, [n][c]
__device__ __half d_Yh[BB * CI * NN];                  // y [c][n]
__device__ __half d_Wt[CI * C];                        // Ww^T [ci][m]

// ============================================================================
//                    fp16 mma + ldmatrix machinery
// ============================================================================
__device__ __forceinline__ u32 packh2(float a, float b) {
    __half2 h = __halves2half2(__float2half_rn(a), __float2half_rn(b));
    return reinterpret_cast<u32&>(h);
}
__device__ __forceinline__ u32 pack2h(__half a, __half b) {
    __half2 h = __halves2half2(a, b);
    return reinterpret_cast<u32&>(h);
}
__device__ __forceinline__ u32 hmul_u32(u32 a, u32 b) {
    __half2 r = __hmul2(reinterpret_cast<__half2&>(a), reinterpret_cast<__half2&>(b));
    return reinterpret_cast<u32&>(r);
}
__device__ __forceinline__ void mma_f16(float c[4], const u32 a[4], const u32 b[2]) {
    asm volatile(
        "mma.sync.aligned.m16n8k16.row.col.f32.f16.f16.f32 "
        "{%0,%1,%2,%3}, {%4,%5,%6,%7}, {%8,%9}, {%0,%1,%2,%3};"
        : "+f"(c[0]), "+f"(c[1]), "+f"(c[2]), "+f"(c[3])
        : "r"(a[0]), "r"(a[1]), "r"(a[2]), "r"(a[3]), "r"(b[0]), "r"(b[1]));
}
#define LDSM4(d, a) \
    asm volatile("ldmatrix.sync.aligned.m8n8.x4.shared.b16 {%0,%1,%2,%3}, [%4];" \
        : "=r"((d)[0]), "=r"((d)[1]), "=r"((d)[2]), "=r"((d)[3]) : "r"(a))
#define LDSM4T(d, a) \
    asm volatile("ldmatrix.sync.aligned.m8n8.x4.trans.shared.b16 {%0,%1,%2,%3}, [%4];" \
        : "=r"((d)[0]), "=r"((d)[1]), "=r"((d)[2]), "=r"((d)[3]) : "r"(a))

__device__ __forceinline__ u32 smem_u32p(const void* p) {
    return (u32)__cvta_generic_to_shared(p);
}
#define CP16(dst, src) asm volatile("cp.async.cg.shared.global [%0], [%1], 16;" :: "r"(dst), "l"(src))
#define CPC()          asm volatile("cp.async.commit_group;")
#define CPW(n)         asm volatile("cp.async.wait_group %0;" :: "n"(n))
#define STS128A(addr, a, b, c, d) \
    asm volatile("st.shared.v4.b32 [%0], {%1,%2,%3,%4};" :: "r"(addr), "r"(a), "r"(b), "r"(c), "r"(d) : "memory")

#define ACC_INIT()                                      \
    float acc[2][8][4];                                 \
    _Pragma("unroll") for (int i = 0; i < 2; i++)       \
    _Pragma("unroll") for (int j = 0; j < 8; j++)       \
    _Pragma("unroll") for (int r = 0; r < 4; r++) acc[i][j][r] = 0.f;

// ldmatrix addr precompute (KTILE = [32 k rows][128 cols] half, 256B rows,
// chunk swizzle c' = c ^ (k&7))
#define KT_ADDRS(adA, adB, base_a, base_b)                               \
    u32 adA[2], adB[4];                                                  \
    {                                                                    \
        const int kA = (lane & 7) + ((lane >> 4) & 1) * 8;               \
        const int oA = (lane >> 3) & 1;                                  \
        _Pragma("unroll")                                                \
        for (int mt = 0; mt < 2; mt++) {                                 \
            const int chk = wm * 4 + mt * 2 + oA;                        \
            adA[mt] = (base_a) + kA * 256 + ((chk ^ (lane & 7)) << 4);   \
        }                                                                \
        const int kB = (lane & 7) + ((lane >> 3) & 1) * 8;               \
        const int oB = (lane >> 4) & 1;                                  \
        _Pragma("unroll")                                                \
        for (int p = 0; p < 4; p++) {                                    \
            const int chk = wn * 8 + p * 2 + oB;                         \
            adB[p] = (base_b) + kB * 256 + ((chk ^ (lane & 7)) << 4);    \
        }                                                                \
    }

#define FCOMP_TT(so)                                                     \
    _Pragma("unroll")                                                    \
    for (int s16 = 0; s16 < 2; ++s16) {                                  \
        const u32 o16 = (so) + s16 * 4096;                               \
        u32 af[2][4], bq[4][4];                                          \
        LDSM4T(af[0], adA[0] + o16);                                     \
        LDSM4T(af[1], adA[1] + o16);                                     \
        _Pragma("unroll")                                                \
        for (int p = 0; p < 4; p++) LDSM4T(bq[p], adB[p] + o16);         \
        _Pragma("unroll")                                                \
        for (int mt = 0; mt < 2; mt++)                                   \
            _Pragma("unroll")                                            \
            for (int p = 0; p < 4; p++) {                                \
                u32 b0[2] = {bq[p][0], bq[p][1]};                        \
                u32 b1[2] = {bq[p][2], bq[p][3]};                        \
                mma_f16(acc[mt][2 * p],     af[mt], b0);                 \
                mma_f16(acc[mt][2 * p + 1], af[mt], b1);                 \
            }                                                            \
    }

#define KT_CP(dstBase, srcPtr, pitch)                                            \
    {                                                                            \
        const int kr = t >> 3, c0k = t & 7;                                      \
        const __half* sp_ = (srcPtr) + (size_t)kr * (pitch);                     \
        CP16((dstBase) + kr * 256 + (((c0k)     ^ (kr & 7)) << 4), sp_ + c0k * 8);       \
        CP16((dstBase) + kr * 256 + (((c0k + 8) ^ (kr & 7)) << 4), sp_ + (c0k + 8) * 8); \
    }

// ---------------- 0: fused packing (x, proj weights, Ww^T) -----------------
#define PX_N (BB * C * NH)          // 1,638,400 u32 stores
#define PW_N (C * 384)              // 98,304 half stores
#define WT_N (CI * C / 2)           // 16,384 u32 stores
__global__ void pack_all_kernel(const float* __restrict__ x,
                                const float* __restrict__ tw,
                                const float* __restrict__ pw,
                                const float* __restrict__ gw,
                                const float* __restrict__ Ww) {
    const int id = blockIdx.x * 256 + threadIdx.x;
    if (id < PX_N) {
        const int n2 = id % NH;
        const int c  = (id / NH) % C;
        const int b  = id / (NH * C);
        const float2 v = *(const float2*)(x + ((size_t)b * C + c) * NN + 2 * n2);
        *(u32*)(d_Xh + ((size_t)b * C + c) * NN + 2 * n2) = packh2(v.x, v.y);
    } else if (id < PX_N + PW_N) {
        const int i = id - PX_N;
        const int c = i / 384, col = i % 384;
        const int which = col >> 7, o = col & 127;
        const float* W = (which == 0) ? tw : (which == 1) ? pw : gw;
        d_Wh[i] = __float2half_rn(W[o * C + c]);
    } else if (id < PX_N + PW_N + WT_N) {
        const int i = id - PX_N - PW_N;
        const int ci = i >> 7, m2 = i & 127;
        *(u32*)(d_Wt + ci * C + 2 * m2) =
            packh2(Ww[(2 * m2) * CI + ci], Ww[(2 * m2 + 1) * CI + ci]);
    }
}

// ---------------- 1: projections (fp16 mma + ldmatrix) ---------------------
__global__ void __launch_bounds__(256, 2) proj_kernel(const float* __restrict__ tb,
                                                      const float* __restrict__ pb,
                                                      const float* __restrict__ gb) {
    __shared__ u32 As[3][2048];
    __shared__ u32 Bs[3][2048];
    const int t = threadIdx.x, lane = t & 31, warp = t >> 5;
    const int wm = warp & 3, wn = warp >> 2;
    const int g = lane >> 2, tig = lane & 3;
    const u32 aB = smem_u32p(As), bB = smem_u32p(Bs);
    KT_ADDRS(adA, adB, aB, bB);

    const int tile = blockIdx.x;                         // 0..299
    const int b = tile / 150;
    const int rem = tile % 150;
    const int which = rem / 50;
    const int n0 = (rem % 50) * 128;
    const __half* Xh = d_Xh + (size_t)b * C * NN;
    const float* bias = (which == 0) ? tb : (which == 1) ? pb : gb;
    ACC_INIT();

    auto issue = [&](int ch, int s) {
        KT_CP(aB + s * 8192, d_Wh + (size_t)(ch * 32) * 384 + which * 128, 384);
        KT_CP(bB + s * 8192, Xh + (size_t)(ch * 32) * NN + n0, NN);
        CPC();
    };
    issue(0, 0); issue(1, 1);
    #pragma unroll
    for (int ch = 0; ch < 8; ++ch) {
        if (ch + 1 < 8) { CPW(1); } else { CPW(0); }
        __syncthreads();
        if (ch + 2 < 8) issue(ch + 2, (ch + 2) % 3);
        FCOMP_TT((ch % 3) * 8192);
    }

    __half* dst = ((which == 0) ? d_Th : (which == 1) ? d_Ph : d_Gh) + (size_t)b * CI * NN;
    #pragma unroll
    for (int mt = 0; mt < 2; mt++) {
        const int r = wm * 32 + mt * 16 + g;
        const float bv0 = bias[r], bv8 = bias[r + 8];
        #pragma unroll
        for (int nt = 0; nt < 8; nt++) {
            const int n = n0 + wn * 64 + nt * 8 + tig * 2;
            *(u32*)(dst + (size_t)r * NN + n) =
                packh2(acc[mt][nt][0] + bv0, acc[mt][nt][1] + bv0);
            *(u32*)(dst + (size_t)(r + 8) * NN + n) =
                packh2(acc[mt][nt][2] + bv8, acc[mt][nt][3] + bv8);
        }
    }
}

// ---------------- 2: f = theta^T phi ; store S fp16 + stats ----------------
__global__ void __launch_bounds__(256, 2) fgemm_kernel() {
    __shared__ u32 As[3][2048];
    __shared__ u32 Bs[3][2048];
    const int b  = blockIdx.z;
    const int n0 = blockIdx.y * 128;
    const int m0 = blockIdx.x * 128;
    const __half* Th = d_Th + (size_t)b * CI * NN;
    const __half* Ph = d_Ph + (size_t)b * CI * NN;
    u32* S = d_Sh + (size_t)b * NN * NH;

    const int t = threadIdx.x, lane = t & 31, warp = t >> 5;
    const int wm = warp & 3, wn = warp >> 2;
    const int g = lane >> 2, tig = lane & 3;
    const u32 aB = smem_u32p(As), bB = smem_u32p(Bs);
    KT_ADDRS(adA, adB, aB, bB);
    ACC_INIT();

    auto issue = [&](int ch, int s) {
        KT_CP(aB + s * 8192, Th + (size_t)(ch * 32) * NN + n0, NN);
        KT_CP(bB + s * 8192, Ph + (size_t)(ch * 32) * NN + m0, NN);
        CPC();
    };
    issue(0, 0); issue(1, 1);
    #pragma unroll
    for (int ch = 0; ch < 4; ++ch) {
        if (ch + 1 < 4) { CPW(1); } else { CPW(0); }
        __syncthreads();
        if (ch + 2 < 4) issue(ch + 2, (ch + 2) % 3);
        FCOMP_TT((ch % 3) * 8192);
    }

    // ---- column-softmax: tile max, then exp (stored as S fp16) + sums ----
    float* red = (float*)As;
    float lv[8][2];
    #pragma unroll
    for (int nt = 0; nt < 8; nt++) {
        lv[nt][0] = fmaxf(fmaxf(acc[0][nt][0], acc[0][nt][2]), fmaxf(acc[1][nt][0], acc[1][nt][2]));
        lv[nt][1] = fmaxf(fmaxf(acc[0][nt][1], acc[0][nt][3]), fmaxf(acc[1][nt][1], acc[1][nt][3]));
        #pragma unroll
        for (int d = 4; d <= 16; d <<= 1) {
            lv[nt][0] = fmaxf(lv[nt][0], __shfl_xor_sync(0xffffffff, lv[nt][0], d));
            lv[nt][1] = fmaxf(lv[nt][1], __shfl_xor_sync(0xffffffff, lv[nt][1], d));
        }
    }
    __syncthreads();
    if (g == 0) {
        #pragma unroll
        for (int nt = 0; nt < 8; nt++) {
            const int col = wn * 64 + nt * 8 + tig * 2;
            red[wm * 128 + col]     = lv[nt][0];
            red[wm * 128 + col + 1] = lv[nt][1];
        }
    }
    __syncthreads();
    if (t < 128) {
        red[512 + t] = fmaxf(fmaxf(red[t], red[128 + t]), fmaxf(red[256 + t], red[384 + t]));
    }
    __syncthreads();
    #pragma unroll
    for (int nt = 0; nt < 8; nt++) {
        const int col = wn * 64 + nt * 8 + tig * 2;
        const float tm0 = red[512 + col], tm1 = red[512 + col + 1];
        float s0 = 0.f, s1 = 0.f;
        #pragma unroll
        for (int mt = 0; mt < 2; mt++) {
            const int n = n0 + wm * 32 + mt * 16 + g;
            const float e0 = __expf(acc[mt][nt][0] - tm0);
            const float e1 = __expf(acc[mt][nt][1] - tm1);
            const float e2 = __expf(acc[mt][nt][2] - tm0);
            const float e3 = __expf(acc[mt][nt][3] - tm1);
            const size_t m2 = (size_t)((m0 + col) >> 1);
            S[(size_t)n * NH + m2]       = packh2(e0, e1);
            S[(size_t)(n + 8) * NH + m2] = packh2(e2, e3);
            s0 += e0 + e2; s1 += e1 + e3;
        }
        #pragma unroll
        for (int d = 4; d <= 16; d <<= 1) {
            s0 += __shfl_xor_sync(0xffffffff, s0, d);
            s1 += __shfl_xor_sync(0xffffffff, s1, d);
        }
        lv[nt][0] = s0; lv[nt][1] = s1;
    }
    __syncthreads();
    if (g == 0) {
        #pragma unroll
        for (int nt = 0; nt < 8; nt++) {
            const int col = wn * 64 + nt * 8 + tig * 2;
            red[wm * 128 + col]     = lv[nt][0];
            red[wm * 128 + col + 1] = lv[nt][1];
        }
    }
    __syncthreads();
    if (t < 128) {
        const float s = red[t] + red[128 + t] + red[256 + t] + red[384 + t];
        const size_t idx = ((size_t)b * NBLK + blockIdx.y) * NN + m0 + t;
        d_pM[idx] = red[512 + t];
        d_pS[idx] = s;
    }
}

// ---------------- 3: merge stats -> corr[nblk][m] half ---------------------
__global__ void __launch_bounds__(256) merge_stats_kernel() {
    __shared__ float2 red[8][32];
    __shared__ float2 resM[32], resR[32];
    const int b    = blockIdx.y;
    const int lane = threadIdx.x & 31, seg = threadIdx.x >> 5;
    const int m2   = blockIdx.x * 32 + lane;
    const float* pM = d_pM + (size_t)b * NBLK * NN + 2 * m2;
    const float* pS = d_pS + (size_t)b * NBLK * NN + 2 * m2;

    float2 vm[7];
    int cnt = 0;
    float M0 = -CUDART_INF_F, M1 = -CUDART_INF_F;
    for (int i = seg; i < NBLK; i += 8) {
        vm[cnt] = *(const float2*)(pM + (size_t)i * NN);
        M0 = fmaxf(M0, vm[cnt].x); M1 = fmaxf(M1, vm[cnt].y);
        cnt++;
    }
    red[seg][lane] = make_float2(M0, M1);
    __syncthreads();
    if (seg == 0) {
        #pragma unroll
        for (int j = 1; j < 8; j++) {
            M0 = fmaxf(M0, red[j][lane].x);
            M1 = fmaxf(M1, red[j][lane].y);
        }
        resM[lane] = make_float2(M0, M1);
    }
    __syncthreads();
    M0 = resM[lane].x; M1 = resM[lane].y;

    float s0 = 0.f, s1 = 0.f;
    {
        int k = 0;
        for (int i = seg; i < NBLK; i += 8, k++) {
            const float2 vs = *(const float2*)(pS + (size_t)i * NN);
            s0 += vs.x * __expf(vm[k].x - M0);
            s1 += vs.y * __expf(vm[k].y - M1);
        }
    }
    red[seg][lane] = make_float2(s0, s1);
    __syncthreads();
    if (seg == 0) {
        #pragma unroll
        for (int j = 1; j < 8; j++) {
            s0 += red[j][lane].x;
            s1 += red[j][lane].y;
        }
        resR[lane] = make_float2(1.f / s0, 1.f / s1);
    }
    __syncthreads();
    const float R0 = resR[lane].x, R1 = resR[lane].y;
    {
        __half* cw = d_corr + (size_t)b * NBLK * NN + 2 * m2;
        int k = 0;
        for (int i = seg; i < NBLK; i += 8, k++)
            *(u32*)(cw + (size_t)i * NN) =
                packh2(__expf(vm[k].x - M0) * R0, __expf(vm[k].y - M1) * R1);
    }
}

// ---------------- 4: transpose g half [c][m] -> [m][c] ---------------------
__global__ void __launch_bounds__(256) gscale_kernel() {
    __shared__ __half s[32][68];
    const int b = blockIdx.z, m0 = blockIdx.x * 64, c0 = blockIdx.y * 32;
    const int t = threadIdx.x;
    #pragma unroll
    for (int r = 0; r < 4; r++) {
        const int idx = t + 256 * r;          // 0..1023
        const int row = idx >> 5;             // c-local 0..31
        const int cp  = idx & 31;             // u32 col (2 m's)
        *(u32*)&s[row][cp * 2] =
            *(const u32*)(d_Gh + ((size_t)b * CI + c0 + row) * NN + m0 + cp * 2);
    }
    __syncthreads();
    #pragma unroll
    for (int r = 0; r < 4; r++) {
        const int idx = t + 256 * r;
        const int mm = idx >> 4;              // 0..63
        const int cp = idx & 15;              // c-pair 0..15
        *(u32*)(d_GSh + ((size_t)b * NN + m0 + mm) * CI + c0 + 2 * cp) =
            pack2h(s[2 * cp][mm], s[2 * cp + 1][mm]);
    }
}

// ---------------- 5: y = (S*corr) g  (ldmatrix fp16 mma, split-K) ----------
__global__ void __launch_bounds__(256, 2) ygemm_kernel() {
    __shared__ u32 As[3][2048];                          // S tile [128 n][32 k] half
    __shared__ u32 Bs[3][2048];                          // B' tile [32 k][128 c] half
    const int b     = blockIdx.z;
    const int split = blockIdx.y;
    const int n0    = blockIdx.x * 128;
    const __half* S   = (const __half*)(const void*)(d_Sh + (size_t)b * NN * NH);
    const __half* GSh = d_GSh + (size_t)b * NN * CI;
    const __half* corrh = d_corr + ((size_t)b * NBLK + blockIdx.x) * NN;
    float* YP = d_YP + ((size_t)split * BB + b) * NN * CI;
    const int kbase = split * (NN / SPLITK);             // 800 per split
    const int NCH   = (NN / SPLITK) / 32;                // 25

    const int t = threadIdx.x, lane = t & 31, warp = t >> 5;
    const int wm = warp & 3, wn = warp >> 2;
    const int g = lane >> 2, tig = lane & 3;
    const u32 aB = smem_u32p(As), bB = smem_u32p(Bs);
    ACC_INIT();

    u32 adAy[2][2];
    {
        const int nl = lane & 15, kh = (lane >> 4) & 1;
        #pragma unroll
        for (int mt = 0; mt < 2; mt++) {
            const int n = wm * 32 + mt * 16 + nl;
            #pragma unroll
            for (int s16 = 0; s16 < 2; s16++) {
                const int chk = s16 * 2 + kh;
                adAy[mt][s16] = aB + n * 64 + ((chk ^ ((n >> 1) & 3)) << 4);
            }
        }
    }
    u32 adB[4];
    {
        const int kB = (lane & 7) + ((lane >> 3) & 1) * 8;
        const int oB = (lane >> 4) & 1;
        #pragma unroll
        for (int p = 0; p < 4; p++) {
            const int chk = wn * 8 + p * 2 + oB;
            adB[p] = bB + kB * 256 + ((chk ^ (lane & 7)) << 4);
        }
    }

    auto issueA = [&](int ch, int s) {
        const int nr = t >> 1, cc = (t & 1) * 2;
        const __half* sp = S + (size_t)(n0 + nr) * NN + kbase + ch * 32;
        const u32 dst = aB + s * 8192 + nr * 64;
        CP16(dst + (((cc)     ^ ((nr >> 1) & 3)) << 4), sp + cc * 8);
        CP16(dst + (((cc + 1) ^ ((nr >> 1) & 3)) << 4), sp + (cc + 1) * 8);
        CPC();
    };
    const int rowB = t >> 3, cB = t & 7;
    uint4 gv[2]; __half crh;
    auto ldB = [&](int ch) {
        const int m = kbase + ch * 32 + rowB;
        const __half* gp = GSh + (size_t)m * CI;
        gv[0] = *(const uint4*)(gp + cB * 8);
        gv[1] = *(const uint4*)(gp + (cB + 8) * 8);
        crh = corrh[m];
    };
    auto stsB = [&](int s) {
        const __half2 crs2 = __half2half2(crh);
        const u32 crs = reinterpret_cast<const u32&>(crs2);
        const u32 dst = bB + s * 8192 + rowB * 256;
        #pragma unroll
        for (int i = 0; i < 2; i++) {
            uint4 w = gv[i];
            STS128A(dst + (((cB + 8 * i) ^ (rowB & 7)) << 4),
                    hmul_u32(w.x, crs), hmul_u32(w.y, crs),
                    hmul_u32(w.z, crs), hmul_u32(w.w, crs));
        }
    };

    ldB(0); issueA(0, 0); issueA(1, 1);
    for (int ch = 0; ch < NCH; ++ch) {
        if (ch + 1 < NCH) { CPW(1); } else { CPW(0); }
        stsB(ch % 3);
        __syncthreads();
        if (ch + 1 < NCH) ldB(ch + 1);
        if (ch + 2 < NCH) issueA(ch + 2, (ch + 2) % 3);
        const u32 so = (ch % 3) * 8192;
        #pragma unroll
        for (int s16 = 0; s16 < 2; ++s16) {
            u32 af[2][4], bq[4][4];
            LDSM4(af[0], adAy[0][s16] + so);
            LDSM4(af[1], adAy[1][s16] + so);
            #pragma unroll
            for (int p = 0; p < 4; p++) LDSM4T(bq[p], adB[p] + so + s16 * 4096);
            #pragma unroll
            for (int mt = 0; mt < 2; mt++)
                #pragma unroll
                for (int p = 0; p < 4; p++) {
                    u32 b0[2] = {bq[p][0], bq[p][1]};
                    u32 b1[2] = {bq[p][2], bq[p][3]};
                    mma_f16(acc[mt][2 * p],     af[mt], b0);
                    mma_f16(acc[mt][2 * p + 1], af[mt], b1);
                }
        }
    }

    #pragma unroll
    for (int mt = 0; mt < 2; mt++) {
        #pragma unroll
        for (int nt = 0; nt < 8; nt++) {
            const int n = n0 + wm * 32 + mt * 16 + g;
            const int c = wn * 64 + nt * 8 + tig * 2;
            *(float2*)(YP + (size_t)n * CI + c)       = make_float2(acc[mt][nt][0], acc[mt][nt][1]);
            *(float2*)(YP + (size_t)(n + 8) * CI + c) = make_float2(acc[mt][nt][2], acc[mt][nt][3]);
        }
    }
}

// ---------------- 6: merge split-K + transpose -> half [c][n] --------------
__global__ void reduceY_kernel() {
    __shared__ float tsm[32][33];
    const int b  = blockIdx.z;
    const int n0 = blockIdx.x * 32;
    const int c0 = blockIdx.y * 32;
    const int tx = threadIdx.x, ty = threadIdx.y;
    const size_t SS = (size_t)BB * NN * CI;
    const size_t base = (size_t)b * NN * CI;
    #pragma unroll
    for (int j = 0; j < 32; j += 8) {
        const size_t idx = base + (size_t)(n0 + ty + j) * CI + c0 + tx;
        float v = 0.f;
        #pragma unroll
        for (int sp = 0; sp < SPLITK; sp++) v += d_YP[sp * SS + idx];
        tsm[tx][ty + j] = v;                             // tsm[c-local][n-local]
    }
    __syncthreads();
    #pragma unroll
    for (int jj = 0; jj < 2; jj++) {
        const int cl = ty + 8 * jj + 16 * (tx >> 4);
        const int n2 = tx & 15;
        *(u32*)(d_Yh + ((size_t)b * CI + c0 + cl) * NN + n0 + 2 * n2) =
            packh2(tsm[cl][2 * n2], tsm[cl][2 * n2 + 1]);
    }
}

// ---------------- 9: out = Ww·y + Wb + x  (ldmatrix fp16 mma) --------------
__global__ void __launch_bounds__(256, 2) out_kernel(const float* __restrict__ x,
                                                     const float* __restrict__ Wb,
                                                     float* __restrict__ out) {
    __shared__ u32 As[3][2048];
    __shared__ u32 Bs[3][2048];
    const int b  = blockIdx.z;
    const int m0 = blockIdx.y * 128;
    const int n0 = blockIdx.x * 128;
    const __half* Yh = d_Yh + (size_t)b * CI * NN;

    const int t = threadIdx.x, lane = t & 31, warp = t >> 5;
    const int wm = warp & 3, wn = warp >> 2;
    const int g = lane >> 2, tig = lane & 3;
    const u32 aB = smem_u32p(As), bB = smem_u32p(Bs);
    KT_ADDRS(adA, adB, aB, bB);
    ACC_INIT();

    auto issue = [&](int ch, int s) {
        KT_CP(aB + s * 8192, d_Wt + (size_t)(ch * 32) * C + m0, C);
        KT_CP(bB + s * 8192, Yh + (size_t)(ch * 32) * NN + n0, NN);
        CPC();
    };
    issue(0, 0); issue(1, 1);
    #pragma unroll
    for (int ch = 0; ch < 4; ++ch) {
        if (ch + 1 < 4) { CPW(1); } else { CPW(0); }
        __syncthreads();
        if (ch + 2 < 4) issue(ch + 2, (ch + 2) % 3);
        FCOMP_TT((ch % 3) * 8192);
    }

    #pragma unroll
    for (int mt = 0; mt < 2; mt++) {
        #pragma unroll
        for (int nt = 0; nt < 8; nt++) {
            const int m = m0 + wm * 32 + mt * 16 + g;
            const int n = n0 + wn * 64 + nt * 8 + tig * 2;
            {
                const float bv = Wb[m];
                const float2 xv = *(const float2*)(x + ((size_t)b * C + m) * NN + n);
                *(float2*)(out + ((size_t)b * C + m) * NN + n) =
                    make_float2(acc[mt][nt][0] + bv + xv.x, acc[mt][nt][1] + bv + xv.y);
            }
            {
                const float bv = Wb[m + 8];
                const float2 xv = *(const float2*)(x + ((size_t)b * C + m + 8) * NN + n);
                *(float2*)(out + ((size_t)b * C + m + 8) * NN + n) =
                    make_float2(acc[mt][nt][2] + bv + xv.x, acc[mt][nt][3] + bv + xv.y);
            }
        }
    }
}

// ---------------------------------------------------------------------------
extern "C" void kernel_launch(void* const* d_in, const int* in_sizes, int n_in,
                              void* d_out, int out_size) {
    const float* x  = (const float*)d_in[0];
    const float* gw = (const float*)d_in[1];
    const float* gb = (const float*)d_in[2];
    const float* tw = (const float*)d_in[3];
    const float* tb = (const float*)d_in[4];
    const float* pw = (const float*)d_in[5];
    const float* pb = (const float*)d_in[6];
    const float* Ww = (const float*)d_in[7];
    const float* Wb = (const float*)d_in[8];
    float* out = (float*)d_out;

    pack_all_kernel<<<(PX_N + PW_N + WT_N + 255) / 256, 256>>>(x, tw, pw, gw, Ww);
    proj_kernel<<<300, 256>>>(tb, pb, gb);
    fgemm_kernel<<<dim3(NN / 128, NN / 128, BB), 256>>>();
    merge_stats_kernel<<<dim3(NH / 32, BB), 256>>>();
    gscale_kernel<<<dim3(NN / 64, CI / 32, BB), 256>>>();
    ygemm_kernel<<<dim3(NN / 128, SPLITK, BB), 256>>>();
    reduceY_kernel<<<dim3(NN / 32, CI / 32, BB), dim3(32, 8)>>>();
    out_kernel<<<dim3(NN / 128, C / 128, BB), 256>>>(x, Wb, out);
}

// round 12
// speedup vs baseline: 7.3412x; 1.0068x over previous
#include <cuda_runtime.h>
#include <cuda_fp16.h>
#include <math_constants.h>
#include <cstdint>

#define BB 2
#define C 256
#define CI 128
#define NN 6400
#define NH (NN / 2)
#define SPLITK 8
#define NBLK (NN / 128)     // 50

typedef unsigned u32;

// ---------------- scratch (all fp16 arrays are plain-half, col-contiguous) --
__device__ __half d_Xh[BB * C * NN];                   // x [c][n]
__device__ __half d_Wh[C * 384];                       // proj weights [c][which*128+o]
__device__ __half d_Th[BB * CI * NN];                  // theta [c][n]
__device__ __half d_Ph[BB * CI * NN];                  // phi   [c][n]
__device__ __half d_Gh[BB * CI * NN];                  // g proj half [c][m]
__device__ u32    d_Sh[(size_t)BB * NN * NH];          // S = exp(f-tileMax): half [n][m]
__device__ float  d_pM[BB * NBLK * NN];
__device__ float  d_pS[BB * NBLK * NN];
__device__ __half d_corr[BB * NBLK * NN];              // corr [nblk][m]
__device__ __half d_GSh[BB * NN * CI];                 // g [m][c]
__device__ float  d_YP[(size_t)SPLITK * BB * NN * CI]; // split-K partials, [n][c]
__device__ __half d_Yh[BB * CI * NN];                  // y [c][n]
__device__ __half d_Wt[CI * C];                        // Ww^T [ci][m]

// ============================================================================
//                    fp16 mma + ldmatrix machinery
// ============================================================================
__device__ __forceinline__ u32 packh2(float a, float b) {
    __half2 h = __halves2half2(__float2half_rn(a), __float2half_rn(b));
    return reinterpret_cast<u32&>(h);
}
__device__ __forceinline__ u32 pack2h(__half a, __half b) {
    __half2 h = __halves2half2(a, b);
    return reinterpret_cast<u32&>(h);
}
__device__ __forceinline__ u32 hmul_u32(u32 a, u32 b) {
    __half2 r = __hmul2(reinterpret_cast<__half2&>(a), reinterpret_cast<__half2&>(b));
    return reinterpret_cast<u32&>(r);
}
__device__ __forceinline__ void mma_f16(float c[4], const u32 a[4], const u32 b[2]) {
    asm volatile(
        "mma.sync.aligned.m16n8k16.row.col.f32.f16.f16.f32 "
        "{%0,%1,%2,%3}, {%4,%5,%6,%7}, {%8,%9}, {%0,%1,%2,%3};"
        : "+f"(c[0]), "+f"(c[1]), "+f"(c[2]), "+f"(c[3])
        : "r"(a[0]), "r"(a[1]), "r"(a[2]), "r"(a[3]), "r"(b[0]), "r"(b[1]));
}
#define LDSM4(d, a) \
    asm volatile("ldmatrix.sync.aligned.m8n8.x4.shared.b16 {%0,%1,%2,%3}, [%4];" \
        : "=r"((d)[0]), "=r"((d)[1]), "=r"((d)[2]), "=r"((d)[3]) : "r"(a))
#define LDSM4T(d, a) \
    asm volatile("ldmatrix.sync.aligned.m8n8.x4.trans.shared.b16 {%0,%1,%2,%3}, [%4];" \
        : "=r"((d)[0]), "=r"((d)[1]), "=r"((d)[2]), "=r"((d)[3]) : "r"(a))

__device__ __forceinline__ u32 smem_u32p(const void* p) {
    return (u32)__cvta_generic_to_shared(p);
}
#define CP16(dst, src) asm volatile("cp.async.cg.shared.global [%0], [%1], 16;" :: "r"(dst), "l"(src))
#define CPC()          asm volatile("cp.async.commit_group;")
#define CPW(n)         asm volatile("cp.async.wait_group %0;" :: "n"(n))
#define STS128A(addr, a, b, c, d) \
    asm volatile("st.shared.v4.b32 [%0], {%1,%2,%3,%4};" :: "r"(addr), "r"(a), "r"(b), "r"(c), "r"(d) : "memory")

#define ACC_INIT()                                      \
    float acc[2][8][4];                                 \
    _Pragma("unroll") for (int i = 0; i < 2; i++)       \
    _Pragma("unroll") for (int j = 0; j < 8; j++)       \
    _Pragma("unroll") for (int r = 0; r < 4; r++) acc[i][j][r] = 0.f;

// ldmatrix addr precompute (KTILE = [32 k rows][128 cols] half, 256B rows,
// chunk swizzle c' = c ^ (k&7))
#define KT_ADDRS(adA, adB, base_a, base_b)                               \
    u32 adA[2], adB[4];                                                  \
    {                                                                    \
        const int kA = (lane & 7) + ((lane >> 4) & 1) * 8;               \
        const int oA = (lane >> 3) & 1;                                  \
        _Pragma("unroll")                                                \
        for (int mt = 0; mt < 2; mt++) {                                 \
            const int chk = wm * 4 + mt * 2 + oA;                        \
            adA[mt] = (base_a) + kA * 256 + ((chk ^ (lane & 7)) << 4);   \
        }                                                                \
        const int kB = (lane & 7) + ((lane >> 3) & 1) * 8;               \
        const int oB = (lane >> 4) & 1;                                  \
        _Pragma("unroll")                                                \
        for (int p = 0; p < 4; p++) {                                    \
            const int chk = wn * 8 + p * 2 + oB;                         \
            adB[p] = (base_b) + kB * 256 + ((chk ^ (lane & 7)) << 4);    \
        }                                                                \
    }

#define FCOMP_TT(so)                                                     \
    _Pragma("unroll")                                                    \
    for (int s16 = 0; s16 < 2; ++s16) {                                  \
        const u32 o16 = (so) + s16 * 4096;                               \
        u32 af[2][4], bq[4][4];                                          \
        LDSM4T(af[0], adA[0] + o16);                                     \
        LDSM4T(af[1], adA[1] + o16);                                     \
        _Pragma("unroll")                                                \
        for (int p = 0; p < 4; p++) LDSM4T(bq[p], adB[p] + o16);         \
        _Pragma("unroll")                                                \
        for (int mt = 0; mt < 2; mt++)                                   \
            _Pragma("unroll")                                            \
            for (int p = 0; p < 4; p++) {                                \
                u32 b0[2] = {bq[p][0], bq[p][1]};                        \
                u32 b1[2] = {bq[p][2], bq[p][3]};                        \
                mma_f16(acc[mt][2 * p],     af[mt], b0);                 \
                mma_f16(acc[mt][2 * p + 1], af[mt], b1);                 \
            }                                                            \
    }

#define KT_CP(dstBase, srcPtr, pitch)                                            \
    {                                                                            \
        const int kr = t >> 3, c0k = t & 7;                                      \
        const __half* sp_ = (srcPtr) + (size_t)kr * (pitch);                     \
        CP16((dstBase) + kr * 256 + (((c0k)     ^ (kr & 7)) << 4), sp_ + c0k * 8);       \
        CP16((dstBase) + kr * 256 + (((c0k + 8) ^ (kr & 7)) << 4), sp_ + (c0k + 8) * 8); \
    }

// ---------------- 0: fused packing (x, proj weights, Ww^T) -----------------
#define PX_N (BB * C * NH)          // 1,638,400 u32 stores
#define PW_N (C * 384)              // 98,304 half stores
#define WT_N (CI * C / 2)           // 16,384 u32 stores
__global__ void pack_all_kernel(const float* __restrict__ x,
                                const float* __restrict__ tw,
                                const float* __restrict__ pw,
                                const float* __restrict__ gw,
                                const float* __restrict__ Ww) {
    const int id = blockIdx.x * 256 + threadIdx.x;
    if (id < PX_N) {
        const int n2 = id % NH;
        const int c  = (id / NH) % C;
        const int b  = id / (NH * C);
        const float2 v = *(const float2*)(x + ((size_t)b * C + c) * NN + 2 * n2);
        *(u32*)(d_Xh + ((size_t)b * C + c) * NN + 2 * n2) = packh2(v.x, v.y);
    } else if (id < PX_N + PW_N) {
        const int i = id - PX_N;
        const int c = i / 384, col = i % 384;
        const int which = col >> 7, o = col & 127;
        const float* W = (which == 0) ? tw : (which == 1) ? pw : gw;
        d_Wh[i] = __float2half_rn(W[o * C + c]);
    } else if (id < PX_N + PW_N + WT_N) {
        const int i = id - PX_N - PW_N;
        const int ci = i >> 7, m2 = i & 127;
        *(u32*)(d_Wt + ci * C + 2 * m2) =
            packh2(Ww[(2 * m2) * CI + ci], Ww[(2 * m2 + 1) * CI + ci]);
    }
}

// ---------------- 1: projections (fp16 mma + ldmatrix) ---------------------
__global__ void __launch_bounds__(256, 2) proj_kernel(const float* __restrict__ tb,
                                                      const float* __restrict__ pb,
                                                      const float* __restrict__ gb) {
    __shared__ u32 As[3][2048];
    __shared__ u32 Bs[3][2048];
    const int t = threadIdx.x, lane = t & 31, warp = t >> 5;
    const int wm = warp & 3, wn = warp >> 2;
    const int g = lane >> 2, tig = lane & 3;
    const u32 aB = smem_u32p(As), bB = smem_u32p(Bs);
    KT_ADDRS(adA, adB, aB, bB);

    const int tile = blockIdx.x;                         // 0..299
    const int b = tile / 150;
    const int rem = tile % 150;
    const int which = rem / 50;
    const int n0 = (rem % 50) * 128;
    const __half* Xh = d_Xh + (size_t)b * C * NN;
    const float* bias = (which == 0) ? tb : (which == 1) ? pb : gb;
    ACC_INIT();

    auto issue = [&](int ch, int s) {
        KT_CP(aB + s * 8192, d_Wh + (size_t)(ch * 32) * 384 + which * 128, 384);
        KT_CP(bB + s * 8192, Xh + (size_t)(ch * 32) * NN + n0, NN);
        CPC();
    };
    issue(0, 0); issue(1, 1);
    #pragma unroll
    for (int ch = 0; ch < 8; ++ch) {
        if (ch + 1 < 8) { CPW(1); } else { CPW(0); }
        __syncthreads();
        if (ch + 2 < 8) issue(ch + 2, (ch + 2) % 3);
        FCOMP_TT((ch % 3) * 8192);
    }

    __half* dst = ((which == 0) ? d_Th : (which == 1) ? d_Ph : d_Gh) + (size_t)b * CI * NN;
    #pragma unroll
    for (int mt = 0; mt < 2; mt++) {
        const int r = wm * 32 + mt * 16 + g;
        const float bv0 = bias[r], bv8 = bias[r + 8];
        #pragma unroll
        for (int nt = 0; nt < 8; nt++) {
            const int n = n0 + wn * 64 + nt * 8 + tig * 2;
            *(u32*)(dst + (size_t)r * NN + n) =
                packh2(acc[mt][nt][0] + bv0, acc[mt][nt][1] + bv0);
            *(u32*)(dst + (size_t)(r + 8) * NN + n) =
                packh2(acc[mt][nt][2] + bv8, acc[mt][nt][3] + bv8);
        }
    }
}

// ---------------- 2: f = theta^T phi ; store S fp16 + stats ----------------
__global__ void __launch_bounds__(256, 2) fgemm_kernel() {
    __shared__ u32 As[3][2048];
    __shared__ u32 Bs[3][2048];
    const int b  = blockIdx.z;
    const int n0 = blockIdx.y * 128;
    const int m0 = blockIdx.x * 128;
    const __half* Th = d_Th + (size_t)b * CI * NN;
    const __half* Ph = d_Ph + (size_t)b * CI * NN;
    u32* S = d_Sh + (size_t)b * NN * NH;

    const int t = threadIdx.x, lane = t & 31, warp = t >> 5;
    const int wm = warp & 3, wn = warp >> 2;
    const int g = lane >> 2, tig = lane & 3;
    const u32 aB = smem_u32p(As), bB = smem_u32p(Bs);
    KT_ADDRS(adA, adB, aB, bB);
    ACC_INIT();

    auto issue = [&](int ch, int s) {
        KT_CP(aB + s * 8192, Th + (size_t)(ch * 32) * NN + n0, NN);
        KT_CP(bB + s * 8192, Ph + (size_t)(ch * 32) * NN + m0, NN);
        CPC();
    };
    issue(0, 0); issue(1, 1);
    #pragma unroll
    for (int ch = 0; ch < 4; ++ch) {
        if (ch + 1 < 4) { CPW(1); } else { CPW(0); }
        __syncthreads();
        if (ch + 2 < 4) issue(ch + 2, (ch + 2) % 3);
        FCOMP_TT((ch % 3) * 8192);
    }

    // ---- column-softmax: tile max, then exp (stored as S fp16) + sums ----
    float* red = (float*)As;
    float lv[8][2];
    #pragma unroll
    for (int nt = 0; nt < 8; nt++) {
        lv[nt][0] = fmaxf(fmaxf(acc[0][nt][0], acc[0][nt][2]), fmaxf(acc[1][nt][0], acc[1][nt][2]));
        lv[nt][1] = fmaxf(fmaxf(acc[0][nt][1], acc[0][nt][3]), fmaxf(acc[1][nt][1], acc[1][nt][3]));
        #pragma unroll
        for (int d = 4; d <= 16; d <<= 1) {
            lv[nt][0] = fmaxf(lv[nt][0], __shfl_xor_sync(0xffffffff, lv[nt][0], d));
            lv[nt][1] = fmaxf(lv[nt][1], __shfl_xor_sync(0xffffffff, lv[nt][1], d));
        }
    }
    __syncthreads();
    if (g == 0) {
        #pragma unroll
        for (int nt = 0; nt < 8; nt++) {
            const int col = wn * 64 + nt * 8 + tig * 2;
            red[wm * 128 + col]     = lv[nt][0];
            red[wm * 128 + col + 1] = lv[nt][1];
        }
    }
    __syncthreads();
    if (t < 128) {
        red[512 + t] = fmaxf(fmaxf(red[t], red[128 + t]), fmaxf(red[256 + t], red[384 + t]));
    }
    __syncthreads();
    #pragma unroll
    for (int nt = 0; nt < 8; nt++) {
        const int col = wn * 64 + nt * 8 + tig * 2;
        const float tm0 = red[512 + col], tm1 = red[512 + col + 1];
        float s0 = 0.f, s1 = 0.f;
        #pragma unroll
        for (int mt = 0; mt < 2; mt++) {
            const int n = n0 + wm * 32 + mt * 16 + g;
            const float e0 = __expf(acc[mt][nt][0] - tm0);
            const float e1 = __expf(acc[mt][nt][1] - tm1);
            const float e2 = __expf(acc[mt][nt][2] - tm0);
            const float e3 = __expf(acc[mt][nt][3] - tm1);
            const size_t m2 = (size_t)((m0 + col) >> 1);
            S[(size_t)n * NH + m2]       = packh2(e0, e1);
            S[(size_t)(n + 8) * NH + m2] = packh2(e2, e3);
            s0 += e0 + e2; s1 += e1 + e3;
        }
        #pragma unroll
        for (int d = 4; d <= 16; d <<= 1) {
            s0 += __shfl_xor_sync(0xffffffff, s0, d);
            s1 += __shfl_xor_sync(0xffffffff, s1, d);
        }
        lv[nt][0] = s0; lv[nt][1] = s1;
    }
    __syncthreads();
    if (g == 0) {
        #pragma unroll
        for (int nt = 0; nt < 8; nt++) {
            const int col = wn * 64 + nt * 8 + tig * 2;
            red[wm * 128 + col]     = lv[nt][0];
            red[wm * 128 + col + 1] = lv[nt][1];
        }
    }
    __syncthreads();
    if (t < 128) {
        const float s = red[t] + red[128 + t] + red[256 + t] + red[384 + t];
        const size_t idx = ((size_t)b * NBLK + blockIdx.y) * NN + m0 + t;
        d_pM[idx] = red[512 + t];
        d_pS[idx] = s;
    }
}

// ---------------- 3+4 fused: g transpose AND softmax-stat merge ------------
// blocks [0, 800): transpose g [c][m] -> [m][c]   (was gscale_kernel)
// blocks [800, 1000): merge stats -> corr         (was merge_stats_kernel)
#define GS_BLOCKS 800
__global__ void __launch_bounds__(512) small_fused_kernel() {
    __shared__ __half sg[32][68];
    __shared__ float2 red[16][32];
    __shared__ float2 resM[32], resR[32];
    const int t = threadIdx.x;
    const int id = blockIdx.x;

    if (id < GS_BLOCKS) {
        // ---- g transpose: tile 32c x 64m ----
        const int m0 = (id % 100) * 64;
        const int c0 = ((id / 100) % 4) * 32;
        const int b  = id / 400;
        #pragma unroll
        for (int r = 0; r < 2; r++) {
            const int idx = t + 512 * r;          // 0..1023
            const int row = idx >> 5;             // c-local 0..31
            const int cp  = idx & 31;             // u32 col (2 m's)
            *(u32*)&sg[row][cp * 2] =
                *(const u32*)(d_Gh + ((size_t)b * CI + c0 + row) * NN + m0 + cp * 2);
        }
        __syncthreads();
        #pragma unroll
        for (int r = 0; r < 2; r++) {
            const int idx = t + 512 * r;
            const int mm = idx >> 4;              // 0..63
            const int cp = idx & 15;              // c-pair 0..15
            *(u32*)(d_GSh + ((size_t)b * NN + m0 + mm) * CI + c0 + 2 * cp) =
                pack2h(sg[2 * cp][mm], sg[2 * cp + 1][mm]);
        }
    } else {
        // ---- stats merge: 32 m2-columns, 16 segments over NBLK=50 ----
        const int id2 = id - GS_BLOCKS;
        const int b = id2 / 100;
        const int lane = t & 31, seg = t >> 5;    // seg 0..15
        const int m2 = (id2 % 100) * 32 + lane;
        const float* pM = d_pM + (size_t)b * NBLK * NN + 2 * m2;
        const float* pS = d_pS + (size_t)b * NBLK * NN + 2 * m2;

        float2 vm[4];
        int cnt = 0;
        float M0 = -CUDART_INF_F, M1 = -CUDART_INF_F;
        for (int i = seg; i < NBLK; i += 16) {
            vm[cnt] = *(const float2*)(pM + (size_t)i * NN);
            M0 = fmaxf(M0, vm[cnt].x); M1 = fmaxf(M1, vm[cnt].y);
            cnt++;
        }
        red[seg][lane] = make_float2(M0, M1);
        __syncthreads();
        if (seg == 0) {
            #pragma unroll
            for (int j = 1; j < 16; j++) {
                M0 = fmaxf(M0, red[j][lane].x);
                M1 = fmaxf(M1, red[j][lane].y);
            }
            resM[lane] = make_float2(M0, M1);
        }
        __syncthreads();
        M0 = resM[lane].x; M1 = resM[lane].y;

        float s0 = 0.f, s1 = 0.f;
        {
            int k = 0;
            for (int i = seg; i < NBLK; i += 16, k++) {
                const float2 vs = *(const float2*)(pS + (size_t)i * NN);
                s0 += vs.x * __expf(vm[k].x - M0);
                s1 += vs.y * __expf(vm[k].y - M1);
            }
        }
        red[seg][lane] = make_float2(s0, s1);
        __syncthreads();
        if (seg == 0) {
            #pragma unroll
            for (int j = 1; j < 16; j++) {
                s0 += red[j][lane].x;
                s1 += red[j][lane].y;
            }
            resR[lane] = make_float2(1.f / s0, 1.f / s1);
        }
        __syncthreads();
        const float R0 = resR[lane].x, R1 = resR[lane].y;
        {
            __half* cw = d_corr + (size_t)b * NBLK * NN + 2 * m2;
            int k = 0;
            for (int i = seg; i < NBLK; i += 16, k++)
                *(u32*)(cw + (size_t)i * NN) =
                    packh2(__expf(vm[k].x - M0) * R0, __expf(vm[k].y - M1) * R1);
        }
    }
}

// ---------------- 5: y = (S*corr) g  (ldmatrix fp16 mma, split-K) ----------
__global__ void __launch_bounds__(256, 2) ygemm_kernel() {
    __shared__ u32 As[3][2048];                          // S tile [128 n][32 k] half
    __shared__ u32 Bs[3][2048];                          // B' tile [32 k][128 c] half
    const int b     = blockIdx.z;
    const int split = blockIdx.y;
    const int n0    = blockIdx.x * 128;
    const __half* S   = (const __half*)(const void*)(d_Sh + (size_t)b * NN * NH);
    const __half* GSh = d_GSh + (size_t)b * NN * CI;
    const __half* corrh = d_corr + ((size_t)b * NBLK + blockIdx.x) * NN;
    float* YP = d_YP + ((size_t)split * BB + b) * NN * CI;
    const int kbase = split * (NN / SPLITK);             // 800 per split
    const int NCH   = (NN / SPLITK) / 32;                // 25

    const int t = threadIdx.x, lane = t & 31, warp = t >> 5;
    const int wm = warp & 3, wn = warp >> 2;
    const int g = lane >> 2, tig = lane & 3;
    const u32 aB = smem_u32p(As), bB = smem_u32p(Bs);
    ACC_INIT();

    u32 adAy[2][2];
    {
        const int nl = lane & 15, kh = (lane >> 4) & 1;
        #pragma unroll
        for (int mt = 0; mt < 2; mt++) {
            const int n = wm * 32 + mt * 16 + nl;
            #pragma unroll
            for (int s16 = 0; s16 < 2; s16++) {
                const int chk = s16 * 2 + kh;
                adAy[mt][s16] = aB + n * 64 + ((chk ^ ((n >> 1) & 3)) << 4);
            }
        }
    }
    u32 adB[4];
    {
        const int kB = (lane & 7) + ((lane >> 3) & 1) * 8;
        const int oB = (lane >> 4) & 1;
        #pragma unroll
        for (int p = 0; p < 4; p++) {
            const int chk = wn * 8 + p * 2 + oB;
            adB[p] = bB + kB * 256 + ((chk ^ (lane & 7)) << 4);
        }
    }

    auto issueA = [&](int ch, int s) {
        const int nr = t >> 1, cc = (t & 1) * 2;
        const __half* sp = S + (size_t)(n0 + nr) * NN + kbase + ch * 32;
        const u32 dst = aB + s * 8192 + nr * 64;
        CP16(dst + (((cc)     ^ ((nr >> 1) & 3)) << 4), sp + cc * 8);
        CP16(dst + (((cc + 1) ^ ((nr >> 1) & 3)) << 4), sp + (cc + 1) * 8);
        CPC();
    };
    const int rowB = t >> 3, cB = t & 7;
    uint4 gv[2]; __half crh;
    auto ldB = [&](int ch) {
        const int m = kbase + ch * 32 + rowB;
        const __half* gp = GSh + (size_t)m * CI;
        gv[0] = *(const uint4*)(gp + cB * 8);
        gv[1] = *(const uint4*)(gp + (cB + 8) * 8);
        crh = corrh[m];
    };
    auto stsB = [&](int s) {
        const __half2 crs2 = __half2half2(crh);
        const u32 crs = reinterpret_cast<const u32&>(crs2);
        const u32 dst = bB + s * 8192 + rowB * 256;
        #pragma unroll
        for (int i = 0; i < 2; i++) {
            uint4 w = gv[i];
            STS128A(dst + (((cB + 8 * i) ^ (rowB & 7)) << 4),
                    hmul_u32(w.x, crs), hmul_u32(w.y, crs),
                    hmul_u32(w.z, crs), hmul_u32(w.w, crs));
        }
    };

    ldB(0); issueA(0, 0); issueA(1, 1);
    for (int ch = 0; ch < NCH; ++ch) {
        if (ch + 1 < NCH) { CPW(1); } else { CPW(0); }
        stsB(ch % 3);
        __syncthreads();
        if (ch + 1 < NCH) ldB(ch + 1);
        if (ch + 2 < NCH) issueA(ch + 2, (ch + 2) % 3);
        const u32 so = (ch % 3) * 8192;
        #pragma unroll
        for (int s16 = 0; s16 < 2; ++s16) {
            u32 af[2][4], bq[4][4];
            LDSM4(af[0], adAy[0][s16] + so);
            LDSM4(af[1], adAy[1][s16] + so);
            #pragma unroll
            for (int p = 0; p < 4; p++) LDSM4T(bq[p], adB[p] + so + s16 * 4096);
            #pragma unroll
            for (int mt = 0; mt < 2; mt++)
                #pragma unroll
                for (int p = 0; p < 4; p++) {
                    u32 b0[2] = {bq[p][0], bq[p][1]};
                    u32 b1[2] = {bq[p][2], bq[p][3]};
                    mma_f16(acc[mt][2 * p],     af[mt], b0);
                    mma_f16(acc[mt][2 * p + 1], af[mt], b1);
                }
        }
    }

    #pragma unroll
    for (int mt = 0; mt < 2; mt++) {
        #pragma unroll
        for (int nt = 0; nt < 8; nt++) {
            const int n = n0 + wm * 32 + mt * 16 + g;
            const int c = wn * 64 + nt * 8 + tig * 2;
            *(float2*)(YP + (size_t)n * CI + c)       = make_float2(acc[mt][nt][0], acc[mt][nt][1]);
            *(float2*)(YP + (size_t)(n + 8) * CI + c) = make_float2(acc[mt][nt][2], acc[mt][nt][3]);
        }
    }
}

// ---------------- 6: merge split-K + transpose -> half [c][n] --------------
__global__ void reduceY_kernel() {
    __shared__ float tsm[32][33];
    const int b  = blockIdx.z;
    const int n0 = blockIdx.x * 32;
    const int c0 = blockIdx.y * 32;
    const int tx = threadIdx.x, ty = threadIdx.y;
    const size_t SS = (size_t)BB * NN * CI;
    const size_t base = (size_t)b * NN * CI;
    #pragma unroll
    for (int j = 0; j < 32; j += 8) {
        const size_t idx = base + (size_t)(n0 + ty + j) * CI + c0 + tx;
        float v = 0.f;
        #pragma unroll
        for (int sp = 0; sp < SPLITK; sp++) v += d_YP[sp * SS + idx];
        tsm[tx][ty + j] = v;                             // tsm[c-local][n-local]
    }
    __syncthreads();
    #pragma unroll
    for (int jj = 0; jj < 2; jj++) {
        const int cl = ty + 8 * jj + 16 * (tx >> 4);
        const int n2 = tx & 15;
        *(u32*)(d_Yh + ((size_t)b * CI + c0 + cl) * NN + n0 + 2 * n2) =
            packh2(tsm[cl][2 * n2], tsm[cl][2 * n2 + 1]);
    }
}

// ---------------- 9: out = Ww·y + Wb + x  (ldmatrix fp16 mma) --------------
__global__ void __launch_bounds__(256, 2) out_kernel(const float* __restrict__ x,
                                                     const float* __restrict__ Wb,
                                                     float* __restrict__ out) {
    __shared__ u32 As[3][2048];
    __shared__ u32 Bs[3][2048];
    const int b  = blockIdx.z;
    const int m0 = blockIdx.y * 128;
    const int n0 = blockIdx.x * 128;
    const __half* Yh = d_Yh + (size_t)b * CI * NN;

    const int t = threadIdx.x, lane = t & 31, warp = t >> 5;
    const int wm = warp & 3, wn = warp >> 2;
    const int g = lane >> 2, tig = lane & 3;
    const u32 aB = smem_u32p(As), bB = smem_u32p(Bs);
    KT_ADDRS(adA, adB, aB, bB);
    ACC_INIT();

    auto issue = [&](int ch, int s) {
        KT_CP(aB + s * 8192, d_Wt + (size_t)(ch * 32) * C + m0, C);
        KT_CP(bB + s * 8192, Yh + (size_t)(ch * 32) * NN + n0, NN);
        CPC();
    };
    issue(0, 0); issue(1, 1);
    #pragma unroll
    for (int ch = 0; ch < 4; ++ch) {
        if (ch + 1 < 4) { CPW(1); } else { CPW(0); }
        __syncthreads();
        if (ch + 2 < 4) issue(ch + 2, (ch + 2) % 3);
        FCOMP_TT((ch % 3) * 8192);
    }

    #pragma unroll
    for (int mt = 0; mt < 2; mt++) {
        #pragma unroll
        for (int nt = 0; nt < 8; nt++) {
            const int m = m0 + wm * 32 + mt * 16 + g;
            const int n = n0 + wn * 64 + nt * 8 + tig * 2;
            {
                const float bv = Wb[m];
                const float2 xv = *(const float2*)(x + ((size_t)b * C + m) * NN + n);
                *(float2*)(out + ((size_t)b * C + m) * NN + n) =
                    make_float2(acc[mt][nt][0] + bv + xv.x, acc[mt][nt][1] + bv + xv.y);
            }
            {
                const float bv = Wb[m + 8];
                const float2 xv = *(const float2*)(x + ((size_t)b * C + m + 8) * NN + n);
                *(float2*)(out + ((size_t)b * C + m + 8) * NN + n) =
                    make_float2(acc[mt][nt][2] + bv + xv.x, acc[mt][nt][3] + bv + xv.y);
            }
        }
    }
}

// ---------------------------------------------------------------------------
extern "C" void kernel_launch(void* const* d_in, const int* in_sizes, int n_in,
                              void* d_out, int out_size) {
    const float* x  = (const float*)d_in[0];
    const float* gw = (const float*)d_in[1];
    const float* gb = (const float*)d_in[2];
    const float* tw = (const float*)d_in[3];
    const float* tb = (const float*)d_in[4];
    const float* pw = (const float*)d_in[5];
    const float* pb = (const float*)d_in[6];
    const float* Ww = (const float*)d_in[7];
    const float* Wb = (const float*)d_in[8];
    float* out = (float*)d_out;

    pack_all_kernel<<<(PX_N + PW_N + WT_N + 255) / 256, 256>>>(x, tw, pw, gw, Ww);
    proj_kernel<<<300, 256>>>(tb, pb, gb);
    fgemm_kernel<<<dim3(NN / 128, NN / 128, BB), 256>>>();
    small_fused_kernel<<<GS_BLOCKS + (NH / 32) * BB / 1, 512>>>();
    ygemm_kernel<<<dim3(NN / 128, SPLITK, BB), 256>>>();
    reduceY_kernel<<<dim3(NN / 32, CI / 32, BB), dim3(32, 8)>>>();
    out_kernel<<<dim3(NN / 128, C / 128, BB), 256>>>(x, Wb, out);
}

// round 13
// speedup vs baseline: 7.4643x; 1.0168x over previous
#include <cuda_runtime.h>
#include <cuda_fp16.h>
#include <math_constants.h>
#include <cstdint>

#define BB 2
#define C 256
#define CI 128
#define NN 6400
#define NH (NN / 2)
#define SPLITK 8
#define NBLK (NN / 128)     // 50

typedef unsigned u32;

// ---------------- scratch (all fp16 arrays are plain-half, col-contiguous) --
__device__ __half d_Xh[BB * C * NN];                   // x [c][n]
__device__ __half d_Wh[C * 384];                       // proj weights [c][which*128+o]
__device__ __half d_Th[BB * CI * NN];                  // theta [c][n]
__device__ __half d_Ph[BB * CI * NN];                  // phi   [c][n]
__device__ __half d_Gh[BB * CI * NN];                  // g proj half [c][m]
__device__ u32    d_Sh[(size_t)BB * NN * NH];          // S = exp(f-tileMax): half [n][m]
__device__ float  d_pM[BB * NBLK * NN];
__device__ float  d_pS[BB * NBLK * NN];
__device__ __half d_corr[BB * NBLK * NN];              // corr [nblk][m]
__device__ __half d_GSh[BB * NN * CI];                 // g [m][c]
__device__ u32    d_YPh[(size_t)SPLITK * BB * NN * (CI / 2)]; // fp16 split-K partials [n][c2]
__device__ __half d_Yh[BB * CI * NN];                  // y [c][n]
__device__ __half d_Wt[CI * C];                        // Ww^T [ci][m]

// ============================================================================
//                    fp16 mma + ldmatrix machinery
// ============================================================================
__device__ __forceinline__ u32 packh2(float a, float b) {
    __half2 h = __halves2half2(__float2half_rn(a), __float2half_rn(b));
    return reinterpret_cast<u32&>(h);
}
__device__ __forceinline__ u32 pack2h(__half a, __half b) {
    __half2 h = __halves2half2(a, b);
    return reinterpret_cast<u32&>(h);
}
__device__ __forceinline__ u32 hmul_u32(u32 a, u32 b) {
    __half2 r = __hmul2(reinterpret_cast<__half2&>(a), reinterpret_cast<__half2&>(b));
    return reinterpret_cast<u32&>(r);
}
__device__ __forceinline__ void mma_f16(float c[4], const u32 a[4], const u32 b[2]) {
    asm volatile(
        "mma.sync.aligned.m16n8k16.row.col.f32.f16.f16.f32 "
        "{%0,%1,%2,%3}, {%4,%5,%6,%7}, {%8,%9}, {%0,%1,%2,%3};"
        : "+f"(c[0]), "+f"(c[1]), "+f"(c[2]), "+f"(c[3])
        : "r"(a[0]), "r"(a[1]), "r"(a[2]), "r"(a[3]), "r"(b[0]), "r"(b[1]));
}
#define LDSM4(d, a) \
    asm volatile("ldmatrix.sync.aligned.m8n8.x4.shared.b16 {%0,%1,%2,%3}, [%4];" \
        : "=r"((d)[0]), "=r"((d)[1]), "=r"((d)[2]), "=r"((d)[3]) : "r"(a))
#define LDSM4T(d, a) \
    asm volatile("ldmatrix.sync.aligned.m8n8.x4.trans.shared.b16 {%0,%1,%2,%3}, [%4];" \
        : "=r"((d)[0]), "=r"((d)[1]), "=r"((d)[2]), "=r"((d)[3]) : "r"(a))

__device__ __forceinline__ u32 smem_u32p(const void* p) {
    return (u32)__cvta_generic_to_shared(p);
}
#define CP16(dst, src) asm volatile("cp.async.cg.shared.global [%0], [%1], 16;" :: "r"(dst), "l"(src))
#define CPC()          asm volatile("cp.async.commit_group;")
#define CPW(n)         asm volatile("cp.async.wait_group %0;" :: "n"(n))
#define STS128A(addr, a, b, c, d) \
    asm volatile("st.shared.v4.b32 [%0], {%1,%2,%3,%4};" :: "r"(addr), "r"(a), "r"(b), "r"(c), "r"(d) : "memory")

#define ACC_INIT()                                      \
    float acc[2][8][4];                                 \
    _Pragma("unroll") for (int i = 0; i < 2; i++)       \
    _Pragma("unroll") for (int j = 0; j < 8; j++)       \
    _Pragma("unroll") for (int r = 0; r < 4; r++) acc[i][j][r] = 0.f;

// ldmatrix addr precompute (KTILE = [32 k rows][128 cols] half, 256B rows,
// chunk swizzle c' = c ^ (k&7))
#define KT_ADDRS(adA, adB, base_a, base_b)                               \
    u32 adA[2], adB[4];                                                  \
    {                                                                    \
        const int kA = (lane & 7) + ((lane >> 4) & 1) * 8;               \
        const int oA = (lane >> 3) & 1;                                  \
        _Pragma("unroll")                                                \
        for (int mt = 0; mt < 2; mt++) {                                 \
            const int chk = wm * 4 + mt * 2 + oA;                        \
            adA[mt] = (base_a) + kA * 256 + ((chk ^ (lane & 7)) << 4);   \
        }                                                                \
        const int kB = (lane & 7) + ((lane >> 3) & 1) * 8;               \
        const int oB = (lane >> 4) & 1;                                  \
        _Pragma("unroll")                                                \
        for (int p = 0; p < 4; p++) {                                    \
            const int chk = wn * 8 + p * 2 + oB;                         \
            adB[p] = (base_b) + kB * 256 + ((chk ^ (lane & 7)) << 4);    \
        }                                                                \
    }

#define FCOMP_TT(so)                                                     \
    _Pragma("unroll")                                                    \
    for (int s16 = 0; s16 < 2; ++s16) {                                  \
        const u32 o16 = (so) + s16 * 4096;                               \
        u32 af[2][4], bq[4][4];                                          \
        LDSM4T(af[0], adA[0] + o16);                                     \
        LDSM4T(af[1], adA[1] + o16);                                     \
        _Pragma("unroll")                                                \
        for (int p = 0; p < 4; p++) LDSM4T(bq[p], adB[p] + o16);         \
        _Pragma("unroll")                                                \
        for (int mt = 0; mt < 2; mt++)                                   \
            _Pragma("unroll")                                            \
            for (int p = 0; p < 4; p++) {                                \
                u32 b0[2] = {bq[p][0], bq[p][1]};                        \
                u32 b1[2] = {bq[p][2], bq[p][3]};                        \
                mma_f16(acc[mt][2 * p],     af[mt], b0);                 \
                mma_f16(acc[mt][2 * p + 1], af[mt], b1);                 \
            }                                                            \
    }

#define KT_CP(dstBase, srcPtr, pitch)                                            \
    {                                                                            \
        const int kr = t >> 3, c0k = t & 7;                                      \
        const __half* sp_ = (srcPtr) + (size_t)kr * (pitch);                     \
        CP16((dstBase) + kr * 256 + (((c0k)     ^ (kr & 7)) << 4), sp_ + c0k * 8);       \
        CP16((dstBase) + kr * 256 + (((c0k + 8) ^ (kr & 7)) << 4), sp_ + (c0k + 8) * 8); \
    }

// ---------------- 0: fused packing (x, proj weights, Ww^T) -----------------
#define PX_N (BB * C * NH)          // 1,638,400 u32 stores
#define PW_N (C * 384)              // 98,304 half stores
#define WT_N (CI * C / 2)           // 16,384 u32 stores
__global__ void pack_all_kernel(const float* __restrict__ x,
                                const float* __restrict__ tw,
                                const float* __restrict__ pw,
                                const float* __restrict__ gw,
                                const float* __restrict__ Ww) {
    const int id = blockIdx.x * 256 + threadIdx.x;
    if (id < PX_N) {
        const int n2 = id % NH;
        const int c  = (id / NH) % C;
        const int b  = id / (NH * C);
        const float2 v = *(const float2*)(x + ((size_t)b * C + c) * NN + 2 * n2);
        *(u32*)(d_Xh + ((size_t)b * C + c) * NN + 2 * n2) = packh2(v.x, v.y);
    } else if (id < PX_N + PW_N) {
        const int i = id - PX_N;
        const int c = i / 384, col = i % 384;
        const int which = col >> 7, o = col & 127;
        const float* W = (which == 0) ? tw : (which == 1) ? pw : gw;
        d_Wh[i] = __float2half_rn(W[o * C + c]);
    } else if (id < PX_N + PW_N + WT_N) {
        const int i = id - PX_N - PW_N;
        const int ci = i >> 7, m2 = i & 127;
        *(u32*)(d_Wt + ci * C + 2 * m2) =
            packh2(Ww[(2 * m2) * CI + ci], Ww[(2 * m2 + 1) * CI + ci]);
    }
}

// ---------------- 1: projections (fp16 mma + ldmatrix) ---------------------
__global__ void __launch_bounds__(256, 2) proj_kernel(const float* __restrict__ tb,
                                                      const float* __restrict__ pb,
                                                      const float* __restrict__ gb) {
    __shared__ u32 As[3][2048];
    __shared__ u32 Bs[3][2048];
    const int t = threadIdx.x, lane = t & 31, warp = t >> 5;
    const int wm = warp & 3, wn = warp >> 2;
    const int g = lane >> 2, tig = lane & 3;
    const u32 aB = smem_u32p(As), bB = smem_u32p(Bs);
    KT_ADDRS(adA, adB, aB, bB);

    const int tile = blockIdx.x;                         // 0..299
    const int b = tile / 150;
    const int rem = tile % 150;
    const int which = rem / 50;
    const int n0 = (rem % 50) * 128;
    const __half* Xh = d_Xh + (size_t)b * C * NN;
    const float* bias = (which == 0) ? tb : (which == 1) ? pb : gb;
    ACC_INIT();

    auto issue = [&](int ch, int s) {
        KT_CP(aB + s * 8192, d_Wh + (size_t)(ch * 32) * 384 + which * 128, 384);
        KT_CP(bB + s * 8192, Xh + (size_t)(ch * 32) * NN + n0, NN);
        CPC();
    };
    issue(0, 0); issue(1, 1);
    #pragma unroll
    for (int ch = 0; ch < 8; ++ch) {
        if (ch + 1 < 8) { CPW(1); } else { CPW(0); }
        __syncthreads();
        if (ch + 2 < 8) issue(ch + 2, (ch + 2) % 3);
        FCOMP_TT((ch % 3) * 8192);
    }

    __half* dst = ((which == 0) ? d_Th : (which == 1) ? d_Ph : d_Gh) + (size_t)b * CI * NN;
    #pragma unroll
    for (int mt = 0; mt < 2; mt++) {
        const int r = wm * 32 + mt * 16 + g;
        const float bv0 = bias[r], bv8 = bias[r + 8];
        #pragma unroll
        for (int nt = 0; nt < 8; nt++) {
            const int n = n0 + wn * 64 + nt * 8 + tig * 2;
            *(u32*)(dst + (size_t)r * NN + n) =
                packh2(acc[mt][nt][0] + bv0, acc[mt][nt][1] + bv0);
            *(u32*)(dst + (size_t)(r + 8) * NN + n) =
                packh2(acc[mt][nt][2] + bv8, acc[mt][nt][3] + bv8);
        }
    }
}

// ---------------- 2: f = theta^T phi ; store S fp16 + stats ----------------
__global__ void __launch_bounds__(256, 2) fgemm_kernel() {
    __shared__ u32 As[3][2048];
    __shared__ u32 Bs[3][2048];
    const int b  = blockIdx.z;
    const int n0 = blockIdx.y * 128;
    const int m0 = blockIdx.x * 128;
    const __half* Th = d_Th + (size_t)b * CI * NN;
    const __half* Ph = d_Ph + (size_t)b * CI * NN;
    u32* S = d_Sh + (size_t)b * NN * NH;

    const int t = threadIdx.x, lane = t & 31, warp = t >> 5;
    const int wm = warp & 3, wn = warp >> 2;
    const int g = lane >> 2, tig = lane & 3;
    const u32 aB = smem_u32p(As), bB = smem_u32p(Bs);
    KT_ADDRS(adA, adB, aB, bB);
    ACC_INIT();

    auto issue = [&](int ch, int s) {
        KT_CP(aB + s * 8192, Th + (size_t)(ch * 32) * NN + n0, NN);
        KT_CP(bB + s * 8192, Ph + (size_t)(ch * 32) * NN + m0, NN);
        CPC();
    };
    issue(0, 0); issue(1, 1);
    #pragma unroll
    for (int ch = 0; ch < 4; ++ch) {
        if (ch + 1 < 4) { CPW(1); } else { CPW(0); }
        __syncthreads();
        if (ch + 2 < 4) issue(ch + 2, (ch + 2) % 3);
        FCOMP_TT((ch % 3) * 8192);
    }

    // ---- column-softmax: tile max, then exp (stored as S fp16) + sums ----
    float* red = (float*)As;
    float lv[8][2];
    #pragma unroll
    for (int nt = 0; nt < 8; nt++) {
        lv[nt][0] = fmaxf(fmaxf(acc[0][nt][0], acc[0][nt][2]), fmaxf(acc[1][nt][0], acc[1][nt][2]));
        lv[nt][1] = fmaxf(fmaxf(acc[0][nt][1], acc[0][nt][3]), fmaxf(acc[1][nt][1], acc[1][nt][3]));
        #pragma unroll
        for (int d = 4; d <= 16; d <<= 1) {
            lv[nt][0] = fmaxf(lv[nt][0], __shfl_xor_sync(0xffffffff, lv[nt][0], d));
            lv[nt][1] = fmaxf(lv[nt][1], __shfl_xor_sync(0xffffffff, lv[nt][1], d));
        }
    }
    __syncthreads();
    if (g == 0) {
        #pragma unroll
        for (int nt = 0; nt < 8; nt++) {
            const int col = wn * 64 + nt * 8 + tig * 2;
            red[wm * 128 + col]     = lv[nt][0];
            red[wm * 128 + col + 1] = lv[nt][1];
        }
    }
    __syncthreads();
    if (t < 128) {
        red[512 + t] = fmaxf(fmaxf(red[t], red[128 + t]), fmaxf(red[256 + t], red[384 + t]));
    }
    __syncthreads();
    #pragma unroll
    for (int nt = 0; nt < 8; nt++) {
        const int col = wn * 64 + nt * 8 + tig * 2;
        const float tm0 = red[512 + col], tm1 = red[512 + col + 1];
        float s0 = 0.f, s1 = 0.f;
        #pragma unroll
        for (int mt = 0; mt < 2; mt++) {
            const int n = n0 + wm * 32 + mt * 16 + g;
            const float e0 = __expf(acc[mt][nt][0] - tm0);
            const float e1 = __expf(acc[mt][nt][1] - tm1);
            const float e2 = __expf(acc[mt][nt][2] - tm0);
            const float e3 = __expf(acc[mt][nt][3] - tm1);
            const size_t m2 = (size_t)((m0 + col) >> 1);
            S[(size_t)n * NH + m2]       = packh2(e0, e1);
            S[(size_t)(n + 8) * NH + m2] = packh2(e2, e3);
            s0 += e0 + e2; s1 += e1 + e3;
        }
        #pragma unroll
        for (int d = 4; d <= 16; d <<= 1) {
            s0 += __shfl_xor_sync(0xffffffff, s0, d);
            s1 += __shfl_xor_sync(0xffffffff, s1, d);
        }
        lv[nt][0] = s0; lv[nt][1] = s1;
    }
    __syncthreads();
    if (g == 0) {
        #pragma unroll
        for (int nt = 0; nt < 8; nt++) {
            const int col = wn * 64 + nt * 8 + tig * 2;
            red[wm * 128 + col]     = lv[nt][0];
            red[wm * 128 + col + 1] = lv[nt][1];
        }
    }
    __syncthreads();
    if (t < 128) {
        const float s = red[t] + red[128 + t] + red[256 + t] + red[384 + t];
        const size_t idx = ((size_t)b * NBLK + blockIdx.y) * NN + m0 + t;
        d_pM[idx] = red[512 + t];
        d_pS[idx] = s;
    }
}

// ---------------- 3+4 fused: g transpose AND softmax-stat merge ------------
#define GS_BLOCKS 800
__global__ void __launch_bounds__(512) small_fused_kernel() {
    __shared__ __half sg[32][68];
    __shared__ float2 red[16][32];
    __shared__ float2 resM[32], resR[32];
    const int t = threadIdx.x;
    const int id = blockIdx.x;

    if (id < GS_BLOCKS) {
        const int m0 = (id % 100) * 64;
        const int c0 = ((id / 100) % 4) * 32;
        const int b  = id / 400;
        #pragma unroll
        for (int r = 0; r < 2; r++) {
            const int idx = t + 512 * r;
            const int row = idx >> 5;
            const int cp  = idx & 31;
            *(u32*)&sg[row][cp * 2] =
                *(const u32*)(d_Gh + ((size_t)b * CI + c0 + row) * NN + m0 + cp * 2);
        }
        __syncthreads();
        #pragma unroll
        for (int r = 0; r < 2; r++) {
            const int idx = t + 512 * r;
            const int mm = idx >> 4;
            const int cp = idx & 15;
            *(u32*)(d_GSh + ((size_t)b * NN + m0 + mm) * CI + c0 + 2 * cp) =
                pack2h(sg[2 * cp][mm], sg[2 * cp + 1][mm]);
        }
    } else {
        const int id2 = id - GS_BLOCKS;
        const int b = id2 / 100;
        const int lane = t & 31, seg = t >> 5;
        const int m2 = (id2 % 100) * 32 + lane;
        const float* pM = d_pM + (size_t)b * NBLK * NN + 2 * m2;
        const float* pS = d_pS + (size_t)b * NBLK * NN + 2 * m2;

        float2 vm[4];
        int cnt = 0;
        float M0 = -CUDART_INF_F, M1 = -CUDART_INF_F;
        for (int i = seg; i < NBLK; i += 16) {
            vm[cnt] = *(const float2*)(pM + (size_t)i * NN);
            M0 = fmaxf(M0, vm[cnt].x); M1 = fmaxf(M1, vm[cnt].y);
            cnt++;
        }
        red[seg][lane] = make_float2(M0, M1);
        __syncthreads();
        if (seg == 0) {
            #pragma unroll
            for (int j = 1; j < 16; j++) {
                M0 = fmaxf(M0, red[j][lane].x);
                M1 = fmaxf(M1, red[j][lane].y);
            }
            resM[lane] = make_float2(M0, M1);
        }
        __syncthreads();
        M0 = resM[lane].x; M1 = resM[lane].y;

        float s0 = 0.f, s1 = 0.f;
        {
            int k = 0;
            for (int i = seg; i < NBLK; i += 16, k++) {
                const float2 vs = *(const float2*)(pS + (size_t)i * NN);
                s0 += vs.x * __expf(vm[k].x - M0);
                s1 += vs.y * __expf(vm[k].y - M1);
            }
        }
        red[seg][lane] = make_float2(s0, s1);
        __syncthreads();
        if (seg == 0) {
            #pragma unroll
            for (int j = 1; j < 16; j++) {
                s0 += red[j][lane].x;
                s1 += red[j][lane].y;
            }
            resR[lane] = make_float2(1.f / s0, 1.f / s1);
        }
        __syncthreads();
        const float R0 = resR[lane].x, R1 = resR[lane].y;
        {
            __half* cw = d_corr + (size_t)b * NBLK * NN + 2 * m2;
            int k = 0;
            for (int i = seg; i < NBLK; i += 16, k++)
                *(u32*)(cw + (size_t)i * NN) =
                    packh2(__expf(vm[k].x - M0) * R0, __expf(vm[k].y - M1) * R1);
        }
    }
}

// ---------------- 5: y = (S*corr) g  (ldmatrix fp16 mma, split-K) ----------
__global__ void __launch_bounds__(256, 2) ygemm_kernel() {
    __shared__ u32 As[3][2048];                          // S tile [128 n][32 k] half
    __shared__ u32 Bs[3][2048];                          // B' tile [32 k][128 c] half
    const int b     = blockIdx.z;
    const int split = blockIdx.y;
    const int n0    = blockIdx.x * 128;
    const __half* S   = (const __half*)(const void*)(d_Sh + (size_t)b * NN * NH);
    const __half* GSh = d_GSh + (size_t)b * NN * CI;
    const __half* corrh = d_corr + ((size_t)b * NBLK + blockIdx.x) * NN;
    u32* YP = d_YPh + ((size_t)split * BB + b) * NN * (CI / 2);
    const int kbase = split * (NN / SPLITK);             // 800 per split
    const int NCH   = (NN / SPLITK) / 32;                // 25

    const int t = threadIdx.x, lane = t & 31, warp = t >> 5;
    const int wm = warp & 3, wn = warp >> 2;
    const int g = lane >> 2, tig = lane & 3;
    const u32 aB = smem_u32p(As), bB = smem_u32p(Bs);
    ACC_INIT();

    u32 adAy[2][2];
    {
        const int nl = lane & 15, kh = (lane >> 4) & 1;
        #pragma unroll
        for (int mt = 0; mt < 2; mt++) {
            const int n = wm * 32 + mt * 16 + nl;
            #pragma unroll
            for (int s16 = 0; s16 < 2; s16++) {
                const int chk = s16 * 2 + kh;
                adAy[mt][s16] = aB + n * 64 + ((chk ^ ((n >> 1) & 3)) << 4);
            }
        }
    }
    u32 adB[4];
    {
        const int kB = (lane & 7) + ((lane >> 3) & 1) * 8;
        const int oB = (lane >> 4) & 1;
        #pragma unroll
        for (int p = 0; p < 4; p++) {
            const int chk = wn * 8 + p * 2 + oB;
            adB[p] = bB + kB * 256 + ((chk ^ (lane & 7)) << 4);
        }
    }

    auto issueA = [&](int ch, int s) {
        const int nr = t >> 1, cc = (t & 1) * 2;
        const __half* sp = S + (size_t)(n0 + nr) * NN + kbase + ch * 32;
        const u32 dst = aB + s * 8192 + nr * 64;
        CP16(dst + (((cc)     ^ ((nr >> 1) & 3)) << 4), sp + cc * 8);
        CP16(dst + (((cc + 1) ^ ((nr >> 1) & 3)) << 4), sp + (cc + 1) * 8);
        CPC();
    };
    const int rowB = t >> 3, cB = t & 7;
    uint4 gv[2]; __half crh;
    auto ldB = [&](int ch) {
        const int m = kbase + ch * 32 + rowB;
        const __half* gp = GSh + (size_t)m * CI;
        gv[0] = *(const uint4*)(gp + cB * 8);
        gv[1] = *(const uint4*)(gp + (cB + 8) * 8);
        crh = corrh[m];
    };
    auto stsB = [&](int s) {
        const __half2 crs2 = __half2half2(crh);
        const u32 crs = reinterpret_cast<const u32&>(crs2);
        const u32 dst = bB + s * 8192 + rowB * 256;
        #pragma unroll
        for (int i = 0; i < 2; i++) {
            uint4 w = gv[i];
            STS128A(dst + (((cB + 8 * i) ^ (rowB & 7)) << 4),
                    hmul_u32(w.x, crs), hmul_u32(w.y, crs),
                    hmul_u32(w.z, crs), hmul_u32(w.w, crs));
        }
    };

    ldB(0); issueA(0, 0); issueA(1, 1);
    for (int ch = 0; ch < NCH; ++ch) {
        if (ch + 1 < NCH) { CPW(1); } else { CPW(0); }
        stsB(ch % 3);
        __syncthreads();
        if (ch + 1 < NCH) ldB(ch + 1);
        if (ch + 2 < NCH) issueA(ch + 2, (ch + 2) % 3);
        const u32 so = (ch % 3) * 8192;
        #pragma unroll
        for (int s16 = 0; s16 < 2; ++s16) {
            u32 af[2][4], bq[4][4];
            LDSM4(af[0], adAy[0][s16] + so);
            LDSM4(af[1], adAy[1][s16] + so);
            #pragma unroll
            for (int p = 0; p < 4; p++) LDSM4T(bq[p], adB[p] + so + s16 * 4096);
            #pragma unroll
            for (int mt = 0; mt < 2; mt++)
                #pragma unroll
                for (int p = 0; p < 4; p++) {
                    u32 b0[2] = {bq[p][0], bq[p][1]};
                    u32 b1[2] = {bq[p][2], bq[p][3]};
                    mma_f16(acc[mt][2 * p],     af[mt], b0);
                    mma_f16(acc[mt][2 * p + 1], af[mt], b1);
                }
        }
    }

    // packed fp16 partial store: u32 per (n, c-pair)
    #pragma unroll
    for (int mt = 0; mt < 2; mt++) {
        #pragma unroll
        for (int nt = 0; nt < 8; nt++) {
            const int n  = n0 + wm * 32 + mt * 16 + g;
            const int c2 = wn * 32 + nt * 4 + tig;
            YP[(size_t)n * (CI / 2) + c2]       = packh2(acc[mt][nt][0], acc[mt][nt][1]);
            YP[(size_t)(n + 8) * (CI / 2) + c2] = packh2(acc[mt][nt][2], acc[mt][nt][3]);
        }
    }
}

// ---------------- 6: merge fp16 split-K + transpose -> half [c][n] ---------
__global__ void __launch_bounds__(256) reduceY_kernel() {
    __shared__ float tsm[64][33];                        // [c-local][n-local]
    const int b  = blockIdx.z;
    const int n0 = blockIdx.x * 32;
    const int c0 = blockIdx.y * 64;
    const int t  = threadIdx.x;
    const size_t SS = (size_t)BB * NN * (CI / 2);
    const size_t base = (size_t)b * NN * (CI / 2);
    #pragma unroll
    for (int r = 0; r < 4; r++) {
        const int idx = t + 256 * r;                     // 0..1023
        const int nl = idx >> 5;                         // 0..31
        const int cp = idx & 31;                         // c2-local 0..31
        const size_t off = base + (size_t)(n0 + nl) * (CI / 2) + (c0 >> 1) + cp;
        float s0 = 0.f, s1 = 0.f;
        #pragma unroll
        for (int sp = 0; sp < SPLITK; sp++) {
            const u32 w = d_YPh[sp * SS + off];
            const __half2 h = reinterpret_cast<const __half2&>(w);
            s0 += __low2float(h); s1 += __high2float(h);
        }
        tsm[2 * cp][nl] = s0; tsm[2 * cp + 1][nl] = s1;
    }
    __syncthreads();
    #pragma unroll
    for (int r = 0; r < 4; r++) {
        const int idx = t + 256 * r;
        const int cl = idx >> 4;                         // 0..63
        const int np = idx & 15;                         // 0..15
        *(u32*)(d_Yh + ((size_t)b * CI + c0 + cl) * NN + n0 + 2 * np) =
            packh2(tsm[cl][2 * np], tsm[cl][2 * np + 1]);
    }
}

// ---------------- 9: out = Ww·y + Wb + x  (ldmatrix fp16 mma) --------------
__global__ void __launch_bounds__(256, 2) out_kernel(const float* __restrict__ x,
                                                     const float* __restrict__ Wb,
                                                     float* __restrict__ out) {
    __shared__ u32 As[3][2048];
    __shared__ u32 Bs[3][2048];
    const int b  = blockIdx.z;
    const int m0 = blockIdx.y * 128;
    const int n0 = blockIdx.x * 128;
    const __half* Yh = d_Yh + (size_t)b * CI * NN;

    const int t = threadIdx.x, lane = t & 31, warp = t >> 5;
    const int wm = warp & 3, wn = warp >> 2;
    const int g = lane >> 2, tig = lane & 3;
    const u32 aB = smem_u32p(As), bB = smem_u32p(Bs);
    KT_ADDRS(adA, adB, aB, bB);
    ACC_INIT();

    auto issue = [&](int ch, int s) {
        KT_CP(aB + s * 8192, d_Wt + (size_t)(ch * 32) * C + m0, C);
        KT_CP(bB + s * 8192, Yh + (size_t)(ch * 32) * NN + n0, NN);
        CPC();
    };
    issue(0, 0); issue(1, 1);
    #pragma unroll
    for (int ch = 0; ch < 4; ++ch) {
        if (ch + 1 < 4) { CPW(1); } else { CPW(0); }
        __syncthreads();
        if (ch + 2 < 4) issue(ch + 2, (ch + 2) % 3);
        FCOMP_TT((ch % 3) * 8192);
    }

    #pragma unroll
    for (int mt = 0; mt < 2; mt++) {
        #pragma unroll
        for (int nt = 0; nt < 8; nt++) {
            const int m = m0 + wm * 32 + mt * 16 + g;
            const int n = n0 + wn * 64 + nt * 8 + tig * 2;
            {
                const float bv = Wb[m];
                const float2 xv = *(const float2*)(x + ((size_t)b * C + m) * NN + n);
                *(float2*)(out + ((size_t)b * C + m) * NN + n) =
                    make_float2(acc[mt][nt][0] + bv + xv.x, acc[mt][nt][1] + bv + xv.y);
            }
            {
                const float bv = Wb[m + 8];
                const float2 xv = *(const float2*)(x + ((size_t)b * C + m + 8) * NN + n);
                *(float2*)(out + ((size_t)b * C + m + 8) * NN + n) =
                    make_float2(acc[mt][nt][2] + bv + xv.x, acc[mt][nt][3] + bv + xv.y);
            }
        }
    }
}

// ---------------------------------------------------------------------------
extern "C" void kernel_launch(void* const* d_in, const int* in_sizes, int n_in,
                              void* d_out, int out_size) {
    const float* x  = (const float*)d_in[0];
    const float* gw = (const float*)d_in[1];
    const float* gb = (const float*)d_in[2];
    const float* tw = (const float*)d_in[3];
    const float* tb = (const float*)d_in[4];
    const float* pw = (const float*)d_in[5];
    const float* pb = (const float*)d_in[6];
    const float* Ww = (const float*)d_in[7];
    const float* Wb = (const float*)d_in[8];
    float* out = (float*)d_out;

    pack_all_kernel<<<(PX_N + PW_N + WT_N + 255) / 256, 256>>>(x, tw, pw, gw, Ww);
    proj_kernel<<<300, 256>>>(tb, pb, gb);
    fgemm_kernel<<<dim3(NN / 128, NN / 128, BB), 256>>>();
    small_fused_kernel<<<GS_BLOCKS + (NH / 32) * BB, 512>>>();
    ygemm_kernel<<<dim3(NN / 128, SPLITK, BB), 256>>>();
    reduceY_kernel<<<dim3(NN / 32, CI / 64, BB), 256>>>();
    out_kernel<<<dim3(NN / 128, C / 128, BB), 256>>>(x, Wb, out);
}